// round 1
// baseline (speedup 1.0000x reference)
#include <cuda_runtime.h>

#define T      1024
#define D      512
#define H      8
#define KC     64
#define BATCH  4
#define BH     (BATCH * H)

// Scratch (device globals; no allocation allowed).
// Layout of all four: [b][t][d] row-major == [b][h][kc][t] per the faithful reshape.
__device__ float g_q[BATCH * T * D];
__device__ float g_k[BATCH * T * D];
__device__ float g_v[BATCH * T * D];
__device__ float g_o[BATCH * T * D];

// ---------------------------------------------------------------------------
// SGEMM body: C[M,512] = A[M,512] @ W[512,512] + bias
// BM=BN=128, BK=8, 256 threads, 8x8 microtile.
// ---------------------------------------------------------------------------
__device__ __forceinline__ void gemm_body(const float* __restrict__ A,
                                          const float* __restrict__ W,
                                          const float* __restrict__ bias,
                                          float* __restrict__ C) {
    __shared__ float As[8][128];
    __shared__ float Bs[8][128];

    const int tid  = threadIdx.x;
    const int m0   = blockIdx.y * 128;
    const int n0   = blockIdx.x * 128;

    const int arow = tid >> 1;            // 0..127
    const int acol = (tid & 1) << 2;      // 0 or 4
    const int brow = tid >> 5;            // 0..7
    const int bcol = (tid & 31) << 2;     // 0..124
    const int tx   = (tid & 15) << 3;     // col base 0..120
    const int ty   = (tid >> 4) << 3;     // row base 0..120

    float acc[8][8];
#pragma unroll
    for (int i = 0; i < 8; ++i)
#pragma unroll
        for (int j = 0; j < 8; ++j) acc[i][j] = 0.f;

    for (int k0 = 0; k0 < D; k0 += 8) {
        float4 av = *(const float4*)(A + (m0 + arow) * D + k0 + acol);
        float4 bv = *(const float4*)(W + (k0 + brow) * D + n0 + bcol);
        __syncthreads();
        As[acol + 0][arow] = av.x;
        As[acol + 1][arow] = av.y;
        As[acol + 2][arow] = av.z;
        As[acol + 3][arow] = av.w;
        *(float4*)(&Bs[brow][bcol]) = bv;
        __syncthreads();
#pragma unroll
        for (int k = 0; k < 8; ++k) {
            float ra[8], rb[8];
            *(float4*)(ra)     = *(const float4*)(&As[k][ty]);
            *(float4*)(ra + 4) = *(const float4*)(&As[k][ty + 4]);
            *(float4*)(rb)     = *(const float4*)(&Bs[k][tx]);
            *(float4*)(rb + 4) = *(const float4*)(&Bs[k][tx + 4]);
#pragma unroll
            for (int i = 0; i < 8; ++i)
#pragma unroll
                for (int j = 0; j < 8; ++j)
                    acc[i][j] += ra[i] * rb[j];
        }
    }

#pragma unroll
    for (int i = 0; i < 8; ++i) {
        float* crow = C + (m0 + ty + i) * D + n0;
#pragma unroll
        for (int j = 0; j < 8; j += 4) {
            float4 o;
            o.x = acc[i][j + 0] + bias[n0 + tx + j + 0];
            o.y = acc[i][j + 1] + bias[n0 + tx + j + 1];
            o.z = acc[i][j + 2] + bias[n0 + tx + j + 2];
            o.w = acc[i][j + 3] + bias[n0 + tx + j + 3];
            *(float4*)(crow + tx + j) = o;
        }
    }
}

// Fused Q/K/V projection: blockIdx.z selects which GEMM.
__global__ __launch_bounds__(256)
void qkv_gemm_kernel(const float* __restrict__ x, const float* __restrict__ c,
                     const float* __restrict__ wq, const float* __restrict__ bq,
                     const float* __restrict__ wk, const float* __restrict__ bk,
                     const float* __restrict__ wv, const float* __restrict__ bv) {
    const float* A;
    const float* W;
    const float* bias;
    float* C;
    if (blockIdx.z == 0)      { A = x; W = wq; bias = bq; C = g_q; }
    else if (blockIdx.z == 1) { A = c; W = wk; bias = bk; C = g_k; }
    else                      { A = c; W = wv; bias = bv; C = g_v; }
    gemm_body(A, W, bias, C);
}

__global__ __launch_bounds__(256)
void out_gemm_kernel(const float* __restrict__ wo, const float* __restrict__ bo,
                     float* __restrict__ out) {
    gemm_body(g_o, wo, bo, out);
}

// ---------------------------------------------------------------------------
// Flash attention with +/-4 banded relative bias and banded relative-value add.
// One thread owns one query row. K/V tiles (64ch x 32 keys) in smem.
// Q/K/V/O all in [bh][c][t] layout (c*T + t), which is the natural buffer layout.
// ---------------------------------------------------------------------------
__global__ __launch_bounds__(128)
void attn_kernel(const float* __restrict__ ek, const float* __restrict__ ev) {
    const int bh  = blockIdx.y;
    const int tid = threadIdx.x;
    const int i   = blockIdx.x * 128 + tid;

    const float* Qb = g_q + bh * (KC * T);
    const float* Kb = g_k + bh * (KC * T);
    const float* Vb = g_v + bh * (KC * T);
    float*       Ob = g_o + bh * (KC * T);

    __shared__ float k_s[KC][32];
    __shared__ float v_s[KC][32];
    __shared__ float ek_s[9][KC];
    __shared__ float ev_s[9][KC];

    for (int idx = tid; idx < 9 * KC; idx += 128) {
        ek_s[idx / KC][idx % KC] = ek[idx];
        ev_s[idx / KC][idx % KC] = ev[idx];
    }

    // Load this thread's query row (coalesced across threads per channel).
    float q[KC];
#pragma unroll
    for (int c = 0; c < KC; ++c) q[c] = Qb[c * T + i];

    __syncthreads();

    // Band bias: rb[r] = inv_sqrt * (q_i . ek[r]), valid key j = i + r - 4.
    float rb[9];
#pragma unroll
    for (int r = 0; r < 9; ++r) {
        float s = 0.f;
#pragma unroll
        for (int c = 0; c < KC; ++c) s += q[c] * ek_s[r][c];
        rb[r] = s * 0.125f;
    }
    // Pre-scale q so the main dot product is already inv_sqrt-scaled.
#pragma unroll
    for (int c = 0; c < KC; ++c) q[c] *= 0.125f;

    float m = -1e30f, l = 0.f;
    float acc[KC];
#pragma unroll
    for (int c = 0; c < KC; ++c) acc[c] = 0.f;
    float wb[9];
#pragma unroll
    for (int r = 0; r < 9; ++r) wb[r] = 0.f;

    for (int j0 = 0; j0 < T; j0 += 32) {
        __syncthreads();
#pragma unroll
        for (int u = 0; u < 16; ++u) {
            int idx = u * 128 + tid;
            int c  = idx >> 5;
            int jj = idx & 31;
            k_s[c][jj] = Kb[c * T + j0 + jj];
            v_s[c][jj] = Vb[c * T + j0 + jj];
        }
        __syncthreads();

        // s[jj] = scaled_q . k_j
        float s[32];
#pragma unroll
        for (int jj = 0; jj < 32; ++jj) s[jj] = 0.f;
#pragma unroll 8
        for (int c = 0; c < KC; ++c) {
            float qc = q[c];
            const float4* kr = (const float4*)k_s[c];
#pragma unroll
            for (int u = 0; u < 8; ++u) {
                float4 kv = kr[u];
                s[4 * u + 0] += qc * kv.x;
                s[4 * u + 1] += qc * kv.y;
                s[4 * u + 2] += qc * kv.z;
                s[4 * u + 3] += qc * kv.w;
            }
        }

        // Banded relative-key bias (band intersects at most 2 tiles per row).
        const bool band = (i - 4 <= j0 + 31) && (i + 4 >= j0);
        if (band) {
#pragma unroll
            for (int jj = 0; jj < 32; ++jj) {
                int r = j0 + jj - i + 4;
                if (r >= 0 && r <= 8) s[jj] += rb[r];
            }
        }

        // Online softmax update.
        float mt = m;
#pragma unroll
        for (int jj = 0; jj < 32; ++jj) mt = fmaxf(mt, s[jj]);
        float corr = __expf(m - mt);
        m = mt;
        l *= corr;
#pragma unroll
        for (int r = 0; r < 9; ++r) wb[r] *= corr;
#pragma unroll
        for (int c = 0; c < KC; ++c) acc[c] *= corr;

        float lsum = 0.f;
#pragma unroll
        for (int jj = 0; jj < 32; ++jj) {
            float e = __expf(s[jj] - m);
            s[jj] = e;
            lsum += e;
        }
        l += lsum;

        // Banded relative-value weights (same rescaling as acc).
        if (band) {
#pragma unroll
            for (int jj = 0; jj < 32; ++jj) {
                int r = j0 + jj - i + 4;
                if (r >= 0 && r <= 8) wb[r] += s[jj];
            }
        }

        // acc[c] += e . v_row[c]
#pragma unroll 8
        for (int c = 0; c < KC; ++c) {
            float a = acc[c];
            const float4* vr = (const float4*)v_s[c];
#pragma unroll
            for (int u = 0; u < 8; ++u) {
                float4 vv = vr[u];
                a += s[4 * u + 0] * vv.x;
                a += s[4 * u + 1] * vv.y;
                a += s[4 * u + 2] * vv.z;
                a += s[4 * u + 3] * vv.w;
            }
            acc[c] = a;
        }
    }

    const float inv_l = 1.f / l;
#pragma unroll
    for (int c = 0; c < KC; ++c) {
        float a = acc[c];
#pragma unroll
        for (int r = 0; r < 9; ++r) a += wb[r] * ev_s[r][c];
        Ob[c * T + i] = a * inv_l;
    }
}

// ---------------------------------------------------------------------------
extern "C" void kernel_launch(void* const* d_in, const int* in_sizes, int n_in,
                              void* d_out, int out_size) {
    const float* x  = (const float*)d_in[0];
    const float* c  = (const float*)d_in[1];
    const float* wq = (const float*)d_in[2];
    const float* bq = (const float*)d_in[3];
    const float* wk = (const float*)d_in[4];
    const float* bk = (const float*)d_in[5];
    const float* wv = (const float*)d_in[6];
    const float* bv = (const float*)d_in[7];
    const float* wo = (const float*)d_in[8];
    const float* bo = (const float*)d_in[9];
    const float* ek = (const float*)d_in[10];
    const float* ev = (const float*)d_in[11];
    float* out = (float*)d_out;

    dim3 gemm_grid(D / 128, (BATCH * T) / 128, 3);   // (4, 32, 3)
    qkv_gemm_kernel<<<gemm_grid, 256>>>(x, c, wq, bq, wk, bk, wv, bv);

    attn_kernel<<<dim3(T / 128, BH), 128>>>(ek, ev);

    out_gemm_kernel<<<dim3(D / 128, (BATCH * T) / 128), 256>>>(wo, bo, out);
}

// round 2
// speedup vs baseline: 1.6860x; 1.6860x over previous
#include <cuda_runtime.h>

#define T      1024
#define D      512
#define H      8
#define KC     64
#define BATCH  4
#define BH     (BATCH * H)

// Scratch (device globals; no allocation allowed).
// Layout of all four: [b][t][d] row-major == [b][h][kc][t] per the faithful reshape.
__device__ float g_q[BATCH * T * D];
__device__ float g_k[BATCH * T * D];
__device__ float g_v[BATCH * T * D];
__device__ float g_o[BATCH * T * D];

// ---------------------------------------------------------------------------
// SGEMM body: C[M,512] = A[M,512] @ W[512,512] + bias
// BM=BN=128, BK=8, 256 threads, 8x8 microtile.
// ---------------------------------------------------------------------------
__device__ __forceinline__ void gemm_body(const float* __restrict__ A,
                                          const float* __restrict__ W,
                                          const float* __restrict__ bias,
                                          float* __restrict__ C) {
    __shared__ float As[8][128];
    __shared__ float Bs[8][128];

    const int tid  = threadIdx.x;
    const int m0   = blockIdx.y * 128;
    const int n0   = blockIdx.x * 128;

    const int arow = tid >> 1;            // 0..127
    const int acol = (tid & 1) << 2;      // 0 or 4
    const int brow = tid >> 5;            // 0..7
    const int bcol = (tid & 31) << 2;     // 0..124
    const int tx   = (tid & 15) << 3;     // col base 0..120
    const int ty   = (tid >> 4) << 3;     // row base 0..120

    float acc[8][8];
#pragma unroll
    for (int i = 0; i < 8; ++i)
#pragma unroll
        for (int j = 0; j < 8; ++j) acc[i][j] = 0.f;

    for (int k0 = 0; k0 < D; k0 += 8) {
        float4 av = *(const float4*)(A + (m0 + arow) * D + k0 + acol);
        float4 bv = *(const float4*)(W + (k0 + brow) * D + n0 + bcol);
        __syncthreads();
        As[acol + 0][arow] = av.x;
        As[acol + 1][arow] = av.y;
        As[acol + 2][arow] = av.z;
        As[acol + 3][arow] = av.w;
        *(float4*)(&Bs[brow][bcol]) = bv;
        __syncthreads();
#pragma unroll
        for (int k = 0; k < 8; ++k) {
            float ra[8], rb[8];
            *(float4*)(ra)     = *(const float4*)(&As[k][ty]);
            *(float4*)(ra + 4) = *(const float4*)(&As[k][ty + 4]);
            *(float4*)(rb)     = *(const float4*)(&Bs[k][tx]);
            *(float4*)(rb + 4) = *(const float4*)(&Bs[k][tx + 4]);
#pragma unroll
            for (int i = 0; i < 8; ++i)
#pragma unroll
                for (int j = 0; j < 8; ++j)
                    acc[i][j] += ra[i] * rb[j];
        }
    }

#pragma unroll
    for (int i = 0; i < 8; ++i) {
        float* crow = C + (m0 + ty + i) * D + n0;
#pragma unroll
        for (int j = 0; j < 8; j += 4) {
            float4 o;
            o.x = acc[i][j + 0] + bias[n0 + tx + j + 0];
            o.y = acc[i][j + 1] + bias[n0 + tx + j + 1];
            o.z = acc[i][j + 2] + bias[n0 + tx + j + 2];
            o.w = acc[i][j + 3] + bias[n0 + tx + j + 3];
            *(float4*)(crow + tx + j) = o;
        }
    }
}

// Fused Q/K/V projection: blockIdx.z selects which GEMM.
__global__ __launch_bounds__(256)
void qkv_gemm_kernel(const float* __restrict__ x, const float* __restrict__ c,
                     const float* __restrict__ wq, const float* __restrict__ bq,
                     const float* __restrict__ wk, const float* __restrict__ bk,
                     const float* __restrict__ wv, const float* __restrict__ bv) {
    const float* A;
    const float* W;
    const float* bias;
    float* C;
    if (blockIdx.z == 0)      { A = x; W = wq; bias = bq; C = g_q; }
    else if (blockIdx.z == 1) { A = c; W = wk; bias = bk; C = g_k; }
    else                      { A = c; W = wv; bias = bv; C = g_v; }
    gemm_body(A, W, bias, C);
}

__global__ __launch_bounds__(256)
void out_gemm_kernel(const float* __restrict__ wo, const float* __restrict__ bo,
                     float* __restrict__ out) {
    gemm_body(g_o, wo, bo, out);
}

// ---------------------------------------------------------------------------
// Flash attention with +/-4 banded relative bias and banded relative-value add.
// One thread owns one query row. K/V tiles (64ch x 32 keys) in smem.
// Q/K/V/O all in [bh][c][t] layout (c*T + t), which is the natural buffer layout.
// ---------------------------------------------------------------------------
__global__ __launch_bounds__(128)
void attn_kernel(const float* __restrict__ ek, const float* __restrict__ ev) {
    const int bh  = blockIdx.y;
    const int tid = threadIdx.x;
    const int i   = blockIdx.x * 128 + tid;

    const float* Qb = g_q + bh * (KC * T);
    const float* Kb = g_k + bh * (KC * T);
    const float* Vb = g_v + bh * (KC * T);
    float*       Ob = g_o + bh * (KC * T);

    __shared__ float k_s[KC][32];
    __shared__ float v_s[KC][32];
    __shared__ float ek_s[9][KC];
    __shared__ float ev_s[9][KC];

    for (int idx = tid; idx < 9 * KC; idx += 128) {
        ek_s[idx / KC][idx % KC] = ek[idx];
        ev_s[idx / KC][idx % KC] = ev[idx];
    }

    // Load this thread's query row (coalesced across threads per channel).
    float q[KC];
#pragma unroll
    for (int c = 0; c < KC; ++c) q[c] = Qb[c * T + i];

    __syncthreads();

    // Band bias: rb[r] = inv_sqrt * (q_i . ek[r]), valid key j = i + r - 4.
    float rb[9];
#pragma unroll
    for (int r = 0; r < 9; ++r) {
        float s = 0.f;
#pragma unroll
        for (int c = 0; c < KC; ++c) s += q[c] * ek_s[r][c];
        rb[r] = s * 0.125f;
    }
    // Pre-scale q so the main dot product is already inv_sqrt-scaled.
#pragma unroll
    for (int c = 0; c < KC; ++c) q[c] *= 0.125f;

    float m = -1e30f, l = 0.f;
    float acc[KC];
#pragma unroll
    for (int c = 0; c < KC; ++c) acc[c] = 0.f;
    float wb[9];
#pragma unroll
    for (int r = 0; r < 9; ++r) wb[r] = 0.f;

    for (int j0 = 0; j0 < T; j0 += 32) {
        __syncthreads();
#pragma unroll
        for (int u = 0; u < 16; ++u) {
            int idx = u * 128 + tid;
            int c  = idx >> 5;
            int jj = idx & 31;
            k_s[c][jj] = Kb[c * T + j0 + jj];
            v_s[c][jj] = Vb[c * T + j0 + jj];
        }
        __syncthreads();

        // s[jj] = scaled_q . k_j
        float s[32];
#pragma unroll
        for (int jj = 0; jj < 32; ++jj) s[jj] = 0.f;
#pragma unroll 8
        for (int c = 0; c < KC; ++c) {
            float qc = q[c];
            const float4* kr = (const float4*)k_s[c];
#pragma unroll
            for (int u = 0; u < 8; ++u) {
                float4 kv = kr[u];
                s[4 * u + 0] += qc * kv.x;
                s[4 * u + 1] += qc * kv.y;
                s[4 * u + 2] += qc * kv.z;
                s[4 * u + 3] += qc * kv.w;
            }
        }

        // Banded relative-key bias (band intersects at most 2 tiles per row).
        const bool band = (i - 4 <= j0 + 31) && (i + 4 >= j0);
        if (band) {
#pragma unroll
            for (int jj = 0; jj < 32; ++jj) {
                int r = j0 + jj - i + 4;
                if (r >= 0 && r <= 8) s[jj] += rb[r];
            }
        }

        // Online softmax update.
        float mt = m;
#pragma unroll
        for (int jj = 0; jj < 32; ++jj) mt = fmaxf(mt, s[jj]);
        float corr = __expf(m - mt);
        m = mt;
        l *= corr;
#pragma unroll
        for (int r = 0; r < 9; ++r) wb[r] *= corr;
#pragma unroll
        for (int c = 0; c < KC; ++c) acc[c] *= corr;

        float lsum = 0.f;
#pragma unroll
        for (int jj = 0; jj < 32; ++jj) {
            float e = __expf(s[jj] - m);
            s[jj] = e;
            lsum += e;
        }
        l += lsum;

        // Banded relative-value weights (same rescaling as acc).
        if (band) {
#pragma unroll
            for (int jj = 0; jj < 32; ++jj) {
                int r = j0 + jj - i + 4;
                if (r >= 0 && r <= 8) wb[r] += s[jj];
            }
        }

        // acc[c] += e . v_row[c]
#pragma unroll 8
        for (int c = 0; c < KC; ++c) {
            float a = acc[c];
            const float4* vr = (const float4*)v_s[c];
#pragma unroll
            for (int u = 0; u < 8; ++u) {
                float4 vv = vr[u];
                a += s[4 * u + 0] * vv.x;
                a += s[4 * u + 1] * vv.y;
                a += s[4 * u + 2] * vv.z;
                a += s[4 * u + 3] * vv.w;
            }
            acc[c] = a;
        }
    }

    const float inv_l = 1.f / l;
#pragma unroll
    for (int c = 0; c < KC; ++c) {
        float a = acc[c];
#pragma unroll
        for (int r = 0; r < 9; ++r) a += wb[r] * ev_s[r][c];
        Ob[c * T + i] = a * inv_l;
    }
}

// ---------------------------------------------------------------------------
extern "C" void kernel_launch(void* const* d_in, const int* in_sizes, int n_in,
                              void* d_out, int out_size) {
    const float* x  = (const float*)d_in[0];
    const float* c  = (const float*)d_in[1];
    const float* wq = (const float*)d_in[2];
    const float* bq = (const float*)d_in[3];
    const float* wk = (const float*)d_in[4];
    const float* bk = (const float*)d_in[5];
    const float* wv = (const float*)d_in[6];
    const float* bv = (const float*)d_in[7];
    const float* wo = (const float*)d_in[8];
    const float* bo = (const float*)d_in[9];
    const float* ek = (const float*)d_in[10];
    const float* ev = (const float*)d_in[11];
    float* out = (float*)d_out;

    dim3 gemm_grid(D / 128, (BATCH * T) / 128, 3);   // (4, 32, 3)
    qkv_gemm_kernel<<<gemm_grid, 256>>>(x, c, wq, bq, wk, bk, wv, bv);

    attn_kernel<<<dim3(T / 128, BH), 128>>>(ek, ev);

    out_gemm_kernel<<<dim3(D / 128, (BATCH * T) / 128), 256>>>(wo, bo, out);
}

// round 5
// speedup vs baseline: 2.0454x; 1.2132x over previous
#include <cuda_runtime.h>
#include <cuda_bf16.h>
#include <cstdint>

#define T      1024
#define D      512
#define KC     64
#define BATCH  4
#define BH     (BATCH * 8)
#define MTOT   (BATCH * T)

// ---------------------------------------------------------------------------
// Device scratch (no allocation allowed)
// ---------------------------------------------------------------------------
__device__ float g_q[MTOT * D];
__device__ float g_k[MTOT * D];
__device__ float g_v[MTOT * D];
__device__ float g_o[MTOT * D];

__device__ __nv_bfloat16 s_x_hi[MTOT * D];
__device__ __nv_bfloat16 s_x_lo[MTOT * D];
__device__ __nv_bfloat16 s_c_hi[MTOT * D];
__device__ __nv_bfloat16 s_c_lo[MTOT * D];
__device__ __nv_bfloat16 s_o_hi[MTOT * D];
__device__ __nv_bfloat16 s_o_lo[MTOT * D];
// Transposed weights [n][k], 4 of them (q, k, v, o)
__device__ __nv_bfloat16 s_w_hi[4 * D * D];
__device__ __nv_bfloat16 s_w_lo[4 * D * D];

__device__ __forceinline__ uint32_t smem_u32(const void* p) {
    uint32_t a;
    asm("{ .reg .u64 t; cvta.to.shared.u64 t, %1; cvt.u32.u64 %0, t; }" : "=r"(a) : "l"(p));
    return a;
}

// ---------------------------------------------------------------------------
// bf16 HMMA GEMM: C[4096,512] = A @ W^T + bias (W stored [n][k]).
// Split pass structure: hi*hi + lo*hi + hi*lo  (K extended 3x).
// CTA tile 128x128, 8 warps of 32x64, BK=32, cp.async double buffer.
// ---------------------------------------------------------------------------
#define BK        32
#define ASTRIDE   40                 // bf16 elems per smem row (32 + 8 pad -> 80B)
#define STAGE_ELEMS (128 * ASTRIDE)  // 5120 bf16 = 10240 B per tile stage
#define NIT       48                 // 3 passes x 16 k-iters

__device__ __forceinline__ void cp_async16(uint32_t saddr, const void* gaddr) {
    asm volatile("cp.async.cg.shared.global [%0], [%1], 16;" :: "r"(saddr), "l"(gaddr));
}
__device__ __forceinline__ void cp_commit() {
    asm volatile("cp.async.commit_group;");
}

__device__ __forceinline__ void ldm_x4(uint32_t addr, uint32_t r[4]) {
    asm volatile("ldmatrix.sync.aligned.m8n8.x4.shared.b16 {%0,%1,%2,%3}, [%4];"
                 : "=r"(r[0]), "=r"(r[1]), "=r"(r[2]), "=r"(r[3]) : "r"(addr));
}

__device__ __forceinline__ void mma16816(float c[4], const uint32_t a[4],
                                         const uint32_t b[2]) {
    asm volatile(
        "mma.sync.aligned.m16n8k16.row.col.f32.bf16.bf16.f32 "
        "{%0,%1,%2,%3}, {%4,%5,%6,%7}, {%8,%9}, {%0,%1,%2,%3};"
        : "+f"(c[0]), "+f"(c[1]), "+f"(c[2]), "+f"(c[3])
        : "r"(a[0]), "r"(a[1]), "r"(a[2]), "r"(a[3]), "r"(b[0]), "r"(b[1]));
}

__device__ __forceinline__ void mma_gemm_body(
    const __nv_bfloat16* __restrict__ a_hi, const __nv_bfloat16* __restrict__ a_lo,
    const __nv_bfloat16* __restrict__ w_hi, const __nv_bfloat16* __restrict__ w_lo,
    const float* __restrict__ bias, float* __restrict__ C) {
    __shared__ __nv_bfloat16 sA[2][STAGE_ELEMS];
    __shared__ __nv_bfloat16 sB[2][STAGE_ELEMS];

    const int tid  = threadIdx.x;
    const int wid  = tid >> 5;
    const int lane = tid & 31;
    const int n0   = blockIdx.x * 128;
    const int m0   = blockIdx.y * 128;

    const __nv_bfloat16* APS[3] = {a_hi, a_lo, a_hi};
    const __nv_bfloat16* BPS[3] = {w_hi, w_hi, w_lo};

    // Loader mapping: row = tid/2, two 16B chunks per thread (32B contiguous).
    const int lrow   = tid >> 1;
    const int lcbase = (tid & 1) * 2;

    auto issue_load = [&](int it, int stage) {
        const __nv_bfloat16* A = APS[it >> 4];
        const __nv_bfloat16* B = BPS[it >> 4];
        const int k0 = (it & 15) * BK;
        const uint32_t sa0 = smem_u32(sA[stage]);
        const uint32_t sb0 = smem_u32(sB[stage]);
#pragma unroll
        for (int cc = 0; cc < 2; ++cc) {
            const int ch = lcbase + cc;
            const uint32_t soff = (uint32_t)(lrow * ASTRIDE + ch * 8) * 2;
            cp_async16(sa0 + soff, A + (m0 + lrow) * D + k0 + ch * 8);
            cp_async16(sb0 + soff, B + (n0 + lrow) * D + k0 + ch * 8);
        }
        cp_commit();
    };

    // Warp tile: 4 warps along M (32 rows each), 2 along N (64 cols each).
    const int wm = (wid & 3) * 32;
    const int wn = (wid >> 2) * 64;

    float acc[2][8][4];
#pragma unroll
    for (int mi = 0; mi < 2; ++mi)
#pragma unroll
        for (int nj = 0; nj < 8; ++nj)
#pragma unroll
            for (int r = 0; r < 4; ++r) acc[mi][nj][r] = 0.f;

    issue_load(0, 0);

    for (int it = 0; it < NIT; ++it) {
        const int stage = it & 1;
        if (it + 1 < NIT) {
            issue_load(it + 1, stage ^ 1);
            asm volatile("cp.async.wait_group 1;");
        } else {
            asm volatile("cp.async.wait_group 0;");
        }
        __syncthreads();

        const uint32_t sAb = smem_u32(sA[stage]);
        const uint32_t sBb = smem_u32(sB[stage]);
#pragma unroll
        for (int ks = 0; ks < BK; ks += 16) {
            uint32_t afrag[2][4];
#pragma unroll
            for (int mi = 0; mi < 2; ++mi) {
                uint32_t addr = sAb +
                    (uint32_t)(((wm + mi * 16 + (lane & 15)) * ASTRIDE) +
                               ks + ((lane >> 4) << 3)) * 2;
                ldm_x4(addr, afrag[mi]);
            }
            uint32_t bfrag[8][2];
#pragma unroll
            for (int nq = 0; nq < 4; ++nq) {
                uint32_t r[4];
                uint32_t addr = sBb +
                    (uint32_t)(((wn + nq * 16 + (lane & 7) + ((lane >> 4) << 3)) * ASTRIDE) +
                               ks + (((lane >> 3) & 1) << 3)) * 2;
                ldm_x4(addr, r);
                bfrag[2 * nq][0]     = r[0];
                bfrag[2 * nq][1]     = r[1];
                bfrag[2 * nq + 1][0] = r[2];
                bfrag[2 * nq + 1][1] = r[3];
            }
#pragma unroll
            for (int mi = 0; mi < 2; ++mi)
#pragma unroll
                for (int nj = 0; nj < 8; ++nj)
                    mma16816(acc[mi][nj], afrag[mi], bfrag[nj]);
        }
        __syncthreads();
    }

    // Epilogue: fragment layout — lane l, atom (mi,nj):
    //   c0,c1: row = wm + mi*16 + l/4,    cols = nj*8 + (l%4)*2 + {0,1}
    //   c2,c3: row + 8
    const int rbase = m0 + wm + (lane >> 2);
    const int cbase = n0 + wn + (lane & 3) * 2;
#pragma unroll
    for (int mi = 0; mi < 2; ++mi) {
#pragma unroll
        for (int nj = 0; nj < 8; ++nj) {
            const int col = cbase + nj * 8;
            const float2 bb = *(const float2*)(bias + col);
            float2 v0, v1;
            v0.x = acc[mi][nj][0] + bb.x;
            v0.y = acc[mi][nj][1] + bb.y;
            v1.x = acc[mi][nj][2] + bb.x;
            v1.y = acc[mi][nj][3] + bb.y;
            *(float2*)(C + (rbase + mi * 16) * D + col)     = v0;
            *(float2*)(C + (rbase + mi * 16 + 8) * D + col) = v1;
        }
    }
}

__global__ __launch_bounds__(256)
void qkv_mma_kernel(const float* __restrict__ bq, const float* __restrict__ bk,
                    const float* __restrict__ bv) {
    if (blockIdx.z == 0)
        mma_gemm_body(s_x_hi, s_x_lo, s_w_hi, s_w_lo, bq, g_q);
    else if (blockIdx.z == 1)
        mma_gemm_body(s_c_hi, s_c_lo, s_w_hi + D * D, s_w_lo + D * D, bk, g_k);
    else
        mma_gemm_body(s_c_hi, s_c_lo, s_w_hi + 2 * D * D, s_w_lo + 2 * D * D, bv, g_v);
}

__global__ __launch_bounds__(256)
void out_mma_kernel(const float* __restrict__ bo, float* __restrict__ out) {
    mma_gemm_body(s_o_hi, s_o_lo, s_w_hi + 3 * D * D, s_w_lo + 3 * D * D, bo, out);
}

// ---------------------------------------------------------------------------
// Split kernels: fp32 -> bf16 hi + bf16 lo (lo = rn(x - hi))
// ---------------------------------------------------------------------------
__device__ __forceinline__ void splitf(float v, __nv_bfloat16& h, __nv_bfloat16& l) {
    h = __float2bfloat16(v);
    l = __float2bfloat16(v - __bfloat162float(h));
}

__device__ __forceinline__ uint32_t pk2(__nv_bfloat16 a, __nv_bfloat16 b) {
    __nv_bfloat162 t = __halves2bfloat162(a, b);
    return *(uint32_t*)&t;
}

__device__ __forceinline__ void split4_store(float4 v, __nv_bfloat16* hi,
                                             __nv_bfloat16* lo, int base) {
    __nv_bfloat16 h0, h1, h2, h3, l0, l1, l2, l3;
    splitf(v.x, h0, l0); splitf(v.y, h1, l1);
    splitf(v.z, h2, l2); splitf(v.w, h3, l3);
    uint2 hp, lp;
    hp.x = pk2(h0, h1); hp.y = pk2(h2, h3);
    lp.x = pk2(l0, l1); lp.y = pk2(l2, l3);
    *(uint2*)(hi + base) = hp;
    *(uint2*)(lo + base) = lp;
}

__global__ __launch_bounds__(256)
void split_xc_kernel(const float* __restrict__ x, const float* __restrict__ c) {
    int idx = blockIdx.x * 256 + threadIdx.x;
    const float* src;
    __nv_bfloat16 *hi, *lo;
    if (idx < MTOT * D / 4) { src = x; hi = s_x_hi; lo = s_x_lo; }
    else { idx -= MTOT * D / 4; src = c; hi = s_c_hi; lo = s_c_lo; }
    float4 v = ((const float4*)src)[idx];
    split4_store(v, hi, lo, idx * 4);
}

__global__ __launch_bounds__(256)
void split_o_kernel() {
    int idx = blockIdx.x * 256 + threadIdx.x;
    float4 v = ((const float4*)g_o)[idx];
    split4_store(v, s_o_hi, s_o_lo, idx * 4);
}

// Tiled transpose + split: Wt[n][k] = W[k][n]. 32x32 tiles, 256 threads.
__global__ __launch_bounds__(256)
void split_w_kernel(const float* __restrict__ wq, const float* __restrict__ wk,
                    const float* __restrict__ wv, const float* __restrict__ wo) {
    __shared__ float tile[32][33];
    const int w = blockIdx.z;
    const float* W = (w == 0) ? wq : (w == 1) ? wk : (w == 2) ? wv : wo;
    const int kb = blockIdx.x * 32;
    const int nb = blockIdx.y * 32;
    const int tx = threadIdx.x & 31;
    const int ty = threadIdx.x >> 5;          // 0..7
#pragma unroll
    for (int i = ty; i < 32; i += 8)
        tile[i][tx] = W[(kb + i) * D + nb + tx];
    __syncthreads();
    __nv_bfloat16* oh = s_w_hi + w * D * D;
    __nv_bfloat16* ol = s_w_lo + w * D * D;
#pragma unroll
    for (int i = ty; i < 32; i += 8) {
        float v = tile[tx][i];
        __nv_bfloat16 h, l;
        splitf(v, h, l);
        oh[(nb + i) * D + kb + tx] = h;
        ol[(nb + i) * D + kb + tx] = l;
    }
}

// ---------------------------------------------------------------------------
// Flash attention with +/-4 banded relative bias (fp32, unchanged).
// ---------------------------------------------------------------------------
__global__ __launch_bounds__(128)
void attn_kernel(const float* __restrict__ ek, const float* __restrict__ ev) {
    const int bh  = blockIdx.y;
    const int tid = threadIdx.x;
    const int i   = blockIdx.x * 128 + tid;

    const float* Qb = g_q + bh * (KC * T);
    const float* Kb = g_k + bh * (KC * T);
    const float* Vb = g_v + bh * (KC * T);
    float*       Ob = g_o + bh * (KC * T);

    __shared__ float k_s[KC][32];
    __shared__ float v_s[KC][32];
    __shared__ float ek_s[9][KC];
    __shared__ float ev_s[9][KC];

    for (int idx = tid; idx < 9 * KC; idx += 128) {
        ek_s[idx / KC][idx % KC] = ek[idx];
        ev_s[idx / KC][idx % KC] = ev[idx];
    }

    float q[KC];
#pragma unroll
    for (int c = 0; c < KC; ++c) q[c] = Qb[c * T + i];

    __syncthreads();

    float rb[9];
#pragma unroll
    for (int r = 0; r < 9; ++r) {
        float s = 0.f;
#pragma unroll
        for (int c = 0; c < KC; ++c) s += q[c] * ek_s[r][c];
        rb[r] = s * 0.125f;
    }
#pragma unroll
    for (int c = 0; c < KC; ++c) q[c] *= 0.125f;

    float m = -1e30f, l = 0.f;
    float acc[KC];
#pragma unroll
    for (int c = 0; c < KC; ++c) acc[c] = 0.f;
    float wb[9];
#pragma unroll
    for (int r = 0; r < 9; ++r) wb[r] = 0.f;

    for (int j0 = 0; j0 < T; j0 += 32) {
        __syncthreads();
#pragma unroll
        for (int u = 0; u < 16; ++u) {
            int idx = u * 128 + tid;
            int c  = idx >> 5;
            int jj = idx & 31;
            k_s[c][jj] = Kb[c * T + j0 + jj];
            v_s[c][jj] = Vb[c * T + j0 + jj];
        }
        __syncthreads();

        float s[32];
#pragma unroll
        for (int jj = 0; jj < 32; ++jj) s[jj] = 0.f;
#pragma unroll 8
        for (int c = 0; c < KC; ++c) {
            float qc = q[c];
            const float4* kr = (const float4*)k_s[c];
#pragma unroll
            for (int u = 0; u < 8; ++u) {
                float4 kv = kr[u];
                s[4 * u + 0] += qc * kv.x;
                s[4 * u + 1] += qc * kv.y;
                s[4 * u + 2] += qc * kv.z;
                s[4 * u + 3] += qc * kv.w;
            }
        }

        const bool band = (i - 4 <= j0 + 31) && (i + 4 >= j0);
        if (band) {
#pragma unroll
            for (int jj = 0; jj < 32; ++jj) {
                int r = j0 + jj - i + 4;
                if (r >= 0 && r <= 8) s[jj] += rb[r];
            }
        }

        float mt = m;
#pragma unroll
        for (int jj = 0; jj < 32; ++jj) mt = fmaxf(mt, s[jj]);
        float corr = __expf(m - mt);
        m = mt;
        l *= corr;
#pragma unroll
        for (int r = 0; r < 9; ++r) wb[r] *= corr;
#pragma unroll
        for (int c = 0; c < KC; ++c) acc[c] *= corr;

        float lsum = 0.f;
#pragma unroll
        for (int jj = 0; jj < 32; ++jj) {
            float e = __expf(s[jj] - m);
            s[jj] = e;
            lsum += e;
        }
        l += lsum;

        if (band) {
#pragma unroll
            for (int jj = 0; jj < 32; ++jj) {
                int r = j0 + jj - i + 4;
                if (r >= 0 && r <= 8) wb[r] += s[jj];
            }
        }

#pragma unroll 8
        for (int c = 0; c < KC; ++c) {
            float a = acc[c];
            const float4* vr = (const float4*)v_s[c];
#pragma unroll
            for (int u = 0; u < 8; ++u) {
                float4 vv = vr[u];
                a += s[4 * u + 0] * vv.x;
                a += s[4 * u + 1] * vv.y;
                a += s[4 * u + 2] * vv.z;
                a += s[4 * u + 3] * vv.w;
            }
            acc[c] = a;
        }
    }

    const float inv_l = 1.f / l;
#pragma unroll
    for (int c = 0; c < KC; ++c) {
        float a = acc[c];
#pragma unroll
        for (int r = 0; r < 9; ++r) a += wb[r] * ev_s[r][c];
        Ob[c * T + i] = a * inv_l;
    }
}

// ---------------------------------------------------------------------------
extern "C" void kernel_launch(void* const* d_in, const int* in_sizes, int n_in,
                              void* d_out, int out_size) {
    const float* x  = (const float*)d_in[0];
    const float* c  = (const float*)d_in[1];
    const float* wq = (const float*)d_in[2];
    const float* bq = (const float*)d_in[3];
    const float* wk = (const float*)d_in[4];
    const float* bk = (const float*)d_in[5];
    const float* wv = (const float*)d_in[6];
    const float* bv = (const float*)d_in[7];
    const float* wo = (const float*)d_in[8];
    const float* bo = (const float*)d_in[9];
    const float* ek = (const float*)d_in[10];
    const float* ev = (const float*)d_in[11];
    float* out = (float*)d_out;

    split_w_kernel<<<dim3(16, 16, 4), 256>>>(wq, wk, wv, wo);
    split_xc_kernel<<<4096, 256>>>(x, c);

    qkv_mma_kernel<<<dim3(4, 32, 3), 256>>>(bq, bk, bv);

    attn_kernel<<<dim3(T / 128, BH), 128>>>(ek, ev);

    split_o_kernel<<<2048, 256>>>();
    out_mma_kernel<<<dim3(4, 32), 256>>>(bo, out);
}

// round 6
// speedup vs baseline: 2.8945x; 1.4151x over previous
#include <cuda_runtime.h>
#include <cuda_bf16.h>
#include <cstdint>

#define T      1024
#define D      512
#define KC     64
#define BATCH  4
#define BH     (BATCH * 8)
#define MTOT   (BATCH * T)

// ---------------------------------------------------------------------------
// Device scratch (no allocation allowed)
// ---------------------------------------------------------------------------
__device__ float g_q[MTOT * D];
__device__ float g_k[MTOT * D];
__device__ float g_v[MTOT * D];

__device__ __nv_bfloat16 s_x_hi[MTOT * D];
__device__ __nv_bfloat16 s_x_lo[MTOT * D];
__device__ __nv_bfloat16 s_c_hi[MTOT * D];
__device__ __nv_bfloat16 s_c_lo[MTOT * D];
__device__ __nv_bfloat16 s_o_hi[MTOT * D];
__device__ __nv_bfloat16 s_o_lo[MTOT * D];
// Transposed weights [n][k], 4 of them (q, k, v, o)
__device__ __nv_bfloat16 s_w_hi[4 * D * D];
__device__ __nv_bfloat16 s_w_lo[4 * D * D];

__device__ __forceinline__ uint32_t smem_u32(const void* p) {
    uint32_t a;
    asm("{ .reg .u64 t; cvta.to.shared.u64 t, %1; cvt.u32.u64 %0, t; }" : "=r"(a) : "l"(p));
    return a;
}

__device__ __forceinline__ void cp_async16(uint32_t saddr, const void* gaddr) {
    asm volatile("cp.async.cg.shared.global [%0], [%1], 16;" :: "r"(saddr), "l"(gaddr));
}
__device__ __forceinline__ void cp_commit() {
    asm volatile("cp.async.commit_group;");
}

__device__ __forceinline__ void ldm_x4(uint32_t addr, uint32_t r[4]) {
    asm volatile("ldmatrix.sync.aligned.m8n8.x4.shared.b16 {%0,%1,%2,%3}, [%4];"
                 : "=r"(r[0]), "=r"(r[1]), "=r"(r[2]), "=r"(r[3]) : "r"(addr));
}
__device__ __forceinline__ void ldm_x4_t(uint32_t addr, uint32_t r[4]) {
    asm volatile("ldmatrix.sync.aligned.m8n8.x4.trans.shared.b16 {%0,%1,%2,%3}, [%4];"
                 : "=r"(r[0]), "=r"(r[1]), "=r"(r[2]), "=r"(r[3]) : "r"(addr));
}

__device__ __forceinline__ void mma16816(float c[4], const uint32_t a[4],
                                         const uint32_t b[2]) {
    asm volatile(
        "mma.sync.aligned.m16n8k16.row.col.f32.bf16.bf16.f32 "
        "{%0,%1,%2,%3}, {%4,%5,%6,%7}, {%8,%9}, {%0,%1,%2,%3};"
        : "+f"(c[0]), "+f"(c[1]), "+f"(c[2]), "+f"(c[3])
        : "r"(a[0]), "r"(a[1]), "r"(a[2]), "r"(a[3]), "r"(b[0]), "r"(b[1]));
}

__device__ __forceinline__ void splitf(float v, __nv_bfloat16& h, __nv_bfloat16& l) {
    h = __float2bfloat16(v);
    l = __float2bfloat16(v - __bfloat162float(h));
}
__device__ __forceinline__ uint32_t pk2(__nv_bfloat16 a, __nv_bfloat16 b) {
    __nv_bfloat162 t = __halves2bfloat162(a, b);
    return *(uint32_t*)&t;
}

// ---------------------------------------------------------------------------
// bf16 HMMA GEMM (validated in R4): C[4096,512] = A @ W^T + bias.
// ---------------------------------------------------------------------------
#define BK        32
#define ASTRIDE   40
#define STAGE_ELEMS (128 * ASTRIDE)
#define NIT       48

__device__ __forceinline__ void mma_gemm_body(
    const __nv_bfloat16* __restrict__ a_hi, const __nv_bfloat16* __restrict__ a_lo,
    const __nv_bfloat16* __restrict__ w_hi, const __nv_bfloat16* __restrict__ w_lo,
    const float* __restrict__ bias, float* __restrict__ C) {
    __shared__ __nv_bfloat16 sA[2][STAGE_ELEMS];
    __shared__ __nv_bfloat16 sB[2][STAGE_ELEMS];

    const int tid  = threadIdx.x;
    const int wid  = tid >> 5;
    const int lane = tid & 31;
    const int n0   = blockIdx.x * 128;
    const int m0   = blockIdx.y * 128;

    const __nv_bfloat16* APS[3] = {a_hi, a_lo, a_hi};
    const __nv_bfloat16* BPS[3] = {w_hi, w_hi, w_lo};

    const int lrow   = tid >> 1;
    const int lcbase = (tid & 1) * 2;

    auto issue_load = [&](int it, int stage) {
        const __nv_bfloat16* A = APS[it >> 4];
        const __nv_bfloat16* B = BPS[it >> 4];
        const int k0 = (it & 15) * BK;
        const uint32_t sa0 = smem_u32(sA[stage]);
        const uint32_t sb0 = smem_u32(sB[stage]);
#pragma unroll
        for (int cc = 0; cc < 2; ++cc) {
            const int ch = lcbase + cc;
            const uint32_t soff = (uint32_t)(lrow * ASTRIDE + ch * 8) * 2;
            cp_async16(sa0 + soff, A + (m0 + lrow) * D + k0 + ch * 8);
            cp_async16(sb0 + soff, B + (n0 + lrow) * D + k0 + ch * 8);
        }
        cp_commit();
    };

    const int wm = (wid & 3) * 32;
    const int wn = (wid >> 2) * 64;

    float acc[2][8][4];
#pragma unroll
    for (int mi = 0; mi < 2; ++mi)
#pragma unroll
        for (int nj = 0; nj < 8; ++nj)
#pragma unroll
            for (int r = 0; r < 4; ++r) acc[mi][nj][r] = 0.f;

    issue_load(0, 0);

    for (int it = 0; it < NIT; ++it) {
        const int stage = it & 1;
        if (it + 1 < NIT) {
            issue_load(it + 1, stage ^ 1);
            asm volatile("cp.async.wait_group 1;");
        } else {
            asm volatile("cp.async.wait_group 0;");
        }
        __syncthreads();

        const uint32_t sAb = smem_u32(sA[stage]);
        const uint32_t sBb = smem_u32(sB[stage]);
#pragma unroll
        for (int ks = 0; ks < BK; ks += 16) {
            uint32_t afrag[2][4];
#pragma unroll
            for (int mi = 0; mi < 2; ++mi) {
                uint32_t addr = sAb +
                    (uint32_t)(((wm + mi * 16 + (lane & 15)) * ASTRIDE) +
                               ks + ((lane >> 4) << 3)) * 2;
                ldm_x4(addr, afrag[mi]);
            }
            uint32_t bfrag[8][2];
#pragma unroll
            for (int nq = 0; nq < 4; ++nq) {
                uint32_t r[4];
                uint32_t addr = sBb +
                    (uint32_t)(((wn + nq * 16 + (lane & 7) + ((lane >> 4) << 3)) * ASTRIDE) +
                               ks + (((lane >> 3) & 1) << 3)) * 2;
                ldm_x4(addr, r);
                bfrag[2 * nq][0]     = r[0];
                bfrag[2 * nq][1]     = r[1];
                bfrag[2 * nq + 1][0] = r[2];
                bfrag[2 * nq + 1][1] = r[3];
            }
#pragma unroll
            for (int mi = 0; mi < 2; ++mi)
#pragma unroll
                for (int nj = 0; nj < 8; ++nj)
                    mma16816(acc[mi][nj], afrag[mi], bfrag[nj]);
        }
        __syncthreads();
    }

    const int rbase = m0 + wm + (lane >> 2);
    const int cbase = n0 + wn + (lane & 3) * 2;
#pragma unroll
    for (int mi = 0; mi < 2; ++mi) {
#pragma unroll
        for (int nj = 0; nj < 8; ++nj) {
            const int col = cbase + nj * 8;
            const float2 bb = *(const float2*)(bias + col);
            float2 v0, v1;
            v0.x = acc[mi][nj][0] + bb.x;
            v0.y = acc[mi][nj][1] + bb.y;
            v1.x = acc[mi][nj][2] + bb.x;
            v1.y = acc[mi][nj][3] + bb.y;
            *(float2*)(C + (rbase + mi * 16) * D + col)     = v0;
            *(float2*)(C + (rbase + mi * 16 + 8) * D + col) = v1;
        }
    }
}

__global__ __launch_bounds__(256)
void qkv_mma_kernel(const float* __restrict__ bq, const float* __restrict__ bk,
                    const float* __restrict__ bv) {
    if (blockIdx.z == 0)
        mma_gemm_body(s_x_hi, s_x_lo, s_w_hi, s_w_lo, bq, g_q);
    else if (blockIdx.z == 1)
        mma_gemm_body(s_c_hi, s_c_lo, s_w_hi + D * D, s_w_lo + D * D, bk, g_k);
    else
        mma_gemm_body(s_c_hi, s_c_lo, s_w_hi + 2 * D * D, s_w_lo + 2 * D * D, bv, g_v);
}

__global__ __launch_bounds__(256)
void out_mma_kernel(const float* __restrict__ bo, float* __restrict__ out) {
    mma_gemm_body(s_o_hi, s_o_lo, s_w_hi + 3 * D * D, s_w_lo + 3 * D * D, bo, out);
}

// ---------------------------------------------------------------------------
// Split kernels
// ---------------------------------------------------------------------------
__device__ __forceinline__ void split4_store(float4 v, __nv_bfloat16* hi,
                                             __nv_bfloat16* lo, int base) {
    __nv_bfloat16 h0, h1, h2, h3, l0, l1, l2, l3;
    splitf(v.x, h0, l0); splitf(v.y, h1, l1);
    splitf(v.z, h2, l2); splitf(v.w, h3, l3);
    uint2 hp, lp;
    hp.x = pk2(h0, h1); hp.y = pk2(h2, h3);
    lp.x = pk2(l0, l1); lp.y = pk2(l2, l3);
    *(uint2*)(hi + base) = hp;
    *(uint2*)(lo + base) = lp;
}

__global__ __launch_bounds__(256)
void split_xc_kernel(const float* __restrict__ x, const float* __restrict__ c) {
    int idx = blockIdx.x * 256 + threadIdx.x;
    const float* src;
    __nv_bfloat16 *hi, *lo;
    if (idx < MTOT * D / 4) { src = x; hi = s_x_hi; lo = s_x_lo; }
    else { idx -= MTOT * D / 4; src = c; hi = s_c_hi; lo = s_c_lo; }
    float4 v = ((const float4*)src)[idx];
    split4_store(v, hi, lo, idx * 4);
}

__global__ __launch_bounds__(256)
void split_w_kernel(const float* __restrict__ wq, const float* __restrict__ wk,
                    const float* __restrict__ wv, const float* __restrict__ wo) {
    __shared__ float tile[32][33];
    const int w = blockIdx.z;
    const float* W = (w == 0) ? wq : (w == 1) ? wk : (w == 2) ? wv : wo;
    const int kb = blockIdx.x * 32;
    const int nb = blockIdx.y * 32;
    const int tx = threadIdx.x & 31;
    const int ty = threadIdx.x >> 5;
#pragma unroll
    for (int i = ty; i < 32; i += 8)
        tile[i][tx] = W[(kb + i) * D + nb + tx];
    __syncthreads();
    __nv_bfloat16* oh = s_w_hi + w * D * D;
    __nv_bfloat16* ol = s_w_lo + w * D * D;
#pragma unroll
    for (int i = ty; i < 32; i += 8) {
        float v = tile[tx][i];
        __nv_bfloat16 h, l;
        splitf(v, h, l);
        oh[(nb + i) * D + kb + tx] = h;
        ol[(nb + i) * D + kb + tx] = l;
    }
}

// ---------------------------------------------------------------------------
// HMMA flash attention with banded relative bias + relative-value add.
// CTA: 128 queries x full 1024-key sweep (k-tiles of 64). 8 warps, m16 each.
// Q/K via ldmatrix.trans from natural [c][tok] smem; V non-trans ([c][tok]=[n][k]).
// Split-precision: S = QhKh+QlKh+QhKl ; PV = PhVh+PlVh+PhVl.
// Writes bf16 hi/lo output directly (faithful-reshape remapped flat index).
// ---------------------------------------------------------------------------
#define SQ 136
#define SK 72
#define OSTRIDE 68
#define OFF_Q   0
#define OFF_KHI 34816
#define OFF_KLO 44032
#define OFF_VHI 53248
#define OFF_VLO 62464
#define OFF_EK  71680
#define OFF_EV  73984
#define OFF_RB  76288
#define OFF_MS  82432
#define OFF_LS  82944
#define ATT_SMEM 83456

__global__ __launch_bounds__(256)
void attn_mma_kernel(const float* __restrict__ ek, const float* __restrict__ ev) {
    extern __shared__ char sm[];
    __nv_bfloat16* qhi = (__nv_bfloat16*)(sm + OFF_Q);
    __nv_bfloat16* qlo = (__nv_bfloat16*)(sm + OFF_Q + 17408);
    float* ost = (float*)(sm + OFF_Q);             // reuses Q region at finalize
    __nv_bfloat16* khi = (__nv_bfloat16*)(sm + OFF_KHI);
    __nv_bfloat16* klo = (__nv_bfloat16*)(sm + OFF_KLO);
    __nv_bfloat16* vhi = (__nv_bfloat16*)(sm + OFF_VHI);
    __nv_bfloat16* vlo = (__nv_bfloat16*)(sm + OFF_VLO);
    float* ek_s = (float*)(sm + OFF_EK);
    float* ev_s = (float*)(sm + OFF_EV);
    float* rbw  = (float*)(sm + OFF_RB);           // rb in mainloop, w at finalize
    float* m_s  = (float*)(sm + OFF_MS);
    float* l_s  = (float*)(sm + OFF_LS);

    const int tid = threadIdx.x, wid = tid >> 5, lane = tid & 31;
    const int bh = blockIdx.y, q0 = blockIdx.x * 128;
    const float* Qb = g_q + bh * 65536;
    const float* Kb = g_k + bh * 65536;
    const float* Vb = g_v + bh * 65536;

    for (int i = tid; i < 576; i += 256) { ek_s[i] = ek[i]; ev_s[i] = ev[i]; }

    // Q tile: [c 0..63][tok 128], scaled by inv_sqrt, split hi/lo.
#pragma unroll
    for (int u = 0; u < 8; ++u) {
        int fi = tid + u * 256;                 // 0..2047
        int c = fi >> 5, c4 = (fi & 31) << 2;
        float4 v = *(const float4*)(Qb + c * 1024 + q0 + c4);
        v.x *= 0.125f; v.y *= 0.125f; v.z *= 0.125f; v.w *= 0.125f;
        __nv_bfloat16 h0,h1,h2,h3,l0,l1,l2,l3;
        splitf(v.x,h0,l0); splitf(v.y,h1,l1); splitf(v.z,h2,l2); splitf(v.w,h3,l3);
        uint2 hp; hp.x = pk2(h0,h1); hp.y = pk2(h2,h3);
        uint2 lp; lp.x = pk2(l0,l1); lp.y = pk2(l2,l3);
        *(uint2*)(qhi + c * SQ + c4) = hp;
        *(uint2*)(qlo + c * SQ + c4) = lp;
    }
    __syncthreads();

    // rb[tok][r] = inv_sqrt * (q_tok . ek[r])   (fp32)
    if (tid < 128) {
        float qv[64];
#pragma unroll
        for (int c = 0; c < 64; ++c) qv[c] = Qb[c * 1024 + q0 + tid];
#pragma unroll
        for (int r = 0; r < 9; ++r) {
            float s = 0.f;
#pragma unroll
            for (int c = 0; c < 64; ++c) s += qv[c] * ek_s[r * 64 + c];
            rbw[tid * 12 + r] = s * 0.125f;
        }
    }

    // Q A-fragments (persistent): m16 x k16 per ks, hi and lo.
    const int wm = wid * 16;
    uint32_t qfh[4][4], qfl[4][4];
    {
        const uint32_t smq_hi = smem_u32(qhi), smq_lo = smem_u32(qlo);
        int coff = (lane & 7) + ((lane >> 4) << 3);
        int tok  = wm + (((lane >> 3) & 1) << 3);
#pragma unroll
        for (int ks = 0; ks < 4; ++ks) {
            uint32_t off = (uint32_t)((ks * 16 + coff) * SQ + tok) * 2;
            ldm_x4_t(smq_hi + off, qfh[ks]);
            ldm_x4_t(smq_lo + off, qfl[ks]);
        }
    }

    float m0 = -1e30f, m1 = -1e30f, l0 = 0.f, l1 = 0.f;
    float oacc[8][4] = {};

    // Prefetch K/V tile 0 into registers.
    float4 pkf[4], pvf[4];
#pragma unroll
    for (int u = 0; u < 4; ++u) {
        int fi = tid + u * 256;
        int row = fi >> 4, c4 = (fi & 15) << 2;
        pkf[u] = *(const float4*)(Kb + row * 1024 + c4);
        pvf[u] = *(const float4*)(Vb + row * 1024 + c4);
    }

    const uint32_t smk_hi = smem_u32(khi), smk_lo = smem_u32(klo);
    const uint32_t smv_hi = smem_u32(vhi), smv_lo = smem_u32(vlo);

    for (int kt = 0; kt < 16; ++kt) {
        const int kg = kt * 64;
        __syncthreads();
        // Convert prefetched fp32 -> bf16 hi/lo smem tiles [c][tok64].
#pragma unroll
        for (int u = 0; u < 4; ++u) {
            int fi = tid + u * 256;
            int row = fi >> 4, c4 = (fi & 15) << 2;
            {
                __nv_bfloat16 h0,h1,h2,h3,l0_,l1_,l2_,l3_;
                splitf(pkf[u].x,h0,l0_); splitf(pkf[u].y,h1,l1_);
                splitf(pkf[u].z,h2,l2_); splitf(pkf[u].w,h3,l3_);
                uint2 hp; hp.x = pk2(h0,h1); hp.y = pk2(h2,h3);
                uint2 lp; lp.x = pk2(l0_,l1_); lp.y = pk2(l2_,l3_);
                *(uint2*)(khi + row * SK + c4) = hp;
                *(uint2*)(klo + row * SK + c4) = lp;
            }
            {
                __nv_bfloat16 h0,h1,h2,h3,l0_,l1_,l2_,l3_;
                splitf(pvf[u].x,h0,l0_); splitf(pvf[u].y,h1,l1_);
                splitf(pvf[u].z,h2,l2_); splitf(pvf[u].w,h3,l3_);
                uint2 hp; hp.x = pk2(h0,h1); hp.y = pk2(h2,h3);
                uint2 lp; lp.x = pk2(l0_,l1_); lp.y = pk2(l2_,l3_);
                *(uint2*)(vhi + row * SK + c4) = hp;
                *(uint2*)(vlo + row * SK + c4) = lp;
            }
        }
        __syncthreads();
        if (kt < 15) {
#pragma unroll
            for (int u = 0; u < 4; ++u) {
                int fi = tid + u * 256;
                int row = fi >> 4, c4 = (fi & 15) << 2;
                pkf[u] = *(const float4*)(Kb + row * 1024 + kg + 64 + c4);
                pvf[u] = *(const float4*)(Vb + row * 1024 + kg + 64 + c4);
            }
        }

        // ---- S = Q.K^T (3-pass split) ----
        float sacc[8][4] = {};
#pragma unroll
        for (int ks = 0; ks < 4; ++ks) {
            int cK = ks * 16 + (lane & 7) + (((lane >> 3) & 1) << 3);
#pragma unroll
            for (int p = 0; p < 4; ++p) {
                int tokp = p * 16 + ((lane >> 4) << 3);
                uint32_t off = (uint32_t)(cK * SK + tokp) * 2;
                uint32_t r[4];
                ldm_x4_t(smk_hi + off, r);
                uint32_t b0[2] = {r[0], r[1]}, b1[2] = {r[2], r[3]};
                mma16816(sacc[2*p],   qfh[ks], b0);
                mma16816(sacc[2*p+1], qfh[ks], b1);
                mma16816(sacc[2*p],   qfl[ks], b0);
                mma16816(sacc[2*p+1], qfl[ks], b1);
                ldm_x4_t(smk_lo + off, r);
                uint32_t c0_[2] = {r[0], r[1]}, c1_[2] = {r[2], r[3]};
                mma16816(sacc[2*p],   qfh[ks], c0_);
                mma16816(sacc[2*p+1], qfh[ks], c1_);
            }
        }

        // ---- banded relative-key bias ----
        const int qwbase = q0 + wm;
        if (kg <= qwbase + 19 && kg + 63 >= qwbase - 4) {
            int qg0 = qwbase + (lane >> 2);
#pragma unroll
            for (int nj = 0; nj < 8; ++nj) {
                int kgg = kg + nj * 8 + ((lane & 3) << 1);
#pragma unroll
                for (int i = 0; i < 4; ++i) {
                    int qg = qg0 + ((i >> 1) << 3);
                    int r = kgg + (i & 1) - qg + 4;
                    if ((unsigned)r <= 8u)
                        sacc[nj][i] += rbw[(qg - q0) * 12 + r];
                }
            }
        }

        // ---- online softmax ----
        float mx0 = -1e30f, mx1 = -1e30f;
#pragma unroll
        for (int nj = 0; nj < 8; ++nj) {
            mx0 = fmaxf(mx0, fmaxf(sacc[nj][0], sacc[nj][1]));
            mx1 = fmaxf(mx1, fmaxf(sacc[nj][2], sacc[nj][3]));
        }
        mx0 = fmaxf(mx0, __shfl_xor_sync(0xffffffffu, mx0, 1));
        mx0 = fmaxf(mx0, __shfl_xor_sync(0xffffffffu, mx0, 2));
        mx1 = fmaxf(mx1, __shfl_xor_sync(0xffffffffu, mx1, 1));
        mx1 = fmaxf(mx1, __shfl_xor_sync(0xffffffffu, mx1, 2));
        float mn0 = fmaxf(m0, mx0), mn1 = fmaxf(m1, mx1);
        float cr0 = __expf(m0 - mn0), cr1 = __expf(m1 - mn1);
        m0 = mn0; m1 = mn1;

        float s0 = 0.f, s1 = 0.f;
        __nv_bfloat16 eh[8][4], el[8][4];
#pragma unroll
        for (int nj = 0; nj < 8; ++nj) {
#pragma unroll
            for (int i = 0; i < 4; ++i) {
                float e = __expf(sacc[nj][i] - ((i < 2) ? m0 : m1));
                if (i < 2) s0 += e; else s1 += e;
                splitf(e, eh[nj][i], el[nj][i]);
            }
        }
        s0 += __shfl_xor_sync(0xffffffffu, s0, 1);
        s0 += __shfl_xor_sync(0xffffffffu, s0, 2);
        s1 += __shfl_xor_sync(0xffffffffu, s1, 1);
        s1 += __shfl_xor_sync(0xffffffffu, s1, 2);
        l0 = l0 * cr0 + s0;
        l1 = l1 * cr1 + s1;
#pragma unroll
        for (int nj = 0; nj < 8; ++nj) {
            oacc[nj][0] *= cr0; oacc[nj][1] *= cr0;
            oacc[nj][2] *= cr1; oacc[nj][3] *= cr1;
        }

        // P fragments (A operand over keys)
        uint32_t pAh[4][4], pAl[4][4];
#pragma unroll
        for (int p = 0; p < 4; ++p) {
            pAh[p][0] = pk2(eh[2*p][0],   eh[2*p][1]);
            pAh[p][1] = pk2(eh[2*p][2],   eh[2*p][3]);
            pAh[p][2] = pk2(eh[2*p+1][0], eh[2*p+1][1]);
            pAh[p][3] = pk2(eh[2*p+1][2], eh[2*p+1][3]);
            pAl[p][0] = pk2(el[2*p][0],   el[2*p][1]);
            pAl[p][1] = pk2(el[2*p][2],   el[2*p][3]);
            pAl[p][2] = pk2(el[2*p+1][0], el[2*p+1][1]);
            pAl[p][3] = pk2(el[2*p+1][2], el[2*p+1][3]);
        }

        // ---- O += P.V (3-pass split) ----
#pragma unroll
        for (int ks = 0; ks < 4; ++ks) {
            int kV = ks * 16 + (((lane >> 3) & 1) << 3);
#pragma unroll
            for (int p = 0; p < 4; ++p) {
                int nV = p * 16 + (lane & 7) + ((lane >> 4) << 3);
                uint32_t off = (uint32_t)(nV * SK + kV) * 2;
                uint32_t r[4];
                ldm_x4(smv_hi + off, r);
                uint32_t b0[2] = {r[0], r[1]}, b1[2] = {r[2], r[3]};
                mma16816(oacc[2*p],   pAh[ks], b0);
                mma16816(oacc[2*p+1], pAh[ks], b1);
                mma16816(oacc[2*p],   pAl[ks], b0);
                mma16816(oacc[2*p+1], pAl[ks], b1);
                ldm_x4(smv_lo + off, r);
                uint32_t c0_[2] = {r[0], r[1]}, c1_[2] = {r[2], r[3]};
                mma16816(oacc[2*p],   pAh[ks], c0_);
                mma16816(oacc[2*p+1], pAh[ks], c1_);
            }
        }
    }

    // ---- finalize ----
    if ((lane & 3) == 0) {
        int row = wm + (lane >> 2);
        m_s[row] = m0; l_s[row] = l0;
        m_s[row + 8] = m1; l_s[row + 8] = l1;
    }
    __syncthreads();

    // Band weights w[tok][r] = exp(s_band - m_final)/l  (fp32 recompute).
    if (tid < 128) {
        float qv[64];
#pragma unroll
        for (int c = 0; c < 64; ++c) qv[c] = Qb[c * 1024 + q0 + tid];
        float mf = m_s[tid];
        float invl = 1.f / l_s[tid];
        int qg = q0 + tid;
        float w[9];
#pragma unroll
        for (int r = 0; r < 9; ++r) {
            int kj = qg + r - 4;
            float wv = 0.f;
            if (kj >= 0 && kj < 1024) {
                float s = 0.f;
#pragma unroll
                for (int c = 0; c < 64; ++c) s += qv[c] * Kb[c * 1024 + kj];
                float s2 = 0.f;
#pragma unroll
                for (int c = 0; c < 64; ++c) s2 += qv[c] * ek_s[r * 64 + c];
                wv = __expf((s + s2) * 0.125f - mf) * invl;
            }
            w[r] = wv;
        }
#pragma unroll
        for (int r = 0; r < 9; ++r) rbw[tid * 12 + r] = w[r];
    }
    __syncthreads();

    // O fragments -> staging smem [tok][c] with 1/l and band-ev add.
    {
        float inv0 = 1.f / l0, inv1 = 1.f / l1;
        int row0 = wm + (lane >> 2), row1 = row0 + 8;
        float w0[9], w1[9];
#pragma unroll
        for (int r = 0; r < 9; ++r) { w0[r] = rbw[row0 * 12 + r]; w1[r] = rbw[row1 * 12 + r]; }
#pragma unroll
        for (int nj = 0; nj < 8; ++nj) {
            int cb = nj * 8 + ((lane & 3) << 1);
#pragma unroll
            for (int i = 0; i < 4; ++i) {
                int cc = cb + (i & 1);
                const float* wr = (i < 2) ? w0 : w1;
                float band = 0.f;
#pragma unroll
                for (int r = 0; r < 9; ++r) band += wr[r] * ev_s[r * 64 + cc];
                float val = oacc[nj][i] * ((i < 2) ? inv0 : inv1) + band;
                ost[((i < 2) ? row0 : row1) * OSTRIDE + cc] = val;
            }
        }
    }
    __syncthreads();

    // Remapped bf16 hi/lo store (faithful reshape flat index).
    const size_t obase = (size_t)(bh >> 3) * 524288 + (size_t)(bh & 7) * 65536;
    for (int idx = tid; idx < 8192; idx += 256) {
        int c = idx >> 7, tl = idx & 127;
        float v = ost[tl * OSTRIDE + c];
        __nv_bfloat16 hh, ll;
        splitf(v, hh, ll);
        s_o_hi[obase + c * 1024 + q0 + tl] = hh;
        s_o_lo[obase + c * 1024 + q0 + tl] = ll;
    }
}

// ---------------------------------------------------------------------------
extern "C" void kernel_launch(void* const* d_in, const int* in_sizes, int n_in,
                              void* d_out, int out_size) {
    const float* x  = (const float*)d_in[0];
    const float* c  = (const float*)d_in[1];
    const float* wq = (const float*)d_in[2];
    const float* bq = (const float*)d_in[3];
    const float* wk = (const float*)d_in[4];
    const float* bk = (const float*)d_in[5];
    const float* wv = (const float*)d_in[6];
    const float* bv = (const float*)d_in[7];
    const float* wo = (const float*)d_in[8];
    const float* bo = (const float*)d_in[9];
    const float* ek = (const float*)d_in[10];
    const float* ev = (const float*)d_in[11];
    float* out = (float*)d_out;

    cudaFuncSetAttribute(attn_mma_kernel,
                         cudaFuncAttributeMaxDynamicSharedMemorySize, ATT_SMEM);

    split_w_kernel<<<dim3(16, 16, 4), 256>>>(wq, wk, wv, wo);
    split_xc_kernel<<<4096, 256>>>(x, c);

    qkv_mma_kernel<<<dim3(4, 32, 3), 256>>>(bq, bk, bv);

    attn_mma_kernel<<<dim3(8, 32), 256, ATT_SMEM>>>(ek, ev);

    out_mma_kernel<<<dim3(4, 32), 256>>>(bo, out);
}

// round 7
// speedup vs baseline: 3.9322x; 1.3585x over previous
#include <cuda_runtime.h>
#include <cuda_bf16.h>
#include <cstdint>

#define T      1024
#define D      512
#define KC     64
#define BATCH  4
#define BH     (BATCH * 8)
#define MTOT   (BATCH * T)

// ---------------------------------------------------------------------------
// Device scratch (no allocation allowed)
// ---------------------------------------------------------------------------
__device__ float g_q[MTOT * D];
__device__ float g_k[MTOT * D];
__device__ float g_v[MTOT * D];

__device__ __nv_bfloat16 s_x_hi[MTOT * D];
__device__ __nv_bfloat16 s_x_lo[MTOT * D];
__device__ __nv_bfloat16 s_c_hi[MTOT * D];
__device__ __nv_bfloat16 s_c_lo[MTOT * D];
__device__ __nv_bfloat16 s_o_hi[MTOT * D];
__device__ __nv_bfloat16 s_o_lo[MTOT * D];
__device__ __nv_bfloat16 s_w_hi[4 * D * D];
__device__ __nv_bfloat16 s_w_lo[4 * D * D];
// Pre-split attention operands ([bh][c][t] layout). Q pre-scaled by inv_sqrt.
__device__ __nv_bfloat16 a_q_hi[MTOT * D];
__device__ __nv_bfloat16 a_q_lo[MTOT * D];
__device__ __nv_bfloat16 a_k_hi[MTOT * D];
__device__ __nv_bfloat16 a_k_lo[MTOT * D];
__device__ __nv_bfloat16 a_v_hi[MTOT * D];
__device__ __nv_bfloat16 a_v_lo[MTOT * D];

__device__ __forceinline__ uint32_t smem_u32(const void* p) {
    uint32_t a;
    asm("{ .reg .u64 t; cvta.to.shared.u64 t, %1; cvt.u32.u64 %0, t; }" : "=r"(a) : "l"(p));
    return a;
}

__device__ __forceinline__ void cp_async16(uint32_t saddr, const void* gaddr) {
    asm volatile("cp.async.cg.shared.global [%0], [%1], 16;" :: "r"(saddr), "l"(gaddr));
}
__device__ __forceinline__ void cp_commit() {
    asm volatile("cp.async.commit_group;");
}

__device__ __forceinline__ void ldm_x4(uint32_t addr, uint32_t r[4]) {
    asm volatile("ldmatrix.sync.aligned.m8n8.x4.shared.b16 {%0,%1,%2,%3}, [%4];"
                 : "=r"(r[0]), "=r"(r[1]), "=r"(r[2]), "=r"(r[3]) : "r"(addr));
}
__device__ __forceinline__ void ldm_x4_t(uint32_t addr, uint32_t r[4]) {
    asm volatile("ldmatrix.sync.aligned.m8n8.x4.trans.shared.b16 {%0,%1,%2,%3}, [%4];"
                 : "=r"(r[0]), "=r"(r[1]), "=r"(r[2]), "=r"(r[3]) : "r"(addr));
}

__device__ __forceinline__ void mma16816(float c[4], const uint32_t a[4],
                                         const uint32_t b[2]) {
    asm volatile(
        "mma.sync.aligned.m16n8k16.row.col.f32.bf16.bf16.f32 "
        "{%0,%1,%2,%3}, {%4,%5,%6,%7}, {%8,%9}, {%0,%1,%2,%3};"
        : "+f"(c[0]), "+f"(c[1]), "+f"(c[2]), "+f"(c[3])
        : "r"(a[0]), "r"(a[1]), "r"(a[2]), "r"(a[3]), "r"(b[0]), "r"(b[1]));
}

__device__ __forceinline__ void splitf(float v, __nv_bfloat16& h, __nv_bfloat16& l) {
    h = __float2bfloat16(v);
    l = __float2bfloat16(v - __bfloat162float(h));
}
__device__ __forceinline__ uint32_t pk2(__nv_bfloat16 a, __nv_bfloat16 b) {
    __nv_bfloat162 t = __halves2bfloat162(a, b);
    return *(uint32_t*)&t;
}

// ---------------------------------------------------------------------------
// bf16 HMMA GEMM (validated R4): C[4096,512] = A @ W^T + bias.
// ---------------------------------------------------------------------------
#define BK        32
#define ASTRIDE   40
#define STAGE_ELEMS (128 * ASTRIDE)
#define NIT       48

__device__ __forceinline__ void mma_gemm_body(
    const __nv_bfloat16* __restrict__ a_hi, const __nv_bfloat16* __restrict__ a_lo,
    const __nv_bfloat16* __restrict__ w_hi, const __nv_bfloat16* __restrict__ w_lo,
    const float* __restrict__ bias, float* __restrict__ C) {
    __shared__ __nv_bfloat16 sA[2][STAGE_ELEMS];
    __shared__ __nv_bfloat16 sB[2][STAGE_ELEMS];

    const int tid  = threadIdx.x;
    const int wid  = tid >> 5;
    const int lane = tid & 31;
    const int n0   = blockIdx.x * 128;
    const int m0   = blockIdx.y * 128;

    const __nv_bfloat16* APS[3] = {a_hi, a_lo, a_hi};
    const __nv_bfloat16* BPS[3] = {w_hi, w_hi, w_lo};

    const int lrow   = tid >> 1;
    const int lcbase = (tid & 1) * 2;

    auto issue_load = [&](int it, int stage) {
        const __nv_bfloat16* A = APS[it >> 4];
        const __nv_bfloat16* B = BPS[it >> 4];
        const int k0 = (it & 15) * BK;
        const uint32_t sa0 = smem_u32(sA[stage]);
        const uint32_t sb0 = smem_u32(sB[stage]);
#pragma unroll
        for (int cc = 0; cc < 2; ++cc) {
            const int ch = lcbase + cc;
            const uint32_t soff = (uint32_t)(lrow * ASTRIDE + ch * 8) * 2;
            cp_async16(sa0 + soff, A + (m0 + lrow) * D + k0 + ch * 8);
            cp_async16(sb0 + soff, B + (n0 + lrow) * D + k0 + ch * 8);
        }
        cp_commit();
    };

    const int wm = (wid & 3) * 32;
    const int wn = (wid >> 2) * 64;

    float acc[2][8][4];
#pragma unroll
    for (int mi = 0; mi < 2; ++mi)
#pragma unroll
        for (int nj = 0; nj < 8; ++nj)
#pragma unroll
            for (int r = 0; r < 4; ++r) acc[mi][nj][r] = 0.f;

    issue_load(0, 0);

    for (int it = 0; it < NIT; ++it) {
        const int stage = it & 1;
        if (it + 1 < NIT) {
            issue_load(it + 1, stage ^ 1);
            asm volatile("cp.async.wait_group 1;");
        } else {
            asm volatile("cp.async.wait_group 0;");
        }
        __syncthreads();

        const uint32_t sAb = smem_u32(sA[stage]);
        const uint32_t sBb = smem_u32(sB[stage]);
#pragma unroll
        for (int ks = 0; ks < BK; ks += 16) {
            uint32_t afrag[2][4];
#pragma unroll
            for (int mi = 0; mi < 2; ++mi) {
                uint32_t addr = sAb +
                    (uint32_t)(((wm + mi * 16 + (lane & 15)) * ASTRIDE) +
                               ks + ((lane >> 4) << 3)) * 2;
                ldm_x4(addr, afrag[mi]);
            }
            uint32_t bfrag[8][2];
#pragma unroll
            for (int nq = 0; nq < 4; ++nq) {
                uint32_t r[4];
                uint32_t addr = sBb +
                    (uint32_t)(((wn + nq * 16 + (lane & 7) + ((lane >> 4) << 3)) * ASTRIDE) +
                               ks + (((lane >> 3) & 1) << 3)) * 2;
                ldm_x4(addr, r);
                bfrag[2 * nq][0]     = r[0];
                bfrag[2 * nq][1]     = r[1];
                bfrag[2 * nq + 1][0] = r[2];
                bfrag[2 * nq + 1][1] = r[3];
            }
#pragma unroll
            for (int mi = 0; mi < 2; ++mi)
#pragma unroll
                for (int nj = 0; nj < 8; ++nj)
                    mma16816(acc[mi][nj], afrag[mi], bfrag[nj]);
        }
        __syncthreads();
    }

    const int rbase = m0 + wm + (lane >> 2);
    const int cbase = n0 + wn + (lane & 3) * 2;
#pragma unroll
    for (int mi = 0; mi < 2; ++mi) {
#pragma unroll
        for (int nj = 0; nj < 8; ++nj) {
            const int col = cbase + nj * 8;
            const float2 bb = *(const float2*)(bias + col);
            float2 v0, v1;
            v0.x = acc[mi][nj][0] + bb.x;
            v0.y = acc[mi][nj][1] + bb.y;
            v1.x = acc[mi][nj][2] + bb.x;
            v1.y = acc[mi][nj][3] + bb.y;
            *(float2*)(C + (rbase + mi * 16) * D + col)     = v0;
            *(float2*)(C + (rbase + mi * 16 + 8) * D + col) = v1;
        }
    }
}

__global__ __launch_bounds__(256)
void qkv_mma_kernel(const float* __restrict__ bq, const float* __restrict__ bk,
                    const float* __restrict__ bv) {
    if (blockIdx.z == 0)
        mma_gemm_body(s_x_hi, s_x_lo, s_w_hi, s_w_lo, bq, g_q);
    else if (blockIdx.z == 1)
        mma_gemm_body(s_c_hi, s_c_lo, s_w_hi + D * D, s_w_lo + D * D, bk, g_k);
    else
        mma_gemm_body(s_c_hi, s_c_lo, s_w_hi + 2 * D * D, s_w_lo + 2 * D * D, bv, g_v);
}

__global__ __launch_bounds__(256)
void out_mma_kernel(const float* __restrict__ bo, float* __restrict__ out) {
    mma_gemm_body(s_o_hi, s_o_lo, s_w_hi + 3 * D * D, s_w_lo + 3 * D * D, bo, out);
}

// ---------------------------------------------------------------------------
// Split kernels
// ---------------------------------------------------------------------------
__device__ __forceinline__ void split4_store(float4 v, __nv_bfloat16* hi,
                                             __nv_bfloat16* lo, int base) {
    __nv_bfloat16 h0, h1, h2, h3, l0, l1, l2, l3;
    splitf(v.x, h0, l0); splitf(v.y, h1, l1);
    splitf(v.z, h2, l2); splitf(v.w, h3, l3);
    uint2 hp, lp;
    hp.x = pk2(h0, h1); hp.y = pk2(h2, h3);
    lp.x = pk2(l0, l1); lp.y = pk2(l2, l3);
    *(uint2*)(hi + base) = hp;
    *(uint2*)(lo + base) = lp;
}

__global__ __launch_bounds__(256)
void split_xc_kernel(const float* __restrict__ x, const float* __restrict__ c) {
    int idx = blockIdx.x * 256 + threadIdx.x;
    const float* src;
    __nv_bfloat16 *hi, *lo;
    if (idx < MTOT * D / 4) { src = x; hi = s_x_hi; lo = s_x_lo; }
    else { idx -= MTOT * D / 4; src = c; hi = s_c_hi; lo = s_c_lo; }
    float4 v = ((const float4*)src)[idx];
    split4_store(v, hi, lo, idx * 4);
}

// Pre-split Q (scaled by inv_sqrt), K, V into bf16 hi/lo global buffers.
__global__ __launch_bounds__(256)
void presplit_qkv_kernel() {
    int idx = blockIdx.x * 256 + threadIdx.x;     // float4 index, 0..524287
    const float* src;
    __nv_bfloat16 *hi, *lo;
    float scale = 1.f;
    if (blockIdx.y == 0)      { src = g_q; hi = a_q_hi; lo = a_q_lo; scale = 0.125f; }
    else if (blockIdx.y == 1) { src = g_k; hi = a_k_hi; lo = a_k_lo; }
    else                      { src = g_v; hi = a_v_hi; lo = a_v_lo; }
    float4 v = ((const float4*)src)[idx];
    v.x *= scale; v.y *= scale; v.z *= scale; v.w *= scale;
    split4_store(v, hi, lo, idx * 4);
}

__global__ __launch_bounds__(256)
void split_w_kernel(const float* __restrict__ wq, const float* __restrict__ wk,
                    const float* __restrict__ wv, const float* __restrict__ wo) {
    __shared__ float tile[32][33];
    const int w = blockIdx.z;
    const float* W = (w == 0) ? wq : (w == 1) ? wk : (w == 2) ? wv : wo;
    const int kb = blockIdx.x * 32;
    const int nb = blockIdx.y * 32;
    const int tx = threadIdx.x & 31;
    const int ty = threadIdx.x >> 5;
#pragma unroll
    for (int i = ty; i < 32; i += 8)
        tile[i][tx] = W[(kb + i) * D + nb + tx];
    __syncthreads();
    __nv_bfloat16* oh = s_w_hi + w * D * D;
    __nv_bfloat16* ol = s_w_lo + w * D * D;
#pragma unroll
    for (int i = ty; i < 32; i += 8) {
        float v = tile[tx][i];
        __nv_bfloat16 h, l;
        splitf(v, h, l);
        oh[(nb + i) * D + kb + tx] = h;
        ol[(nb + i) * D + kb + tx] = l;
    }
}

// ---------------------------------------------------------------------------
// HMMA flash attention, pre-split operands + cp.async double-buffered K/V.
// CTA: 128 queries x 1024-key sweep (k-tiles of 64). 8 warps, m16 each.
// ---------------------------------------------------------------------------
#define SQ 136
#define SK 72
#define OSTRIDE 68
#define KVCOMP  9216                     // 64 * SK * 2 bytes per component
#define KVSTAGE (4 * KVCOMP)             // khi,klo,vhi,vlo
#define OFF_Q   0
#define OFF_KV  34816
#define OFF_EK  (OFF_KV + 2 * KVSTAGE)   // 108544
#define OFF_EV  (OFF_EK + 2304)
#define OFF_RB  (OFF_EV + 2304)
#define OFF_MS  (OFF_RB + 6144)
#define OFF_LS  (OFF_MS + 512)
#define ATT_SMEM (OFF_LS + 512)          // 120320

__global__ __launch_bounds__(256)
void attn_mma_kernel(const float* __restrict__ ek, const float* __restrict__ ev) {
    extern __shared__ char sm[];
    float* ost = (float*)(sm + OFF_Q);            // finalize staging (reuses Q)
    float* ek_s = (float*)(sm + OFF_EK);
    float* ev_s = (float*)(sm + OFF_EV);
    float* rbw  = (float*)(sm + OFF_RB);
    float* m_s  = (float*)(sm + OFF_MS);
    float* l_s  = (float*)(sm + OFF_LS);

    const int tid = threadIdx.x, wid = tid >> 5, lane = tid & 31;
    const int bh = blockIdx.y, q0 = blockIdx.x * 128;
    const size_t base = (size_t)bh * 65536;
    const float* Qb = g_q + base;
    const float* Kb = g_k + base;

    const uint32_t smq = smem_u32(sm + OFF_Q);

    // Issue Q tile loads (qhi, qlo): [c 0..63][tok 128] rows of 256B.
#pragma unroll
    for (int u = 0; u < 8; ++u) {
        int idx = tid + u * 256;          // 0..2047
        int comp = idx >> 10;             // 0=hi 1=lo
        int rem  = idx & 1023;
        int row  = rem >> 4, ch = rem & 15;
        const __nv_bfloat16* src = (comp ? a_q_lo : a_q_hi) + base + row * 1024 + q0 + ch * 8;
        cp_async16(smq + comp * 17408 + (uint32_t)(row * SQ + ch * 8) * 2, src);
    }
    cp_commit();

    // Issue K/V stage 0.
    const uint32_t smkv = smem_u32(sm + OFF_KV);
    {
        int comp = tid >> 6, row = tid & 63;
        const __nv_bfloat16* srcs[4] = {a_k_hi + base, a_k_lo + base,
                                        a_v_hi + base, a_v_lo + base};
        const __nv_bfloat16* src = srcs[comp] + row * 1024;
        uint32_t dst = smkv + comp * KVCOMP + (uint32_t)(row * SK) * 2;
#pragma unroll
        for (int ch = 0; ch < 8; ++ch)
            cp_async16(dst + ch * 16, src + ch * 8);
    }
    cp_commit();

    for (int i = tid; i < 576; i += 256) { ek_s[i] = ek[i]; ev_s[i] = ev[i]; }

    // rb[tok][r] = inv_sqrt * (q_tok . ek[r])   (fp32; overlaps cp.async)
    if (tid < 128) {
        float qv[64];
#pragma unroll
        for (int c = 0; c < 64; ++c) qv[c] = Qb[c * 1024 + q0 + tid];
#pragma unroll
        for (int r = 0; r < 9; ++r) {
            float s = 0.f;
#pragma unroll
            for (int c = 0; c < 64; ++c) s += qv[c] * ek_s[r * 64 + c];
            rbw[tid * 12 + r] = s * 0.125f;
        }
    }

    asm volatile("cp.async.wait_group 0;");
    __syncthreads();

    // Persistent Q A-fragments.
    const int wm = wid * 16;
    uint32_t qfh[4][4], qfl[4][4];
    {
        int coff = (lane & 7) + ((lane >> 4) << 3);
        int tok  = wm + (((lane >> 3) & 1) << 3);
#pragma unroll
        for (int ks = 0; ks < 4; ++ks) {
            uint32_t off = (uint32_t)((ks * 16 + coff) * SQ + tok) * 2;
            ldm_x4_t(smq + off, qfh[ks]);
            ldm_x4_t(smq + 17408 + off, qfl[ks]);
        }
    }

    float m0 = -1e30f, m1 = -1e30f, l0 = 0.f, l1 = 0.f;
    float oacc[8][4] = {};

    const int kvcomp = tid >> 6, kvrow = tid & 63;
    const __nv_bfloat16* kvsrcs[4] = {a_k_hi + base, a_k_lo + base,
                                      a_v_hi + base, a_v_lo + base};
    const __nv_bfloat16* kvsrc = kvsrcs[kvcomp] + kvrow * 1024;
    const uint32_t kvdst0 = smkv + kvcomp * KVCOMP + (uint32_t)(kvrow * SK) * 2;

    for (int kt = 0; kt < 16; ++kt) {
        const int kg = kt * 64;
        const uint32_t sbuf = smkv + (uint32_t)(kt & 1) * KVSTAGE;

        if (kt > 0) asm volatile("cp.async.wait_group 0;");
        __syncthreads();

        if (kt < 15) {  // issue next stage into other buffer
            uint32_t dst = kvdst0 + (uint32_t)((kt & 1) ^ 1) * KVSTAGE;
            const __nv_bfloat16* src = kvsrc + kg + 64;
#pragma unroll
            for (int ch = 0; ch < 8; ++ch)
                cp_async16(dst + ch * 16, src + ch * 8);
            cp_commit();
        }

        const uint32_t smk_hi = sbuf, smk_lo = sbuf + KVCOMP;
        const uint32_t smv_hi = sbuf + 2 * KVCOMP, smv_lo = sbuf + 3 * KVCOMP;

        // ---- S = Q.K^T (3-pass split) ----
        float sacc[8][4] = {};
#pragma unroll
        for (int ks = 0; ks < 4; ++ks) {
            int cK = ks * 16 + (lane & 7) + (((lane >> 3) & 1) << 3);
#pragma unroll
            for (int p = 0; p < 4; ++p) {
                int tokp = p * 16 + ((lane >> 4) << 3);
                uint32_t off = (uint32_t)(cK * SK + tokp) * 2;
                uint32_t r[4];
                ldm_x4_t(smk_hi + off, r);
                uint32_t b0[2] = {r[0], r[1]}, b1[2] = {r[2], r[3]};
                mma16816(sacc[2*p],   qfh[ks], b0);
                mma16816(sacc[2*p+1], qfh[ks], b1);
                mma16816(sacc[2*p],   qfl[ks], b0);
                mma16816(sacc[2*p+1], qfl[ks], b1);
                ldm_x4_t(smk_lo + off, r);
                uint32_t c0_[2] = {r[0], r[1]}, c1_[2] = {r[2], r[3]};
                mma16816(sacc[2*p],   qfh[ks], c0_);
                mma16816(sacc[2*p+1], qfh[ks], c1_);
            }
        }

        // ---- banded relative-key bias ----
        const int qwbase = q0 + wm;
        if (kg <= qwbase + 19 && kg + 63 >= qwbase - 4) {
            int qg0 = qwbase + (lane >> 2);
#pragma unroll
            for (int nj = 0; nj < 8; ++nj) {
                int kgg = kg + nj * 8 + ((lane & 3) << 1);
#pragma unroll
                for (int i = 0; i < 4; ++i) {
                    int qg = qg0 + ((i >> 1) << 3);
                    int r = kgg + (i & 1) - qg + 4;
                    if ((unsigned)r <= 8u)
                        sacc[nj][i] += rbw[(qg - q0) * 12 + r];
                }
            }
        }

        // ---- online softmax ----
        float mx0 = -1e30f, mx1 = -1e30f;
#pragma unroll
        for (int nj = 0; nj < 8; ++nj) {
            mx0 = fmaxf(mx0, fmaxf(sacc[nj][0], sacc[nj][1]));
            mx1 = fmaxf(mx1, fmaxf(sacc[nj][2], sacc[nj][3]));
        }
        mx0 = fmaxf(mx0, __shfl_xor_sync(0xffffffffu, mx0, 1));
        mx0 = fmaxf(mx0, __shfl_xor_sync(0xffffffffu, mx0, 2));
        mx1 = fmaxf(mx1, __shfl_xor_sync(0xffffffffu, mx1, 1));
        mx1 = fmaxf(mx1, __shfl_xor_sync(0xffffffffu, mx1, 2));
        float mn0 = fmaxf(m0, mx0), mn1 = fmaxf(m1, mx1);
        float cr0 = __expf(m0 - mn0), cr1 = __expf(m1 - mn1);
        m0 = mn0; m1 = mn1;

        float s0 = 0.f, s1 = 0.f;
        __nv_bfloat16 eh[8][4], el[8][4];
#pragma unroll
        for (int nj = 0; nj < 8; ++nj) {
#pragma unroll
            for (int i = 0; i < 4; ++i) {
                float e = __expf(sacc[nj][i] - ((i < 2) ? m0 : m1));
                if (i < 2) s0 += e; else s1 += e;
                splitf(e, eh[nj][i], el[nj][i]);
            }
        }
        s0 += __shfl_xor_sync(0xffffffffu, s0, 1);
        s0 += __shfl_xor_sync(0xffffffffu, s0, 2);
        s1 += __shfl_xor_sync(0xffffffffu, s1, 1);
        s1 += __shfl_xor_sync(0xffffffffu, s1, 2);
        l0 = l0 * cr0 + s0;
        l1 = l1 * cr1 + s1;
#pragma unroll
        for (int nj = 0; nj < 8; ++nj) {
            oacc[nj][0] *= cr0; oacc[nj][1] *= cr0;
            oacc[nj][2] *= cr1; oacc[nj][3] *= cr1;
        }

        uint32_t pAh[4][4], pAl[4][4];
#pragma unroll
        for (int p = 0; p < 4; ++p) {
            pAh[p][0] = pk2(eh[2*p][0],   eh[2*p][1]);
            pAh[p][1] = pk2(eh[2*p][2],   eh[2*p][3]);
            pAh[p][2] = pk2(eh[2*p+1][0], eh[2*p+1][1]);
            pAh[p][3] = pk2(eh[2*p+1][2], eh[2*p+1][3]);
            pAl[p][0] = pk2(el[2*p][0],   el[2*p][1]);
            pAl[p][1] = pk2(el[2*p][2],   el[2*p][3]);
            pAl[p][2] = pk2(el[2*p+1][0], el[2*p+1][1]);
            pAl[p][3] = pk2(el[2*p+1][2], el[2*p+1][3]);
        }

        // ---- O += P.V (3-pass split) ----
#pragma unroll
        for (int ks = 0; ks < 4; ++ks) {
            int kV = ks * 16 + (((lane >> 3) & 1) << 3);
#pragma unroll
            for (int p = 0; p < 4; ++p) {
                int nV = p * 16 + (lane & 7) + ((lane >> 4) << 3);
                uint32_t off = (uint32_t)(nV * SK + kV) * 2;
                uint32_t r[4];
                ldm_x4(smv_hi + off, r);
                uint32_t b0[2] = {r[0], r[1]}, b1[2] = {r[2], r[3]};
                mma16816(oacc[2*p],   pAh[ks], b0);
                mma16816(oacc[2*p+1], pAh[ks], b1);
                mma16816(oacc[2*p],   pAl[ks], b0);
                mma16816(oacc[2*p+1], pAl[ks], b1);
                ldm_x4(smv_lo + off, r);
                uint32_t c0_[2] = {r[0], r[1]}, c1_[2] = {r[2], r[3]};
                mma16816(oacc[2*p],   pAh[ks], c0_);
                mma16816(oacc[2*p+1], pAh[ks], c1_);
            }
        }
    }

    // ---- finalize ----
    if ((lane & 3) == 0) {
        int row = wm + (lane >> 2);
        m_s[row] = m0; l_s[row] = l0;
        m_s[row + 8] = m1; l_s[row + 8] = l1;
    }
    __syncthreads();

    // Band weights w[tok][r] = exp(s_band - m_final)/l  (fp32 recompute).
    if (tid < 128) {
        float qv[64];
#pragma unroll
        for (int c = 0; c < 64; ++c) qv[c] = Qb[c * 1024 + q0 + tid];
        float mf = m_s[tid];
        float invl = 1.f / l_s[tid];
        int qg = q0 + tid;
        float w[9];
#pragma unroll
        for (int r = 0; r < 9; ++r) {
            int kj = qg + r - 4;
            float wv = 0.f;
            if (kj >= 0 && kj < 1024) {
                float s = 0.f;
#pragma unroll
                for (int c = 0; c < 64; ++c) s += qv[c] * Kb[c * 1024 + kj];
                float s2 = 0.f;
#pragma unroll
                for (int c = 0; c < 64; ++c) s2 += qv[c] * ek_s[r * 64 + c];
                wv = __expf((s + s2) * 0.125f - mf) * invl;
            }
            w[r] = wv;
        }
#pragma unroll
        for (int r = 0; r < 9; ++r) rbw[tid * 12 + r] = w[r];
    }
    __syncthreads();

    // O fragments -> staging smem [tok][c] with 1/l and band-ev add.
    {
        float inv0 = 1.f / l0, inv1 = 1.f / l1;
        int row0 = wm + (lane >> 2), row1 = row0 + 8;
        float w0[9], w1[9];
#pragma unroll
        for (int r = 0; r < 9; ++r) { w0[r] = rbw[row0 * 12 + r]; w1[r] = rbw[row1 * 12 + r]; }
#pragma unroll
        for (int nj = 0; nj < 8; ++nj) {
            int cb = nj * 8 + ((lane & 3) << 1);
#pragma unroll
            for (int i = 0; i < 4; ++i) {
                int cc = cb + (i & 1);
                const float* wr = (i < 2) ? w0 : w1;
                float band = 0.f;
#pragma unroll
                for (int r = 0; r < 9; ++r) band += wr[r] * ev_s[r * 64 + cc];
                float val = oacc[nj][i] * ((i < 2) ? inv0 : inv1) + band;
                ost[((i < 2) ? row0 : row1) * OSTRIDE + cc] = val;
            }
        }
    }
    __syncthreads();

    // Remapped bf16 hi/lo store (faithful reshape flat index).
    const size_t obase = (size_t)(bh >> 3) * 524288 + (size_t)(bh & 7) * 65536;
    for (int idx = tid; idx < 8192; idx += 256) {
        int c = idx >> 7, tl = idx & 127;
        float v = ost[tl * OSTRIDE + c];
        __nv_bfloat16 hh, ll;
        splitf(v, hh, ll);
        s_o_hi[obase + c * 1024 + q0 + tl] = hh;
        s_o_lo[obase + c * 1024 + q0 + tl] = ll;
    }
}

// ---------------------------------------------------------------------------
extern "C" void kernel_launch(void* const* d_in, const int* in_sizes, int n_in,
                              void* d_out, int out_size) {
    const float* x  = (const float*)d_in[0];
    const float* c  = (const float*)d_in[1];
    const float* wq = (const float*)d_in[2];
    const float* bq = (const float*)d_in[3];
    const float* wk = (const float*)d_in[4];
    const float* bk = (const float*)d_in[5];
    const float* wv = (const float*)d_in[6];
    const float* bv = (const float*)d_in[7];
    const float* wo = (const float*)d_in[8];
    const float* bo = (const float*)d_in[9];
    const float* ek = (const float*)d_in[10];
    const float* ev = (const float*)d_in[11];
    float* out = (float*)d_out;

    cudaFuncSetAttribute(attn_mma_kernel,
                         cudaFuncAttributeMaxDynamicSharedMemorySize, ATT_SMEM);

    split_w_kernel<<<dim3(16, 16, 4), 256>>>(wq, wk, wv, wo);
    split_xc_kernel<<<4096, 256>>>(x, c);

    qkv_mma_kernel<<<dim3(4, 32, 3), 256>>>(bq, bk, bv);

    presplit_qkv_kernel<<<dim3(2048, 3), 256>>>();

    attn_mma_kernel<<<dim3(8, 32), 256, ATT_SMEM>>>(ek, ev);

    out_mma_kernel<<<dim3(4, 32), 256>>>(bo, out);
}

// round 8
// speedup vs baseline: 4.0285x; 1.0245x over previous
#include <cuda_runtime.h>
#include <cuda_bf16.h>
#include <cstdint>

#define T      1024
#define D      512
#define KC     64
#define BATCH  4
#define BH     (BATCH * 8)
#define MTOT   (BATCH * T)

// exp2-domain scale: 0.125 * log2(e)
#define QSCALE 0.1803368801111f

// ---------------------------------------------------------------------------
// Device scratch (no allocation allowed)
// ---------------------------------------------------------------------------
__device__ float g_q[MTOT * D];
__device__ float g_k[MTOT * D];
__device__ float g_v[MTOT * D];

__device__ __nv_bfloat16 s_x_hi[MTOT * D];
__device__ __nv_bfloat16 s_x_lo[MTOT * D];
__device__ __nv_bfloat16 s_c_hi[MTOT * D];
__device__ __nv_bfloat16 s_c_lo[MTOT * D];
__device__ __nv_bfloat16 s_o_hi[MTOT * D];
__device__ __nv_bfloat16 s_o_lo[MTOT * D];
__device__ __nv_bfloat16 s_w_hi[4 * D * D];
__device__ __nv_bfloat16 s_w_lo[4 * D * D];
// Pre-split attention operands ([bh][c][t]). Q pre-scaled by 0.125*log2(e).
__device__ __nv_bfloat16 a_q_hi[MTOT * D];
__device__ __nv_bfloat16 a_q_lo[MTOT * D];
__device__ __nv_bfloat16 a_k_hi[MTOT * D];
__device__ __nv_bfloat16 a_k_lo[MTOT * D];
__device__ __nv_bfloat16 a_v_hi[MTOT * D];
__device__ __nv_bfloat16 a_v_lo[MTOT * D];

__device__ __forceinline__ uint32_t smem_u32(const void* p) {
    uint32_t a;
    asm("{ .reg .u64 t; cvta.to.shared.u64 t, %1; cvt.u32.u64 %0, t; }" : "=r"(a) : "l"(p));
    return a;
}

__device__ __forceinline__ void cp_async16(uint32_t saddr, const void* gaddr) {
    asm volatile("cp.async.cg.shared.global [%0], [%1], 16;" :: "r"(saddr), "l"(gaddr));
}
__device__ __forceinline__ void cp_commit() {
    asm volatile("cp.async.commit_group;");
}

__device__ __forceinline__ void ldm_x4(uint32_t addr, uint32_t r[4]) {
    asm volatile("ldmatrix.sync.aligned.m8n8.x4.shared.b16 {%0,%1,%2,%3}, [%4];"
                 : "=r"(r[0]), "=r"(r[1]), "=r"(r[2]), "=r"(r[3]) : "r"(addr));
}
__device__ __forceinline__ void ldm_x4_t(uint32_t addr, uint32_t r[4]) {
    asm volatile("ldmatrix.sync.aligned.m8n8.x4.trans.shared.b16 {%0,%1,%2,%3}, [%4];"
                 : "=r"(r[0]), "=r"(r[1]), "=r"(r[2]), "=r"(r[3]) : "r"(addr));
}

__device__ __forceinline__ void mma16816(float c[4], const uint32_t a[4],
                                         const uint32_t b[2]) {
    asm volatile(
        "mma.sync.aligned.m16n8k16.row.col.f32.bf16.bf16.f32 "
        "{%0,%1,%2,%3}, {%4,%5,%6,%7}, {%8,%9}, {%0,%1,%2,%3};"
        : "+f"(c[0]), "+f"(c[1]), "+f"(c[2]), "+f"(c[3])
        : "r"(a[0]), "r"(a[1]), "r"(a[2]), "r"(a[3]), "r"(b[0]), "r"(b[1]));
}

__device__ __forceinline__ void splitf(float v, __nv_bfloat16& h, __nv_bfloat16& l) {
    h = __float2bfloat16(v);
    l = __float2bfloat16(v - __bfloat162float(h));
}
__device__ __forceinline__ uint32_t pk2(__nv_bfloat16 a, __nv_bfloat16 b) {
    __nv_bfloat162 t = __halves2bfloat162(a, b);
    return *(uint32_t*)&t;
}
__device__ __forceinline__ float ex2(float x) {
    float y;
    asm("ex2.approx.ftz.f32 %0, %1;" : "=f"(y) : "f"(x));
    return y;
}

// ---------------------------------------------------------------------------
// bf16 HMMA GEMM (validated R4): C[4096,512] = A @ W^T + bias.
// ---------------------------------------------------------------------------
#define BK        32
#define ASTRIDE   40
#define STAGE_ELEMS (128 * ASTRIDE)
#define NIT       48

__device__ __forceinline__ void mma_gemm_body(
    const __nv_bfloat16* __restrict__ a_hi, const __nv_bfloat16* __restrict__ a_lo,
    const __nv_bfloat16* __restrict__ w_hi, const __nv_bfloat16* __restrict__ w_lo,
    const float* __restrict__ bias, float* __restrict__ C) {
    __shared__ __nv_bfloat16 sA[2][STAGE_ELEMS];
    __shared__ __nv_bfloat16 sB[2][STAGE_ELEMS];

    const int tid  = threadIdx.x;
    const int wid  = tid >> 5;
    const int lane = tid & 31;
    const int n0   = blockIdx.x * 128;
    const int m0   = blockIdx.y * 128;

    const __nv_bfloat16* APS[3] = {a_hi, a_lo, a_hi};
    const __nv_bfloat16* BPS[3] = {w_hi, w_hi, w_lo};

    const int lrow   = tid >> 1;
    const int lcbase = (tid & 1) * 2;

    auto issue_load = [&](int it, int stage) {
        const __nv_bfloat16* A = APS[it >> 4];
        const __nv_bfloat16* B = BPS[it >> 4];
        const int k0 = (it & 15) * BK;
        const uint32_t sa0 = smem_u32(sA[stage]);
        const uint32_t sb0 = smem_u32(sB[stage]);
#pragma unroll
        for (int cc = 0; cc < 2; ++cc) {
            const int ch = lcbase + cc;
            const uint32_t soff = (uint32_t)(lrow * ASTRIDE + ch * 8) * 2;
            cp_async16(sa0 + soff, A + (m0 + lrow) * D + k0 + ch * 8);
            cp_async16(sb0 + soff, B + (n0 + lrow) * D + k0 + ch * 8);
        }
        cp_commit();
    };

    const int wm = (wid & 3) * 32;
    const int wn = (wid >> 2) * 64;

    float acc[2][8][4];
#pragma unroll
    for (int mi = 0; mi < 2; ++mi)
#pragma unroll
        for (int nj = 0; nj < 8; ++nj)
#pragma unroll
            for (int r = 0; r < 4; ++r) acc[mi][nj][r] = 0.f;

    issue_load(0, 0);

    for (int it = 0; it < NIT; ++it) {
        const int stage = it & 1;
        if (it + 1 < NIT) {
            issue_load(it + 1, stage ^ 1);
            asm volatile("cp.async.wait_group 1;");
        } else {
            asm volatile("cp.async.wait_group 0;");
        }
        __syncthreads();

        const uint32_t sAb = smem_u32(sA[stage]);
        const uint32_t sBb = smem_u32(sB[stage]);
#pragma unroll
        for (int ks = 0; ks < BK; ks += 16) {
            uint32_t afrag[2][4];
#pragma unroll
            for (int mi = 0; mi < 2; ++mi) {
                uint32_t addr = sAb +
                    (uint32_t)(((wm + mi * 16 + (lane & 15)) * ASTRIDE) +
                               ks + ((lane >> 4) << 3)) * 2;
                ldm_x4(addr, afrag[mi]);
            }
            uint32_t bfrag[8][2];
#pragma unroll
            for (int nq = 0; nq < 4; ++nq) {
                uint32_t r[4];
                uint32_t addr = sBb +
                    (uint32_t)(((wn + nq * 16 + (lane & 7) + ((lane >> 4) << 3)) * ASTRIDE) +
                               ks + (((lane >> 3) & 1) << 3)) * 2;
                ldm_x4(addr, r);
                bfrag[2 * nq][0]     = r[0];
                bfrag[2 * nq][1]     = r[1];
                bfrag[2 * nq + 1][0] = r[2];
                bfrag[2 * nq + 1][1] = r[3];
            }
#pragma unroll
            for (int mi = 0; mi < 2; ++mi)
#pragma unroll
                for (int nj = 0; nj < 8; ++nj)
                    mma16816(acc[mi][nj], afrag[mi], bfrag[nj]);
        }
        __syncthreads();
    }

    const int rbase = m0 + wm + (lane >> 2);
    const int cbase = n0 + wn + (lane & 3) * 2;
#pragma unroll
    for (int mi = 0; mi < 2; ++mi) {
#pragma unroll
        for (int nj = 0; nj < 8; ++nj) {
            const int col = cbase + nj * 8;
            const float2 bb = *(const float2*)(bias + col);
            float2 v0, v1;
            v0.x = acc[mi][nj][0] + bb.x;
            v0.y = acc[mi][nj][1] + bb.y;
            v1.x = acc[mi][nj][2] + bb.x;
            v1.y = acc[mi][nj][3] + bb.y;
            *(float2*)(C + (rbase + mi * 16) * D + col)     = v0;
            *(float2*)(C + (rbase + mi * 16 + 8) * D + col) = v1;
        }
    }
}

__global__ __launch_bounds__(256)
void qkv_mma_kernel(const float* __restrict__ bq, const float* __restrict__ bk,
                    const float* __restrict__ bv) {
    if (blockIdx.z == 0)
        mma_gemm_body(s_x_hi, s_x_lo, s_w_hi, s_w_lo, bq, g_q);
    else if (blockIdx.z == 1)
        mma_gemm_body(s_c_hi, s_c_lo, s_w_hi + D * D, s_w_lo + D * D, bk, g_k);
    else
        mma_gemm_body(s_c_hi, s_c_lo, s_w_hi + 2 * D * D, s_w_lo + 2 * D * D, bv, g_v);
}

__global__ __launch_bounds__(256)
void out_mma_kernel(const float* __restrict__ bo, float* __restrict__ out) {
    mma_gemm_body(s_o_hi, s_o_lo, s_w_hi + 3 * D * D, s_w_lo + 3 * D * D, bo, out);
}

// ---------------------------------------------------------------------------
// Split kernels
// ---------------------------------------------------------------------------
__device__ __forceinline__ void split4_store(float4 v, __nv_bfloat16* hi,
                                             __nv_bfloat16* lo, int base) {
    __nv_bfloat16 h0, h1, h2, h3, l0, l1, l2, l3;
    splitf(v.x, h0, l0); splitf(v.y, h1, l1);
    splitf(v.z, h2, l2); splitf(v.w, h3, l3);
    uint2 hp, lp;
    hp.x = pk2(h0, h1); hp.y = pk2(h2, h3);
    lp.x = pk2(l0, l1); lp.y = pk2(l2, l3);
    *(uint2*)(hi + base) = hp;
    *(uint2*)(lo + base) = lp;
}

__global__ __launch_bounds__(256)
void split_xc_kernel(const float* __restrict__ x, const float* __restrict__ c) {
    int idx = blockIdx.x * 256 + threadIdx.x;
    const float* src;
    __nv_bfloat16 *hi, *lo;
    if (idx < MTOT * D / 4) { src = x; hi = s_x_hi; lo = s_x_lo; }
    else { idx -= MTOT * D / 4; src = c; hi = s_c_hi; lo = s_c_lo; }
    float4 v = ((const float4*)src)[idx];
    split4_store(v, hi, lo, idx * 4);
}

// Pre-split Q (scaled by 0.125*log2e), K, V into bf16 hi/lo global buffers.
__global__ __launch_bounds__(256)
void presplit_qkv_kernel() {
    int idx = blockIdx.x * 256 + threadIdx.x;
    const float* src;
    __nv_bfloat16 *hi, *lo;
    float scale = 1.f;
    if (blockIdx.y == 0)      { src = g_q; hi = a_q_hi; lo = a_q_lo; scale = QSCALE; }
    else if (blockIdx.y == 1) { src = g_k; hi = a_k_hi; lo = a_k_lo; }
    else                      { src = g_v; hi = a_v_hi; lo = a_v_lo; }
    float4 v = ((const float4*)src)[idx];
    v.x *= scale; v.y *= scale; v.z *= scale; v.w *= scale;
    split4_store(v, hi, lo, idx * 4);
}

__global__ __launch_bounds__(256)
void split_w_kernel(const float* __restrict__ wq, const float* __restrict__ wk,
                    const float* __restrict__ wv, const float* __restrict__ wo) {
    __shared__ float tile[32][33];
    const int w = blockIdx.z;
    const float* W = (w == 0) ? wq : (w == 1) ? wk : (w == 2) ? wv : wo;
    const int kb = blockIdx.x * 32;
    const int nb = blockIdx.y * 32;
    const int tx = threadIdx.x & 31;
    const int ty = threadIdx.x >> 5;
#pragma unroll
    for (int i = ty; i < 32; i += 8)
        tile[i][tx] = W[(kb + i) * D + nb + tx];
    __syncthreads();
    __nv_bfloat16* oh = s_w_hi + w * D * D;
    __nv_bfloat16* ol = s_w_lo + w * D * D;
#pragma unroll
    for (int i = ty; i < 32; i += 8) {
        float v = tile[tx][i];
        __nv_bfloat16 h, l;
        splitf(v, h, l);
        oh[(nb + i) * D + kb + tx] = h;
        ol[(nb + i) * D + kb + tx] = l;
    }
}

// ---------------------------------------------------------------------------
// HMMA flash attention, fixed-m softmax (scores provably bounded), exp2 domain.
// CTA: 128 queries x 1024-key sweep (k-tiles of 64). 8 warps, m16 each.
// ---------------------------------------------------------------------------
#define SQ 136
#define SK 72
#define OSTRIDE 68
#define KVCOMP  9216
#define KVSTAGE (4 * KVCOMP)
#define OFF_Q   0
#define OFF_KV  34816
#define OFF_EK  (OFF_KV + 2 * KVSTAGE)
#define OFF_EV  (OFF_EK + 2304)
#define OFF_RB  (OFF_EV + 2304)
#define OFF_LS  (OFF_RB + 6144)
#define ATT_SMEM (OFF_LS + 512)

__global__ __launch_bounds__(256)
void attn_mma_kernel(const float* __restrict__ ek, const float* __restrict__ ev) {
    extern __shared__ char sm[];
    float* ost = (float*)(sm + OFF_Q);            // finalize staging (reuses Q)
    float* ek_s = (float*)(sm + OFF_EK);
    float* ev_s = (float*)(sm + OFF_EV);
    float* rbw  = (float*)(sm + OFF_RB);
    float* l_s  = (float*)(sm + OFF_LS);

    const int tid = threadIdx.x, wid = tid >> 5, lane = tid & 31;
    const int bh = blockIdx.y, q0 = blockIdx.x * 128;
    const size_t base = (size_t)bh * 65536;
    const float* Qb = g_q + base;
    const float* Kb = g_k + base;

    const uint32_t smq = smem_u32(sm + OFF_Q);

    // Q tile loads (qhi, qlo).
#pragma unroll
    for (int u = 0; u < 8; ++u) {
        int idx = tid + u * 256;
        int comp = idx >> 10;
        int rem  = idx & 1023;
        int row  = rem >> 4, ch = rem & 15;
        const __nv_bfloat16* src = (comp ? a_q_lo : a_q_hi) + base + row * 1024 + q0 + ch * 8;
        cp_async16(smq + comp * 17408 + (uint32_t)(row * SQ + ch * 8) * 2, src);
    }
    cp_commit();

    // K/V stage 0.
    const uint32_t smkv = smem_u32(sm + OFF_KV);
    {
        int comp = tid >> 6, row = tid & 63;
        const __nv_bfloat16* srcs[4] = {a_k_hi + base, a_k_lo + base,
                                        a_v_hi + base, a_v_lo + base};
        const __nv_bfloat16* src = srcs[comp] + row * 1024;
        uint32_t dst = smkv + comp * KVCOMP + (uint32_t)(row * SK) * 2;
#pragma unroll
        for (int ch = 0; ch < 8; ++ch)
            cp_async16(dst + ch * 16, src + ch * 8);
    }
    cp_commit();

    for (int i = tid; i < 576; i += 256) { ek_s[i] = ek[i]; ev_s[i] = ev[i]; }

    // rb[tok][r] = (q_tok . ek[r]) * 0.125 * log2e   (exp2 domain)
    if (tid < 128) {
        float qv[64];
#pragma unroll
        for (int c = 0; c < 64; ++c) qv[c] = Qb[c * 1024 + q0 + tid];
#pragma unroll
        for (int r = 0; r < 9; ++r) {
            float s = 0.f;
#pragma unroll
            for (int c = 0; c < 64; ++c) s += qv[c] * ek_s[r * 64 + c];
            rbw[tid * 12 + r] = s * QSCALE;
        }
    }

    asm volatile("cp.async.wait_group 0;");
    __syncthreads();

    // Persistent Q A-fragments.
    const int wm = wid * 16;
    uint32_t qfh[4][4], qfl[4][4];
    {
        int coff = (lane & 7) + ((lane >> 4) << 3);
        int tok  = wm + (((lane >> 3) & 1) << 3);
#pragma unroll
        for (int ks = 0; ks < 4; ++ks) {
            uint32_t off = (uint32_t)((ks * 16 + coff) * SQ + tok) * 2;
            ldm_x4_t(smq + off, qfh[ks]);
            ldm_x4_t(smq + 17408 + off, qfl[ks]);
        }
    }

    float l0 = 0.f, l1 = 0.f;      // per-thread partial row sums (fixed m = 0)
    float oacc[8][4] = {};

    const int kvcomp = tid >> 6, kvrow = tid & 63;
    const __nv_bfloat16* kvsrcs[4] = {a_k_hi + base, a_k_lo + base,
                                      a_v_hi + base, a_v_lo + base};
    const __nv_bfloat16* kvsrc = kvsrcs[kvcomp] + kvrow * 1024;
    const uint32_t kvdst0 = smkv + kvcomp * KVCOMP + (uint32_t)(kvrow * SK) * 2;

    for (int kt = 0; kt < 16; ++kt) {
        const int kg = kt * 64;
        const uint32_t sbuf = smkv + (uint32_t)(kt & 1) * KVSTAGE;

        if (kt > 0) asm volatile("cp.async.wait_group 0;");
        __syncthreads();

        if (kt < 15) {
            uint32_t dst = kvdst0 + (uint32_t)((kt & 1) ^ 1) * KVSTAGE;
            const __nv_bfloat16* src = kvsrc + kg + 64;
#pragma unroll
            for (int ch = 0; ch < 8; ++ch)
                cp_async16(dst + ch * 16, src + ch * 8);
            cp_commit();
        }

        const uint32_t smk_hi = sbuf, smk_lo = sbuf + KVCOMP;
        const uint32_t smv_hi = sbuf + 2 * KVCOMP, smv_lo = sbuf + 3 * KVCOMP;

        // ---- S = Q.K^T (3-pass split) ----
        float sacc[8][4] = {};
#pragma unroll
        for (int ks = 0; ks < 4; ++ks) {
            int cK = ks * 16 + (lane & 7) + (((lane >> 3) & 1) << 3);
#pragma unroll
            for (int p = 0; p < 4; ++p) {
                int tokp = p * 16 + ((lane >> 4) << 3);
                uint32_t off = (uint32_t)(cK * SK + tokp) * 2;
                uint32_t r[4];
                ldm_x4_t(smk_hi + off, r);
                uint32_t b0[2] = {r[0], r[1]}, b1[2] = {r[2], r[3]};
                mma16816(sacc[2*p],   qfh[ks], b0);
                mma16816(sacc[2*p+1], qfh[ks], b1);
                mma16816(sacc[2*p],   qfl[ks], b0);
                mma16816(sacc[2*p+1], qfl[ks], b1);
                ldm_x4_t(smk_lo + off, r);
                uint32_t c0_[2] = {r[0], r[1]}, c1_[2] = {r[2], r[3]};
                mma16816(sacc[2*p],   qfh[ks], c0_);
                mma16816(sacc[2*p+1], qfh[ks], c1_);
            }
        }

        // ---- banded relative-key bias ----
        const int qwbase = q0 + wm;
        if (kg <= qwbase + 19 && kg + 63 >= qwbase - 4) {
            int qg0 = qwbase + (lane >> 2);
#pragma unroll
            for (int nj = 0; nj < 8; ++nj) {
                int kgg = kg + nj * 8 + ((lane & 3) << 1);
#pragma unroll
                for (int i = 0; i < 4; ++i) {
                    int qg = qg0 + ((i >> 1) << 3);
                    int r = kgg + (i & 1) - qg + 4;
                    if ((unsigned)r <= 8u)
                        sacc[nj][i] += rbw[(qg - q0) * 12 + r];
                }
            }
        }

        // ---- fixed-m softmax: e = 2^s directly; accumulate l per-thread ----
        __nv_bfloat16 eh[8][4], el[8][4];
#pragma unroll
        for (int nj = 0; nj < 8; ++nj) {
#pragma unroll
            for (int i = 0; i < 4; ++i) {
                float e = ex2(sacc[nj][i]);
                if (i < 2) l0 += e; else l1 += e;
                splitf(e, eh[nj][i], el[nj][i]);
            }
        }

        uint32_t pAh[4][4], pAl[4][4];
#pragma unroll
        for (int p = 0; p < 4; ++p) {
            pAh[p][0] = pk2(eh[2*p][0],   eh[2*p][1]);
            pAh[p][1] = pk2(eh[2*p][2],   eh[2*p][3]);
            pAh[p][2] = pk2(eh[2*p+1][0], eh[2*p+1][1]);
            pAh[p][3] = pk2(eh[2*p+1][2], eh[2*p+1][3]);
            pAl[p][0] = pk2(el[2*p][0],   el[2*p][1]);
            pAl[p][1] = pk2(el[2*p][2],   el[2*p][3]);
            pAl[p][2] = pk2(el[2*p+1][0], el[2*p+1][1]);
            pAl[p][3] = pk2(el[2*p+1][2], el[2*p+1][3]);
        }

        // ---- O += P.V (3-pass split) ----
#pragma unroll
        for (int ks = 0; ks < 4; ++ks) {
            int kV = ks * 16 + (((lane >> 3) & 1) << 3);
#pragma unroll
            for (int p = 0; p < 4; ++p) {
                int nV = p * 16 + (lane & 7) + ((lane >> 4) << 3);
                uint32_t off = (uint32_t)(nV * SK + kV) * 2;
                uint32_t r[4];
                ldm_x4(smv_hi + off, r);
                uint32_t b0[2] = {r[0], r[1]}, b1[2] = {r[2], r[3]};
                mma16816(oacc[2*p],   pAh[ks], b0);
                mma16816(oacc[2*p+1], pAh[ks], b1);
                mma16816(oacc[2*p],   pAl[ks], b0);
                mma16816(oacc[2*p+1], pAl[ks], b1);
                ldm_x4(smv_lo + off, r);
                uint32_t c0_[2] = {r[0], r[1]}, c1_[2] = {r[2], r[3]};
                mma16816(oacc[2*p],   pAh[ks], c0_);
                mma16816(oacc[2*p+1], pAh[ks], c1_);
            }
        }
    }

    // ---- single end-of-loop l reduction across the quad ----
    l0 += __shfl_xor_sync(0xffffffffu, l0, 1);
    l0 += __shfl_xor_sync(0xffffffffu, l0, 2);
    l1 += __shfl_xor_sync(0xffffffffu, l1, 1);
    l1 += __shfl_xor_sync(0xffffffffu, l1, 2);

    if ((lane & 3) == 0) {
        int row = wm + (lane >> 2);
        l_s[row] = l0;
        l_s[row + 8] = l1;
    }
    __syncthreads();

    // Band weights w[tok][r] = 2^((s+s2)*QSCALE) / l  (fp32 recompute, m = 0).
    if (tid < 128) {
        float qv[64];
#pragma unroll
        for (int c = 0; c < 64; ++c) qv[c] = Qb[c * 1024 + q0 + tid];
        float invl = 1.f / l_s[tid];
        int qg = q0 + tid;
        float w[9];
#pragma unroll
        for (int r = 0; r < 9; ++r) {
            int kj = qg + r - 4;
            float wv = 0.f;
            if (kj >= 0 && kj < 1024) {
                float s = 0.f;
#pragma unroll
                for (int c = 0; c < 64; ++c) s += qv[c] * Kb[c * 1024 + kj];
                float s2 = 0.f;
#pragma unroll
                for (int c = 0; c < 64; ++c) s2 += qv[c] * ek_s[r * 64 + c];
                wv = ex2((s + s2) * QSCALE) * invl;
            }
            w[r] = wv;
        }
#pragma unroll
        for (int r = 0; r < 9; ++r) rbw[tid * 12 + r] = w[r];
    }
    __syncthreads();

    // O fragments -> staging smem [tok][c] with 1/l and band-ev add.
    {
        float inv0 = 1.f / l0, inv1 = 1.f / l1;
        int row0 = wm + (lane >> 2), row1 = row0 + 8;
        float w0[9], w1[9];
#pragma unroll
        for (int r = 0; r < 9; ++r) { w0[r] = rbw[row0 * 12 + r]; w1[r] = rbw[row1 * 12 + r]; }
#pragma unroll
        for (int nj = 0; nj < 8; ++nj) {
            int cb = nj * 8 + ((lane & 3) << 1);
#pragma unroll
            for (int i = 0; i < 4; ++i) {
                int cc = cb + (i & 1);
                const float* wr = (i < 2) ? w0 : w1;
                float band = 0.f;
#pragma unroll
                for (int r = 0; r < 9; ++r) band += wr[r] * ev_s[r * 64 + cc];
                float val = oacc[nj][i] * ((i < 2) ? inv0 : inv1) + band;
                ost[((i < 2) ? row0 : row1) * OSTRIDE + cc] = val;
            }
        }
    }
    __syncthreads();

    // Remapped bf16 hi/lo store (faithful reshape flat index).
    const size_t obase = (size_t)(bh >> 3) * 524288 + (size_t)(bh & 7) * 65536;
    for (int idx = tid; idx < 8192; idx += 256) {
        int c = idx >> 7, tl = idx & 127;
        float v = ost[tl * OSTRIDE + c];
        __nv_bfloat16 hh, ll;
        splitf(v, hh, ll);
        s_o_hi[obase + c * 1024 + q0 + tl] = hh;
        s_o_lo[obase + c * 1024 + q0 + tl] = ll;
    }
}

// ---------------------------------------------------------------------------
extern "C" void kernel_launch(void* const* d_in, const int* in_sizes, int n_in,
                              void* d_out, int out_size) {
    const float* x  = (const float*)d_in[0];
    const float* c  = (const float*)d_in[1];
    const float* wq = (const float*)d_in[2];
    const float* bq = (const float*)d_in[3];
    const float* wk = (const float*)d_in[4];
    const float* bk = (const float*)d_in[5];
    const float* wv = (const float*)d_in[6];
    const float* bv = (const float*)d_in[7];
    const float* wo = (const float*)d_in[8];
    const float* bo = (const float*)d_in[9];
    const float* ek = (const float*)d_in[10];
    const float* ev = (const float*)d_in[11];
    float* out = (float*)d_out;

    cudaFuncSetAttribute(attn_mma_kernel,
                         cudaFuncAttributeMaxDynamicSharedMemorySize, ATT_SMEM);

    split_w_kernel<<<dim3(16, 16, 4), 256>>>(wq, wk, wv, wo);
    split_xc_kernel<<<4096, 256>>>(x, c);

    qkv_mma_kernel<<<dim3(4, 32, 3), 256>>>(bq, bk, bv);

    presplit_qkv_kernel<<<dim3(2048, 3), 256>>>();

    attn_mma_kernel<<<dim3(8, 32), 256, ATT_SMEM>>>(ek, ev);

    out_mma_kernel<<<dim3(4, 32), 256>>>(bo, out);
}

// round 9
// speedup vs baseline: 5.3155x; 1.3195x over previous
#include <cuda_runtime.h>
#include <cuda_bf16.h>
#include <cuda_fp16.h>
#include <cstdint>

#define T      1024
#define D      512
#define KC     64
#define BATCH  4
#define BH     (BATCH * 8)
#define MTOT   (BATCH * T)

// exp2-domain scale: 0.125 * log2(e)
#define QSCALE 0.1803368801111f

// ---------------------------------------------------------------------------
// Device scratch (no allocation allowed)
// ---------------------------------------------------------------------------
__device__ float g_q[MTOT * D];
__device__ float g_k[MTOT * D];
__device__ float g_v[MTOT * D];

__device__ __nv_bfloat16 s_x_hi[MTOT * D];
__device__ __nv_bfloat16 s_x_lo[MTOT * D];
__device__ __nv_bfloat16 s_c_hi[MTOT * D];
__device__ __nv_bfloat16 s_c_lo[MTOT * D];
__device__ __nv_bfloat16 s_o_hi[MTOT * D];
__device__ __nv_bfloat16 s_o_lo[MTOT * D];
__device__ __nv_bfloat16 s_w_hi[4 * D * D];
__device__ __nv_bfloat16 s_w_lo[4 * D * D];
// Single-precision fp16 attention operands ([bh][c][t]); Q pre-scaled.
__device__ __half a_q_h[MTOT * D];
__device__ __half a_k_h[MTOT * D];
__device__ __half a_v_h[MTOT * D];

__device__ __forceinline__ uint32_t smem_u32(const void* p) {
    uint32_t a;
    asm("{ .reg .u64 t; cvta.to.shared.u64 t, %1; cvt.u32.u64 %0, t; }" : "=r"(a) : "l"(p));
    return a;
}

__device__ __forceinline__ void cp_async16(uint32_t saddr, const void* gaddr) {
    asm volatile("cp.async.cg.shared.global [%0], [%1], 16;" :: "r"(saddr), "l"(gaddr));
}
__device__ __forceinline__ void cp_commit() {
    asm volatile("cp.async.commit_group;");
}

__device__ __forceinline__ void ldm_x4(uint32_t addr, uint32_t r[4]) {
    asm volatile("ldmatrix.sync.aligned.m8n8.x4.shared.b16 {%0,%1,%2,%3}, [%4];"
                 : "=r"(r[0]), "=r"(r[1]), "=r"(r[2]), "=r"(r[3]) : "r"(addr));
}
__device__ __forceinline__ void ldm_x4_t(uint32_t addr, uint32_t r[4]) {
    asm volatile("ldmatrix.sync.aligned.m8n8.x4.trans.shared.b16 {%0,%1,%2,%3}, [%4];"
                 : "=r"(r[0]), "=r"(r[1]), "=r"(r[2]), "=r"(r[3]) : "r"(addr));
}

__device__ __forceinline__ void mma16816(float c[4], const uint32_t a[4],
                                         const uint32_t b[2]) {
    asm volatile(
        "mma.sync.aligned.m16n8k16.row.col.f32.bf16.bf16.f32 "
        "{%0,%1,%2,%3}, {%4,%5,%6,%7}, {%8,%9}, {%0,%1,%2,%3};"
        : "+f"(c[0]), "+f"(c[1]), "+f"(c[2]), "+f"(c[3])
        : "r"(a[0]), "r"(a[1]), "r"(a[2]), "r"(a[3]), "r"(b[0]), "r"(b[1]));
}
__device__ __forceinline__ void mma16816h(float c[4], const uint32_t a[4],
                                          const uint32_t b[2]) {
    asm volatile(
        "mma.sync.aligned.m16n8k16.row.col.f32.f16.f16.f32 "
        "{%0,%1,%2,%3}, {%4,%5,%6,%7}, {%8,%9}, {%0,%1,%2,%3};"
        : "+f"(c[0]), "+f"(c[1]), "+f"(c[2]), "+f"(c[3])
        : "r"(a[0]), "r"(a[1]), "r"(a[2]), "r"(a[3]), "r"(b[0]), "r"(b[1]));
}

__device__ __forceinline__ void splitf(float v, __nv_bfloat16& h, __nv_bfloat16& l) {
    h = __float2bfloat16(v);
    l = __float2bfloat16(v - __bfloat162float(h));
}
__device__ __forceinline__ uint32_t pk2(__nv_bfloat16 a, __nv_bfloat16 b) {
    __nv_bfloat162 t = __halves2bfloat162(a, b);
    return *(uint32_t*)&t;
}
__device__ __forceinline__ uint32_t pk2h(float a, float b) {
    __half2 t = __floats2half2_rn(a, b);
    return *(uint32_t*)&t;
}
__device__ __forceinline__ float ex2(float x) {
    float y;
    asm("ex2.approx.ftz.f32 %0, %1;" : "=f"(y) : "f"(x));
    return y;
}

// ---------------------------------------------------------------------------
// bf16 HMMA GEMM (validated R4): C[4096,512] = A @ W^T + bias.
// ---------------------------------------------------------------------------
#define BK        32
#define ASTRIDE   40
#define STAGE_ELEMS (128 * ASTRIDE)
#define NIT       48

__device__ __forceinline__ void mma_gemm_body(
    const __nv_bfloat16* __restrict__ a_hi, const __nv_bfloat16* __restrict__ a_lo,
    const __nv_bfloat16* __restrict__ w_hi, const __nv_bfloat16* __restrict__ w_lo,
    const float* __restrict__ bias, float* __restrict__ C) {
    __shared__ __nv_bfloat16 sA[2][STAGE_ELEMS];
    __shared__ __nv_bfloat16 sB[2][STAGE_ELEMS];

    const int tid  = threadIdx.x;
    const int wid  = tid >> 5;
    const int lane = tid & 31;
    const int n0   = blockIdx.x * 128;
    const int m0   = blockIdx.y * 128;

    const __nv_bfloat16* APS[3] = {a_hi, a_lo, a_hi};
    const __nv_bfloat16* BPS[3] = {w_hi, w_hi, w_lo};

    const int lrow   = tid >> 1;
    const int lcbase = (tid & 1) * 2;

    auto issue_load = [&](int it, int stage) {
        const __nv_bfloat16* A = APS[it >> 4];
        const __nv_bfloat16* B = BPS[it >> 4];
        const int k0 = (it & 15) * BK;
        const uint32_t sa0 = smem_u32(sA[stage]);
        const uint32_t sb0 = smem_u32(sB[stage]);
#pragma unroll
        for (int cc = 0; cc < 2; ++cc) {
            const int ch = lcbase + cc;
            const uint32_t soff = (uint32_t)(lrow * ASTRIDE + ch * 8) * 2;
            cp_async16(sa0 + soff, A + (m0 + lrow) * D + k0 + ch * 8);
            cp_async16(sb0 + soff, B + (n0 + lrow) * D + k0 + ch * 8);
        }
        cp_commit();
    };

    const int wm = (wid & 3) * 32;
    const int wn = (wid >> 2) * 64;

    float acc[2][8][4];
#pragma unroll
    for (int mi = 0; mi < 2; ++mi)
#pragma unroll
        for (int nj = 0; nj < 8; ++nj)
#pragma unroll
            for (int r = 0; r < 4; ++r) acc[mi][nj][r] = 0.f;

    issue_load(0, 0);

    for (int it = 0; it < NIT; ++it) {
        const int stage = it & 1;
        if (it + 1 < NIT) {
            issue_load(it + 1, stage ^ 1);
            asm volatile("cp.async.wait_group 1;");
        } else {
            asm volatile("cp.async.wait_group 0;");
        }
        __syncthreads();

        const uint32_t sAb = smem_u32(sA[stage]);
        const uint32_t sBb = smem_u32(sB[stage]);
#pragma unroll
        for (int ks = 0; ks < BK; ks += 16) {
            uint32_t afrag[2][4];
#pragma unroll
            for (int mi = 0; mi < 2; ++mi) {
                uint32_t addr = sAb +
                    (uint32_t)(((wm + mi * 16 + (lane & 15)) * ASTRIDE) +
                               ks + ((lane >> 4) << 3)) * 2;
                ldm_x4(addr, afrag[mi]);
            }
            uint32_t bfrag[8][2];
#pragma unroll
            for (int nq = 0; nq < 4; ++nq) {
                uint32_t r[4];
                uint32_t addr = sBb +
                    (uint32_t)(((wn + nq * 16 + (lane & 7) + ((lane >> 4) << 3)) * ASTRIDE) +
                               ks + (((lane >> 3) & 1) << 3)) * 2;
                ldm_x4(addr, r);
                bfrag[2 * nq][0]     = r[0];
                bfrag[2 * nq][1]     = r[1];
                bfrag[2 * nq + 1][0] = r[2];
                bfrag[2 * nq + 1][1] = r[3];
            }
#pragma unroll
            for (int mi = 0; mi < 2; ++mi)
#pragma unroll
                for (int nj = 0; nj < 8; ++nj)
                    mma16816(acc[mi][nj], afrag[mi], bfrag[nj]);
        }
        __syncthreads();
    }

    const int rbase = m0 + wm + (lane >> 2);
    const int cbase = n0 + wn + (lane & 3) * 2;
#pragma unroll
    for (int mi = 0; mi < 2; ++mi) {
#pragma unroll
        for (int nj = 0; nj < 8; ++nj) {
            const int col = cbase + nj * 8;
            const float2 bb = *(const float2*)(bias + col);
            float2 v0, v1;
            v0.x = acc[mi][nj][0] + bb.x;
            v0.y = acc[mi][nj][1] + bb.y;
            v1.x = acc[mi][nj][2] + bb.x;
            v1.y = acc[mi][nj][3] + bb.y;
            *(float2*)(C + (rbase + mi * 16) * D + col)     = v0;
            *(float2*)(C + (rbase + mi * 16 + 8) * D + col) = v1;
        }
    }
}

__global__ __launch_bounds__(256)
void qkv_mma_kernel(const float* __restrict__ bq, const float* __restrict__ bk,
                    const float* __restrict__ bv) {
    if (blockIdx.z == 0)
        mma_gemm_body(s_x_hi, s_x_lo, s_w_hi, s_w_lo, bq, g_q);
    else if (blockIdx.z == 1)
        mma_gemm_body(s_c_hi, s_c_lo, s_w_hi + D * D, s_w_lo + D * D, bk, g_k);
    else
        mma_gemm_body(s_c_hi, s_c_lo, s_w_hi + 2 * D * D, s_w_lo + 2 * D * D, bv, g_v);
}

__global__ __launch_bounds__(256)
void out_mma_kernel(const float* __restrict__ bo, float* __restrict__ out) {
    mma_gemm_body(s_o_hi, s_o_lo, s_w_hi + 3 * D * D, s_w_lo + 3 * D * D, bo, out);
}

// ---------------------------------------------------------------------------
// Split kernels
// ---------------------------------------------------------------------------
__device__ __forceinline__ void split4_store(float4 v, __nv_bfloat16* hi,
                                             __nv_bfloat16* lo, int base) {
    __nv_bfloat16 h0, h1, h2, h3, l0, l1, l2, l3;
    splitf(v.x, h0, l0); splitf(v.y, h1, l1);
    splitf(v.z, h2, l2); splitf(v.w, h3, l3);
    uint2 hp, lp;
    hp.x = pk2(h0, h1); hp.y = pk2(h2, h3);
    lp.x = pk2(l0, l1); lp.y = pk2(l2, l3);
    *(uint2*)(hi + base) = hp;
    *(uint2*)(lo + base) = lp;
}

__global__ __launch_bounds__(256)
void split_xc_kernel(const float* __restrict__ x, const float* __restrict__ c) {
    int idx = blockIdx.x * 256 + threadIdx.x;
    const float* src;
    __nv_bfloat16 *hi, *lo;
    if (idx < MTOT * D / 4) { src = x; hi = s_x_hi; lo = s_x_lo; }
    else { idx -= MTOT * D / 4; src = c; hi = s_c_hi; lo = s_c_lo; }
    float4 v = ((const float4*)src)[idx];
    split4_store(v, hi, lo, idx * 4);
}

// fp16 convert for attention operands; Q scaled by 0.125*log2e.
__global__ __launch_bounds__(256)
void presplit_qkv_kernel() {
    int idx = blockIdx.x * 256 + threadIdx.x;     // float4 index
    const float* src;
    __half* dst;
    float scale = 1.f;
    if (blockIdx.y == 0)      { src = g_q; dst = a_q_h; scale = QSCALE; }
    else if (blockIdx.y == 1) { src = g_k; dst = a_k_h; }
    else                      { src = g_v; dst = a_v_h; }
    float4 v = ((const float4*)src)[idx];
    uint2 p;
    p.x = pk2h(v.x * scale, v.y * scale);
    p.y = pk2h(v.z * scale, v.w * scale);
    *(uint2*)(dst + idx * 4) = p;
}

__global__ __launch_bounds__(256)
void split_w_kernel(const float* __restrict__ wq, const float* __restrict__ wk,
                    const float* __restrict__ wv, const float* __restrict__ wo) {
    __shared__ float tile[32][33];
    const int w = blockIdx.z;
    const float* W = (w == 0) ? wq : (w == 1) ? wk : (w == 2) ? wv : wo;
    const int kb = blockIdx.x * 32;
    const int nb = blockIdx.y * 32;
    const int tx = threadIdx.x & 31;
    const int ty = threadIdx.x >> 5;
#pragma unroll
    for (int i = ty; i < 32; i += 8)
        tile[i][tx] = W[(kb + i) * D + nb + tx];
    __syncthreads();
    __nv_bfloat16* oh = s_w_hi + w * D * D;
    __nv_bfloat16* ol = s_w_lo + w * D * D;
#pragma unroll
    for (int i = ty; i < 32; i += 8) {
        float v = tile[tx][i];
        __nv_bfloat16 h, l;
        splitf(v, h, l);
        oh[(nb + i) * D + kb + tx] = h;
        ol[(nb + i) * D + kb + tx] = l;
    }
}

// ---------------------------------------------------------------------------
// fp16 single-pass HMMA flash attention, fixed-m softmax, exp2 domain.
// CTA: 128 queries x 1024-key sweep (k-tiles of 64). 8 warps, m16 each.
// 2 CTAs/SM (regs<=128, smem 64KB) -> 256 CTAs in one wave.
// ---------------------------------------------------------------------------
#define SQ 136
#define SK 72
#define OSTRIDE 68
#define KVCOMP  9216                     // 64 ch * SK * 2B per component
#define KVSTAGE (2 * KVCOMP)             // K, V
#define OFF_Q   0
#define OFF_KV  17408
#define OFF_EK  (OFF_KV + 2 * KVSTAGE)   // 54272
#define OFF_EV  (OFF_EK + 2304)
#define OFF_RB  (OFF_EV + 2304)
#define OFF_LS  (OFF_RB + 6144)
#define ATT_SMEM (OFF_LS + 512)          // 65536

__global__ __launch_bounds__(256, 2)
void attn_mma_kernel(const float* __restrict__ ek, const float* __restrict__ ev) {
    extern __shared__ char sm[];
    float* ost = (float*)(sm + OFF_Q);            // finalize staging (reuses Q/KV)
    float* ek_s = (float*)(sm + OFF_EK);
    float* ev_s = (float*)(sm + OFF_EV);
    float* rbw  = (float*)(sm + OFF_RB);
    float* l_s  = (float*)(sm + OFF_LS);

    const int tid = threadIdx.x, wid = tid >> 5, lane = tid & 31;
    const int bh = blockIdx.y, q0 = blockIdx.x * 128;
    const size_t base = (size_t)bh * 65536;
    const float* Qb = g_q + base;
    const float* Kb = g_k + base;

    const uint32_t smq = smem_u32(sm + OFF_Q);

    // Q tile load: [c 0..63][tok 128] fp16 (256B rows).
#pragma unroll
    for (int u = 0; u < 4; ++u) {
        int idx = tid + u * 256;          // 0..1023
        int row = idx >> 4, ch = idx & 15;
        cp_async16(smq + (uint32_t)(row * SQ + ch * 8) * 2,
                   a_q_h + base + row * 1024 + q0 + ch * 8);
    }
    cp_commit();

    // K/V stage 0.
    const uint32_t smkv = smem_u32(sm + OFF_KV);
    const int kvcomp = tid >> 7, kvrow = (tid >> 1) & 63, kvhalf = tid & 1;
    const __half* kvsrc = (kvcomp ? a_v_h : a_k_h) + base + kvrow * 1024 + kvhalf * 32;
    const uint32_t kvdst0 = smkv + (uint32_t)kvcomp * KVCOMP +
                            (uint32_t)(kvrow * SK + kvhalf * 32) * 2;
    {
#pragma unroll
        for (int ch = 0; ch < 4; ++ch)
            cp_async16(kvdst0 + ch * 16, kvsrc + ch * 8);
    }
    cp_commit();

    for (int i = tid; i < 576; i += 256) { ek_s[i] = ek[i]; ev_s[i] = ev[i]; }

    // rb[tok][r] = (q_tok . ek[r]) * QSCALE   (exp2 domain, fp32)
    if (tid < 128) {
        float qv[64];
#pragma unroll
        for (int c = 0; c < 64; ++c) qv[c] = Qb[c * 1024 + q0 + tid];
#pragma unroll
        for (int r = 0; r < 9; ++r) {
            float s = 0.f;
#pragma unroll
            for (int c = 0; c < 64; ++c) s += qv[c] * ek_s[r * 64 + c];
            rbw[tid * 12 + r] = s * QSCALE;
        }
    }

    asm volatile("cp.async.wait_group 0;");
    __syncthreads();

    // Persistent Q A-fragments.
    const int wm = wid * 16;
    uint32_t qf[4][4];
    {
        int coff = (lane & 7) + ((lane >> 4) << 3);
        int tok  = wm + (((lane >> 3) & 1) << 3);
#pragma unroll
        for (int ks = 0; ks < 4; ++ks)
            ldm_x4_t(smq + (uint32_t)((ks * 16 + coff) * SQ + tok) * 2, qf[ks]);
    }

    float l0 = 0.f, l1 = 0.f;
    float oacc[8][4] = {};

    for (int kt = 0; kt < 16; ++kt) {
        const int kg = kt * 64;
        const uint32_t sbuf = smkv + (uint32_t)(kt & 1) * KVSTAGE;

        if (kt > 0) asm volatile("cp.async.wait_group 0;");
        __syncthreads();

        if (kt < 15) {
            uint32_t dst = kvdst0 + (uint32_t)((kt & 1) ^ 1) * KVSTAGE;
            const __half* src = kvsrc + kg + 64;
#pragma unroll
            for (int ch = 0; ch < 4; ++ch)
                cp_async16(dst + ch * 16, src + ch * 8);
            cp_commit();
        }

        const uint32_t smk = sbuf, smv = sbuf + KVCOMP;

        // ---- S = Q.K^T (single fp16 pass) ----
        float sacc[8][4] = {};
#pragma unroll
        for (int ks = 0; ks < 4; ++ks) {
            int cK = ks * 16 + (lane & 7) + (((lane >> 3) & 1) << 3);
#pragma unroll
            for (int p = 0; p < 4; ++p) {
                int tokp = p * 16 + ((lane >> 4) << 3);
                uint32_t r[4];
                ldm_x4_t(smk + (uint32_t)(cK * SK + tokp) * 2, r);
                uint32_t b0[2] = {r[0], r[1]}, b1[2] = {r[2], r[3]};
                mma16816h(sacc[2*p],   qf[ks], b0);
                mma16816h(sacc[2*p+1], qf[ks], b1);
            }
        }

        // ---- banded relative-key bias ----
        const int qwbase = q0 + wm;
        if (kg <= qwbase + 19 && kg + 63 >= qwbase - 4) {
            int qg0 = qwbase + (lane >> 2);
#pragma unroll
            for (int nj = 0; nj < 8; ++nj) {
                int kgg = kg + nj * 8 + ((lane & 3) << 1);
#pragma unroll
                for (int i = 0; i < 4; ++i) {
                    int qg = qg0 + ((i >> 1) << 3);
                    int r = kgg + (i & 1) - qg + 4;
                    if ((unsigned)r <= 8u)
                        sacc[nj][i] += rbw[(qg - q0) * 12 + r];
                }
            }
        }

        // ---- fixed-m softmax: e = 2^s; l per-thread; pack fp16 P frags ----
        uint32_t pA[4][4];
#pragma unroll
        for (int p = 0; p < 4; ++p) {
            float e00 = ex2(sacc[2*p][0]),   e01 = ex2(sacc[2*p][1]);
            float e02 = ex2(sacc[2*p][2]),   e03 = ex2(sacc[2*p][3]);
            float e10 = ex2(sacc[2*p+1][0]), e11 = ex2(sacc[2*p+1][1]);
            float e12 = ex2(sacc[2*p+1][2]), e13 = ex2(sacc[2*p+1][3]);
            l0 += e00 + e01 + e10 + e11;
            l1 += e02 + e03 + e12 + e13;
            pA[p][0] = pk2h(e00, e01);
            pA[p][1] = pk2h(e02, e03);
            pA[p][2] = pk2h(e10, e11);
            pA[p][3] = pk2h(e12, e13);
        }

        // ---- O += P.V (single fp16 pass) ----
#pragma unroll
        for (int ks = 0; ks < 4; ++ks) {
            int kV = ks * 16 + (((lane >> 3) & 1) << 3);
#pragma unroll
            for (int p = 0; p < 4; ++p) {
                int nV = p * 16 + (lane & 7) + ((lane >> 4) << 3);
                uint32_t r[4];
                ldm_x4(smv + (uint32_t)(nV * SK + kV) * 2, r);
                uint32_t b0[2] = {r[0], r[1]}, b1[2] = {r[2], r[3]};
                mma16816h(oacc[2*p],   pA[ks], b0);
                mma16816h(oacc[2*p+1], pA[ks], b1);
            }
        }
    }

    // ---- single end-of-loop l reduction across the quad ----
    l0 += __shfl_xor_sync(0xffffffffu, l0, 1);
    l0 += __shfl_xor_sync(0xffffffffu, l0, 2);
    l1 += __shfl_xor_sync(0xffffffffu, l1, 1);
    l1 += __shfl_xor_sync(0xffffffffu, l1, 2);

    if ((lane & 3) == 0) {
        int row = wm + (lane >> 2);
        l_s[row] = l0;
        l_s[row + 8] = l1;
    }
    __syncthreads();

    // Band weights w[tok][r] = 2^((s+s2)*QSCALE) / l  (fp32 recompute, m=0).
    if (tid < 128) {
        float qv[64];
#pragma unroll
        for (int c = 0; c < 64; ++c) qv[c] = Qb[c * 1024 + q0 + tid];
        float invl = 1.f / l_s[tid];
        int qg = q0 + tid;
        float w[9];
#pragma unroll
        for (int r = 0; r < 9; ++r) {
            int kj = qg + r - 4;
            float wv = 0.f;
            if (kj >= 0 && kj < 1024) {
                float s = 0.f;
#pragma unroll
                for (int c = 0; c < 64; ++c) s += qv[c] * Kb[c * 1024 + kj];
                float s2 = 0.f;
#pragma unroll
                for (int c = 0; c < 64; ++c) s2 += qv[c] * ek_s[r * 64 + c];
                wv = ex2((s + s2) * QSCALE) * invl;
            }
            w[r] = wv;
        }
#pragma unroll
        for (int r = 0; r < 9; ++r) rbw[tid * 12 + r] = w[r];
    }
    __syncthreads();

    // O fragments -> staging smem [tok][c] with 1/l and band-ev add.
    {
        float inv0 = 1.f / l0, inv1 = 1.f / l1;
        int row0 = wm + (lane >> 2), row1 = row0 + 8;
        float w0[9], w1[9];
#pragma unroll
        for (int r = 0; r < 9; ++r) { w0[r] = rbw[row0 * 12 + r]; w1[r] = rbw[row1 * 12 + r]; }
#pragma unroll
        for (int nj = 0; nj < 8; ++nj) {
            int cb = nj * 8 + ((lane & 3) << 1);
#pragma unroll
            for (int i = 0; i < 4; ++i) {
                int cc = cb + (i & 1);
                const float* wr = (i < 2) ? w0 : w1;
                float band = 0.f;
#pragma unroll
                for (int r = 0; r < 9; ++r) band += wr[r] * ev_s[r * 64 + cc];
                float val = oacc[nj][i] * ((i < 2) ? inv0 : inv1) + band;
                ost[((i < 2) ? row0 : row1) * OSTRIDE + cc] = val;
            }
        }
    }
    __syncthreads();

    // Remapped bf16 hi/lo store (faithful reshape flat index).
    const size_t obase = (size_t)(bh >> 3) * 524288 + (size_t)(bh & 7) * 65536;
    for (int idx = tid; idx < 8192; idx += 256) {
        int c = idx >> 7, tl = idx & 127;
        float v = ost[tl * OSTRIDE + c];
        __nv_bfloat16 hh, ll;
        splitf(v, hh, ll);
        s_o_hi[obase + c * 1024 + q0 + tl] = hh;
        s_o_lo[obase + c * 1024 + q0 + tl] = ll;
    }
}

// ---------------------------------------------------------------------------
extern "C" void kernel_launch(void* const* d_in, const int* in_sizes, int n_in,
                              void* d_out, int out_size) {
    const float* x  = (const float*)d_in[0];
    const float* c  = (const float*)d_in[1];
    const float* wq = (const float*)d_in[2];
    const float* bq = (const float*)d_in[3];
    const float* wk = (const float*)d_in[4];
    const float* bk = (const float*)d_in[5];
    const float* wv = (const float*)d_in[6];
    const float* bv = (const float*)d_in[7];
    const float* wo = (const float*)d_in[8];
    const float* bo = (const float*)d_in[9];
    const float* ek = (const float*)d_in[10];
    const float* ev = (const float*)d_in[11];
    float* out = (float*)d_out;

    cudaFuncSetAttribute(attn_mma_kernel,
                         cudaFuncAttributeMaxDynamicSharedMemorySize, ATT_SMEM);

    split_w_kernel<<<dim3(16, 16, 4), 256>>>(wq, wk, wv, wo);
    split_xc_kernel<<<4096, 256>>>(x, c);

    qkv_mma_kernel<<<dim3(4, 32, 3), 256>>>(bq, bk, bv);

    presplit_qkv_kernel<<<dim3(2048, 3), 256>>>();

    attn_mma_kernel<<<dim3(8, 32), 256, ATT_SMEM>>>(ek, ev);

    out_mma_kernel<<<dim3(4, 32), 256>>>(bo, out);
}

// round 11
// speedup vs baseline: 7.2096x; 1.3563x over previous
#include <cuda_runtime.h>
#include <cuda_bf16.h>
#include <cuda_fp16.h>
#include <cstdint>

#define T      1024
#define D      512
#define KC     64
#define BATCH  4
#define BH     (BATCH * 8)
#define MTOT   (BATCH * T)

// exp2-domain scale: 0.125 * log2(e)
#define QSCALE 0.1803368801111f

// ---------------------------------------------------------------------------
// Device scratch (no allocation allowed)
// ---------------------------------------------------------------------------
__device__ float g_q[MTOT * D];           // fp32 q (attn rb + band recompute)
__device__ float g_k[MTOT * D];           // fp32 k (attn band recompute)

__device__ __half h_x[MTOT * D];          // fp16 activations
__device__ __half h_c[MTOT * D];
__device__ __half h_wh[4 * D * D];        // fp16 weight split, [n][k], q/k/v/o
__device__ __half h_wl[4 * D * D];
__device__ __half a_q_h[MTOT * D];        // attn operands (q pre-scaled)
__device__ __half a_k_h[MTOT * D];
__device__ __half a_v_h[MTOT * D];
__device__ __half a_o_h[MTOT * D];        // attn output (out-GEMM A operand)

__device__ __forceinline__ uint32_t smem_u32(const void* p) {
    uint32_t a;
    asm("{ .reg .u64 t; cvta.to.shared.u64 t, %1; cvt.u32.u64 %0, t; }" : "=r"(a) : "l"(p));
    return a;
}

__device__ __forceinline__ void cp_async16(uint32_t saddr, const void* gaddr) {
    asm volatile("cp.async.cg.shared.global [%0], [%1], 16;" :: "r"(saddr), "l"(gaddr));
}
__device__ __forceinline__ void cp_commit() {
    asm volatile("cp.async.commit_group;");
}

__device__ __forceinline__ void ldm_x4(uint32_t addr, uint32_t r[4]) {
    asm volatile("ldmatrix.sync.aligned.m8n8.x4.shared.b16 {%0,%1,%2,%3}, [%4];"
                 : "=r"(r[0]), "=r"(r[1]), "=r"(r[2]), "=r"(r[3]) : "r"(addr));
}
__device__ __forceinline__ void ldm_x4_t(uint32_t addr, uint32_t r[4]) {
    asm volatile("ldmatrix.sync.aligned.m8n8.x4.trans.shared.b16 {%0,%1,%2,%3}, [%4];"
                 : "=r"(r[0]), "=r"(r[1]), "=r"(r[2]), "=r"(r[3]) : "r"(addr));
}

__device__ __forceinline__ void mma16816h(float c[4], const uint32_t a[4],
                                          const uint32_t b[2]) {
    asm volatile(
        "mma.sync.aligned.m16n8k16.row.col.f32.f16.f16.f32 "
        "{%0,%1,%2,%3}, {%4,%5,%6,%7}, {%8,%9}, {%0,%1,%2,%3};"
        : "+f"(c[0]), "+f"(c[1]), "+f"(c[2]), "+f"(c[3])
        : "r"(a[0]), "r"(a[1]), "r"(a[2]), "r"(a[3]), "r"(b[0]), "r"(b[1]));
}

__device__ __forceinline__ uint32_t pk2h(float a, float b) {
    __half2 t = __floats2half2_rn(a, b);
    return *(uint32_t*)&t;
}
__device__ __forceinline__ float ex2(float x) {
    float y;
    asm("ex2.approx.ftz.f32 %0, %1;" : "=f"(y) : "f"(x));
    return y;
}

// ---------------------------------------------------------------------------
// fp16 HMMA GEMM, 2-pass (A single fp16, W = Wh + Wl): C = A @ W^T + bias.
// CTA tile 128x128, 8 warps of 32x64, BK=32, cp.async double buffer.
// Optionally writes fp32 C and/or fp16 Ch (scaled) outputs.
// ---------------------------------------------------------------------------
#define BK        32
#define ASTRIDE   40
#define STAGE_ELEMS (128 * ASTRIDE)
#define NIT       32                     // 2 passes x 16 k-iters

__device__ __forceinline__ void mma_gemm_body_h(
    const __half* __restrict__ A,
    const __half* __restrict__ Wh, const __half* __restrict__ Wl,
    const float* __restrict__ bias,
    float* __restrict__ Cf, __half* __restrict__ Ch, float hscale) {
    __shared__ __half sA[2][STAGE_ELEMS];
    __shared__ __half sB[2][STAGE_ELEMS];

    const int tid  = threadIdx.x;
    const int wid  = tid >> 5;
    const int lane = tid & 31;
    const int n0   = blockIdx.x * 128;
    const int m0   = blockIdx.y * 128;

    const __half* BPS[2] = {Wh, Wl};

    const int lrow   = tid >> 1;
    const int lcbase = (tid & 1) * 2;

    auto issue_load = [&](int it, int stage) {
        const __half* B = BPS[it >> 4];
        const int k0 = (it & 15) * BK;
        const uint32_t sa0 = smem_u32(sA[stage]);
        const uint32_t sb0 = smem_u32(sB[stage]);
#pragma unroll
        for (int cc = 0; cc < 2; ++cc) {
            const int ch = lcbase + cc;
            const uint32_t soff = (uint32_t)(lrow * ASTRIDE + ch * 8) * 2;
            cp_async16(sa0 + soff, A + (m0 + lrow) * D + k0 + ch * 8);
            cp_async16(sb0 + soff, B + (n0 + lrow) * D + k0 + ch * 8);
        }
        cp_commit();
    };

    const int wm = (wid & 3) * 32;
    const int wn = (wid >> 2) * 64;

    float acc[2][8][4];
#pragma unroll
    for (int mi = 0; mi < 2; ++mi)
#pragma unroll
        for (int nj = 0; nj < 8; ++nj)
#pragma unroll
            for (int r = 0; r < 4; ++r) acc[mi][nj][r] = 0.f;

    issue_load(0, 0);

    for (int it = 0; it < NIT; ++it) {
        const int stage = it & 1;
        if (it + 1 < NIT) {
            issue_load(it + 1, stage ^ 1);
            asm volatile("cp.async.wait_group 1;");
        } else {
            asm volatile("cp.async.wait_group 0;");
        }
        __syncthreads();

        const uint32_t sAb = smem_u32(sA[stage]);
        const uint32_t sBb = smem_u32(sB[stage]);
#pragma unroll
        for (int ks = 0; ks < BK; ks += 16) {
            uint32_t afrag[2][4];
#pragma unroll
            for (int mi = 0; mi < 2; ++mi) {
                uint32_t addr = sAb +
                    (uint32_t)(((wm + mi * 16 + (lane & 15)) * ASTRIDE) +
                               ks + ((lane >> 4) << 3)) * 2;
                ldm_x4(addr, afrag[mi]);
            }
            uint32_t bfrag[8][2];
#pragma unroll
            for (int nq = 0; nq < 4; ++nq) {
                uint32_t r[4];
                uint32_t addr = sBb +
                    (uint32_t)(((wn + nq * 16 + (lane & 7) + ((lane >> 4) << 3)) * ASTRIDE) +
                               ks + (((lane >> 3) & 1) << 3)) * 2;
                ldm_x4(addr, r);
                bfrag[2 * nq][0]     = r[0];
                bfrag[2 * nq][1]     = r[1];
                bfrag[2 * nq + 1][0] = r[2];
                bfrag[2 * nq + 1][1] = r[3];
            }
#pragma unroll
            for (int mi = 0; mi < 2; ++mi)
#pragma unroll
                for (int nj = 0; nj < 8; ++nj)
                    mma16816h(acc[mi][nj], afrag[mi], bfrag[nj]);
        }
        __syncthreads();
    }

    const int rbase = m0 + wm + (lane >> 2);
    const int cbase = n0 + wn + (lane & 3) * 2;
#pragma unroll
    for (int mi = 0; mi < 2; ++mi) {
#pragma unroll
        for (int nj = 0; nj < 8; ++nj) {
            const int col = cbase + nj * 8;
            const float2 bb = *(const float2*)(bias + col);
            float2 v0, v1;
            v0.x = acc[mi][nj][0] + bb.x;
            v0.y = acc[mi][nj][1] + bb.y;
            v1.x = acc[mi][nj][2] + bb.x;
            v1.y = acc[mi][nj][3] + bb.y;
            const int r0 = (rbase + mi * 16) * D + col;
            const int r1 = (rbase + mi * 16 + 8) * D + col;
            if (Cf) {
                *(float2*)(Cf + r0) = v0;
                *(float2*)(Cf + r1) = v1;
            }
            if (Ch) {
                *(uint32_t*)(Ch + r0) = pk2h(v0.x * hscale, v0.y * hscale);
                *(uint32_t*)(Ch + r1) = pk2h(v1.x * hscale, v1.y * hscale);
            }
        }
    }
}

__global__ __launch_bounds__(256)
void qkv_mma_kernel(const float* __restrict__ bq, const float* __restrict__ bk,
                    const float* __restrict__ bv) {
    if (blockIdx.z == 0)
        mma_gemm_body_h(h_x, h_wh, h_wl, bq, g_q, a_q_h, QSCALE);
    else if (blockIdx.z == 1)
        mma_gemm_body_h(h_c, h_wh + D * D, h_wl + D * D, bk, g_k, a_k_h, 1.f);
    else
        mma_gemm_body_h(h_c, h_wh + 2 * D * D, h_wl + 2 * D * D, bv,
                        nullptr, a_v_h, 1.f);
}

__global__ __launch_bounds__(256)
void out_mma_kernel(const float* __restrict__ bo, float* __restrict__ out) {
    mma_gemm_body_h(a_o_h, h_wh + 3 * D * D, h_wl + 3 * D * D, bo,
                    out, nullptr, 1.f);
}

// ---------------------------------------------------------------------------
// Convert kernels
// ---------------------------------------------------------------------------
__global__ __launch_bounds__(256)
void convert_xc_kernel(const float* __restrict__ x, const float* __restrict__ c) {
    int idx = blockIdx.x * 256 + threadIdx.x;     // float4 index
    const float* src;
    __half* dst;
    if (idx < MTOT * D / 4) { src = x; dst = h_x; }
    else { idx -= MTOT * D / 4; src = c; dst = h_c; }
    float4 v = ((const float4*)src)[idx];
    uint2 p;
    p.x = pk2h(v.x, v.y);
    p.y = pk2h(v.z, v.w);
    *(uint2*)(dst + idx * 4) = p;
}

// Tiled transpose + fp16 split: Wt[n][k] = W[k][n]; wh = fp16(w), wl = fp16(w-wh).
__global__ __launch_bounds__(256)
void convert_w_kernel(const float* __restrict__ wq, const float* __restrict__ wk,
                      const float* __restrict__ wv, const float* __restrict__ wo) {
    __shared__ float tile[32][33];
    const int w = blockIdx.z;
    const float* W = (w == 0) ? wq : (w == 1) ? wk : (w == 2) ? wv : wo;
    const int kb = blockIdx.x * 32;
    const int nb = blockIdx.y * 32;
    const int tx = threadIdx.x & 31;
    const int ty = threadIdx.x >> 5;
#pragma unroll
    for (int i = ty; i < 32; i += 8)
        tile[i][tx] = W[(kb + i) * D + nb + tx];
    __syncthreads();
    __half* oh = h_wh + w * D * D;
    __half* ol = h_wl + w * D * D;
#pragma unroll
    for (int i = ty; i < 32; i += 8) {
        float v = tile[tx][i];
        __half h = __float2half(v);
        __half l = __float2half(v - __half2float(h));
        oh[(nb + i) * D + kb + tx] = h;
        ol[(nb + i) * D + kb + tx] = l;
    }
}

// ---------------------------------------------------------------------------
// fp16 single-pass HMMA flash attention, fixed-m softmax, exp2 domain.
// CTA: 128 queries x 1024-key sweep (k-tiles of 64). 8 warps, m16 each.
// 2 CTAs/SM -> 256 CTAs in one wave.
// ---------------------------------------------------------------------------
#define SQ 136
#define SK 72
#define OSTRIDE 68
#define KVCOMP  9216
#define KVSTAGE (2 * KVCOMP)
#define OFF_Q   0
#define OFF_KV  17408
#define OFF_EK  (OFF_KV + 2 * KVSTAGE)
#define OFF_EV  (OFF_EK + 2304)
#define OFF_RB  (OFF_EV + 2304)
#define OFF_LS  (OFF_RB + 6144)
#define ATT_SMEM (OFF_LS + 512)          // 65536

__global__ __launch_bounds__(256, 2)
void attn_mma_kernel(const float* __restrict__ ek, const float* __restrict__ ev) {
    extern __shared__ char sm[];
    float* ost = (float*)(sm + OFF_Q);            // finalize staging (reuses Q/KV)
    float* ek_s = (float*)(sm + OFF_EK);
    float* ev_s = (float*)(sm + OFF_EV);
    float* rbw  = (float*)(sm + OFF_RB);
    float* l_s  = (float*)(sm + OFF_LS);

    const int tid = threadIdx.x, wid = tid >> 5, lane = tid & 31;
    const int bh = blockIdx.y, q0 = blockIdx.x * 128;
    const size_t base = (size_t)bh * 65536;
    const float* Qb = g_q + base;
    const float* Kb = g_k + base;

    const uint32_t smq = smem_u32(sm + OFF_Q);

    // Q tile load: [c 0..63][tok 128] fp16.
#pragma unroll
    for (int u = 0; u < 4; ++u) {
        int idx = tid + u * 256;
        int row = idx >> 4, ch = idx & 15;
        cp_async16(smq + (uint32_t)(row * SQ + ch * 8) * 2,
                   a_q_h + base + row * 1024 + q0 + ch * 8);
    }
    cp_commit();

    // K/V stage 0.
    const uint32_t smkv = smem_u32(sm + OFF_KV);
    const int kvcomp = tid >> 7, kvrow = (tid >> 1) & 63, kvhalf = tid & 1;
    const __half* kvsrc = (kvcomp ? a_v_h : a_k_h) + base + kvrow * 1024 + kvhalf * 32;
    const uint32_t kvdst0 = smkv + (uint32_t)kvcomp * KVCOMP +
                            (uint32_t)(kvrow * SK + kvhalf * 32) * 2;
    {
#pragma unroll
        for (int ch = 0; ch < 4; ++ch)
            cp_async16(kvdst0 + ch * 16, kvsrc + ch * 8);
    }
    cp_commit();

    for (int i = tid; i < 576; i += 256) { ek_s[i] = ek[i]; ev_s[i] = ev[i]; }

    // rb[tok][r] = (q_tok . ek[r]) * QSCALE   (exp2 domain, fp32)
    if (tid < 128) {
        float qv[64];
#pragma unroll
        for (int c = 0; c < 64; ++c) qv[c] = Qb[c * 1024 + q0 + tid];
#pragma unroll
        for (int r = 0; r < 9; ++r) {
            float s = 0.f;
#pragma unroll
            for (int c = 0; c < 64; ++c) s += qv[c] * ek_s[r * 64 + c];
            rbw[tid * 12 + r] = s * QSCALE;
        }
    }

    asm volatile("cp.async.wait_group 0;");
    __syncthreads();

    // Persistent Q A-fragments.
    const int wm = wid * 16;
    uint32_t qf[4][4];
    {
        int coff = (lane & 7) + ((lane >> 4) << 3);
        int tok  = wm + (((lane >> 3) & 1) << 3);
#pragma unroll
        for (int ks = 0; ks < 4; ++ks)
            ldm_x4_t(smq + (uint32_t)((ks * 16 + coff) * SQ + tok) * 2, qf[ks]);
    }

    float l0 = 0.f, l1 = 0.f;
    float oacc[8][4] = {};

    for (int kt = 0; kt < 16; ++kt) {
        const int kg = kt * 64;
        const uint32_t sbuf = smkv + (uint32_t)(kt & 1) * KVSTAGE;

        if (kt > 0) asm volatile("cp.async.wait_group 0;");
        __syncthreads();

        if (kt < 15) {
            uint32_t dst = kvdst0 + (uint32_t)((kt & 1) ^ 1) * KVSTAGE;
            const __half* src = kvsrc + kg + 64;
#pragma unroll
            for (int ch = 0; ch < 4; ++ch)
                cp_async16(dst + ch * 16, src + ch * 8);
            cp_commit();
        }

        const uint32_t smk = sbuf, smv = sbuf + KVCOMP;

        // ---- S = Q.K^T (single fp16 pass) ----
        float sacc[8][4] = {};
#pragma unroll
        for (int ks = 0; ks < 4; ++ks) {
            int cK = ks * 16 + (lane & 7) + (((lane >> 3) & 1) << 3);
#pragma unroll
            for (int p = 0; p < 4; ++p) {
                int tokp = p * 16 + ((lane >> 4) << 3);
                uint32_t r[4];
                ldm_x4_t(smk + (uint32_t)(cK * SK + tokp) * 2, r);
                uint32_t b0[2] = {r[0], r[1]}, b1[2] = {r[2], r[3]};
                mma16816h(sacc[2*p],   qf[ks], b0);
                mma16816h(sacc[2*p+1], qf[ks], b1);
            }
        }

        // ---- banded relative-key bias ----
        const int qwbase = q0 + wm;
        if (kg <= qwbase + 19 && kg + 63 >= qwbase - 4) {
            int qg0 = qwbase + (lane >> 2);
#pragma unroll
            for (int nj = 0; nj < 8; ++nj) {
                int kgg = kg + nj * 8 + ((lane & 3) << 1);
#pragma unroll
                for (int i = 0; i < 4; ++i) {
                    int qg = qg0 + ((i >> 1) << 3);
                    int r = kgg + (i & 1) - qg + 4;
                    if ((unsigned)r <= 8u)
                        sacc[nj][i] += rbw[(qg - q0) * 12 + r];
                }
            }
        }

        // ---- fixed-m softmax: e = 2^s; l per-thread; pack fp16 P frags ----
        uint32_t pA[4][4];
#pragma unroll
        for (int p = 0; p < 4; ++p) {
            float e00 = ex2(sacc[2*p][0]),   e01 = ex2(sacc[2*p][1]);
            float e02 = ex2(sacc[2*p][2]),   e03 = ex2(sacc[2*p][3]);
            float e10 = ex2(sacc[2*p+1][0]), e11 = ex2(sacc[2*p+1][1]);
            float e12 = ex2(sacc[2*p+1][2]), e13 = ex2(sacc[2*p+1][3]);
            l0 += e00 + e01 + e10 + e11;
            l1 += e02 + e03 + e12 + e13;
            pA[p][0] = pk2h(e00, e01);
            pA[p][1] = pk2h(e02, e03);
            pA[p][2] = pk2h(e10, e11);
            pA[p][3] = pk2h(e12, e13);
        }

        // ---- O += P.V (single fp16 pass) ----
#pragma unroll
        for (int ks = 0; ks < 4; ++ks) {
            int kV = ks * 16 + (((lane >> 3) & 1) << 3);
#pragma unroll
            for (int p = 0; p < 4; ++p) {
                int nV = p * 16 + (lane & 7) + ((lane >> 4) << 3);
                uint32_t r[4];
                ldm_x4(smv + (uint32_t)(nV * SK + kV) * 2, r);
                uint32_t b0[2] = {r[0], r[1]}, b1[2] = {r[2], r[3]};
                mma16816h(oacc[2*p],   pA[ks], b0);
                mma16816h(oacc[2*p+1], pA[ks], b1);
            }
        }
    }

    // ---- single end-of-loop l reduction across the quad ----
    l0 += __shfl_xor_sync(0xffffffffu, l0, 1);
    l0 += __shfl_xor_sync(0xffffffffu, l0, 2);
    l1 += __shfl_xor_sync(0xffffffffu, l1, 1);
    l1 += __shfl_xor_sync(0xffffffffu, l1, 2);

    if ((lane & 3) == 0) {
        int row = wm + (lane >> 2);
        l_s[row] = l0;
        l_s[row + 8] = l1;
    }
    __syncthreads();

    // Band weights w[tok][r] = 2^((s+s2)*QSCALE) / l  (fp32 recompute, m=0).
    if (tid < 128) {
        float qv[64];
#pragma unroll
        for (int c = 0; c < 64; ++c) qv[c] = Qb[c * 1024 + q0 + tid];
        float invl = 1.f / l_s[tid];
        int qg = q0 + tid;
        float w[9];
#pragma unroll
        for (int r = 0; r < 9; ++r) {
            int kj = qg + r - 4;
            float wv = 0.f;
            if (kj >= 0 && kj < 1024) {
                float s = 0.f;
#pragma unroll
                for (int c = 0; c < 64; ++c) s += qv[c] * Kb[c * 1024 + kj];
                float s2 = 0.f;
#pragma unroll
                for (int c = 0; c < 64; ++c) s2 += qv[c] * ek_s[r * 64 + c];
                wv = ex2((s + s2) * QSCALE) * invl;
            }
            w[r] = wv;
        }
#pragma unroll
        for (int r = 0; r < 9; ++r) rbw[tid * 12 + r] = w[r];
    }
    __syncthreads();

    // O fragments -> staging smem [tok][c] with 1/l and band-ev add.
    {
        float inv0 = 1.f / l0, inv1 = 1.f / l1;
        int row0 = wm + (lane >> 2), row1 = row0 + 8;
        float w0[9], w1[9];
#pragma unroll
        for (int r = 0; r < 9; ++r) { w0[r] = rbw[row0 * 12 + r]; w1[r] = rbw[row1 * 12 + r]; }
#pragma unroll
        for (int nj = 0; nj < 8; ++nj) {
            int cb = nj * 8 + ((lane & 3) << 1);
#pragma unroll
            for (int i = 0; i < 4; ++i) {
                int cc = cb + (i & 1);
                const float* wr = (i < 2) ? w0 : w1;
                float band = 0.f;
#pragma unroll
                for (int r = 0; r < 9; ++r) band += wr[r] * ev_s[r * 64 + cc];
                float val = oacc[nj][i] * ((i < 2) ? inv0 : inv1) + band;
                ost[((i < 2) ? row0 : row1) * OSTRIDE + cc] = val;
            }
        }
    }
    __syncthreads();

    // Remapped fp16 store (faithful reshape flat index).
    const size_t obase = (size_t)(bh >> 3) * 524288 + (size_t)(bh & 7) * 65536;
    for (int idx = tid; idx < 8192; idx += 256) {
        int c = idx >> 7, tl = idx & 127;
        float v = ost[tl * OSTRIDE + c];
        a_o_h[obase + c * 1024 + q0 + tl] = __float2half(v);
    }
}

// ---------------------------------------------------------------------------
extern "C" void kernel_launch(void* const* d_in, const int* in_sizes, int n_in,
                              void* d_out, int out_size) {
    const float* x  = (const float*)d_in[0];
    const float* c  = (const float*)d_in[1];
    const float* wq = (const float*)d_in[2];
    const float* bq = (const float*)d_in[3];
    const float* wk = (const float*)d_in[4];
    const float* bk = (const float*)d_in[5];
    const float* wv = (const float*)d_in[6];
    const float* bv = (const float*)d_in[7];
    const float* wo = (const float*)d_in[8];
    const float* bo = (const float*)d_in[9];
    const float* ek = (const float*)d_in[10];
    const float* ev = (const float*)d_in[11];
    float* out = (float*)d_out;

    cudaFuncSetAttribute(attn_mma_kernel,
                         cudaFuncAttributeMaxDynamicSharedMemorySize, ATT_SMEM);

    convert_w_kernel<<<dim3(16, 16, 4), 256>>>(wq, wk, wv, wo);
    convert_xc_kernel<<<4096, 256>>>(x, c);

    qkv_mma_kernel<<<dim3(4, 32, 3), 256>>>(bq, bk, bv);

    attn_mma_kernel<<<dim3(8, 32), 256, ATT_SMEM>>>(ek, ev);

    out_mma_kernel<<<dim3(4, 32), 256>>>(bo, out);
}

// round 12
// speedup vs baseline: 8.0202x; 1.1124x over previous
#include <cuda_runtime.h>
#include <cuda_bf16.h>
#include <cuda_fp16.h>
#include <cstdint>

#define T      1024
#define D      512
#define KC     64
#define BATCH  4
#define BH     (BATCH * 8)
#define MTOT   (BATCH * T)

// exp2-domain scale: 0.125 * log2(e)
#define QSCALE 0.1803368801111f

// ---------------------------------------------------------------------------
// Device scratch (no allocation allowed)
// ---------------------------------------------------------------------------
__device__ float g_q[MTOT * D];           // fp32 q (attn rb + band recompute)
__device__ float g_k[MTOT * D];           // fp32 k (attn band recompute)

__device__ __half h_x[MTOT * D];          // fp16 activations
__device__ __half h_c[MTOT * D];
__device__ __half h_wh[4 * D * D];        // fp16 weight split, [n][k], q/k/v/o
__device__ __half h_wl[4 * D * D];
__device__ __half a_q_h[MTOT * D];        // attn operands (q pre-scaled)
__device__ __half a_k_h[MTOT * D];
__device__ __half a_v_h[MTOT * D];
__device__ __half a_o_h[MTOT * D];        // attn output (out-GEMM A operand)

__device__ __forceinline__ uint32_t smem_u32(const void* p) {
    uint32_t a;
    asm("{ .reg .u64 t; cvta.to.shared.u64 t, %1; cvt.u32.u64 %0, t; }" : "=r"(a) : "l"(p));
    return a;
}

__device__ __forceinline__ void cp_async16(uint32_t saddr, const void* gaddr) {
    asm volatile("cp.async.cg.shared.global [%0], [%1], 16;" :: "r"(saddr), "l"(gaddr));
}
__device__ __forceinline__ void cp_commit() {
    asm volatile("cp.async.commit_group;");
}

__device__ __forceinline__ void ldm_x4(uint32_t addr, uint32_t r[4]) {
    asm volatile("ldmatrix.sync.aligned.m8n8.x4.shared.b16 {%0,%1,%2,%3}, [%4];"
                 : "=r"(r[0]), "=r"(r[1]), "=r"(r[2]), "=r"(r[3]) : "r"(addr));
}
__device__ __forceinline__ void ldm_x4_t(uint32_t addr, uint32_t r[4]) {
    asm volatile("ldmatrix.sync.aligned.m8n8.x4.trans.shared.b16 {%0,%1,%2,%3}, [%4];"
                 : "=r"(r[0]), "=r"(r[1]), "=r"(r[2]), "=r"(r[3]) : "r"(addr));
}

__device__ __forceinline__ void mma16816h(float c[4], const uint32_t a[4],
                                          const uint32_t b[2]) {
    asm volatile(
        "mma.sync.aligned.m16n8k16.row.col.f32.f16.f16.f32 "
        "{%0,%1,%2,%3}, {%4,%5,%6,%7}, {%8,%9}, {%0,%1,%2,%3};"
        : "+f"(c[0]), "+f"(c[1]), "+f"(c[2]), "+f"(c[3])
        : "r"(a[0]), "r"(a[1]), "r"(a[2]), "r"(a[3]), "r"(b[0]), "r"(b[1]));
}

__device__ __forceinline__ uint32_t pk2h(float a, float b) {
    __half2 t = __floats2half2_rn(a, b);
    return *(uint32_t*)&t;
}
__device__ __forceinline__ float ex2(float x) {
    float y;
    asm("ex2.approx.ftz.f32 %0, %1;" : "=f"(y) : "f"(x));
    return y;
}

// ---------------------------------------------------------------------------
// fp16 HMMA GEMM, NPASS passes (A single fp16; W = Wh [+ Wl]): C = A @ W^T + b.
// CTA tile 128x128, 8 warps of 32x64, BK=32, cp.async double buffer.
// ---------------------------------------------------------------------------
#define BK        32
#define ASTRIDE   40
#define STAGE_ELEMS (128 * ASTRIDE)

template <int NPASS>
__device__ __forceinline__ void mma_gemm_body_h(
    const __half* __restrict__ A,
    const __half* __restrict__ Wh, const __half* __restrict__ Wl,
    const float* __restrict__ bias,
    float* __restrict__ Cf, __half* __restrict__ Ch, float hscale) {
    __shared__ __half sA[2][STAGE_ELEMS];
    __shared__ __half sB[2][STAGE_ELEMS];

    constexpr int NITER = NPASS * 16;

    const int tid  = threadIdx.x;
    const int wid  = tid >> 5;
    const int lane = tid & 31;
    const int n0   = blockIdx.x * 128;
    const int m0   = blockIdx.y * 128;

    const __half* BPS[2] = {Wh, Wl};

    const int lrow   = tid >> 1;
    const int lcbase = (tid & 1) * 2;

    auto issue_load = [&](int it, int stage) {
        const __half* B = BPS[it >> 4];
        const int k0 = (it & 15) * BK;
        const uint32_t sa0 = smem_u32(sA[stage]);
        const uint32_t sb0 = smem_u32(sB[stage]);
#pragma unroll
        for (int cc = 0; cc < 2; ++cc) {
            const int ch = lcbase + cc;
            const uint32_t soff = (uint32_t)(lrow * ASTRIDE + ch * 8) * 2;
            cp_async16(sa0 + soff, A + (m0 + lrow) * D + k0 + ch * 8);
            cp_async16(sb0 + soff, B + (n0 + lrow) * D + k0 + ch * 8);
        }
        cp_commit();
    };

    const int wm = (wid & 3) * 32;
    const int wn = (wid >> 2) * 64;

    float acc[2][8][4];
#pragma unroll
    for (int mi = 0; mi < 2; ++mi)
#pragma unroll
        for (int nj = 0; nj < 8; ++nj)
#pragma unroll
            for (int r = 0; r < 4; ++r) acc[mi][nj][r] = 0.f;

    issue_load(0, 0);

    for (int it = 0; it < NITER; ++it) {
        const int stage = it & 1;
        if (it + 1 < NITER) {
            issue_load(it + 1, stage ^ 1);
            asm volatile("cp.async.wait_group 1;");
        } else {
            asm volatile("cp.async.wait_group 0;");
        }
        __syncthreads();

        const uint32_t sAb = smem_u32(sA[stage]);
        const uint32_t sBb = smem_u32(sB[stage]);
#pragma unroll
        for (int ks = 0; ks < BK; ks += 16) {
            uint32_t afrag[2][4];
#pragma unroll
            for (int mi = 0; mi < 2; ++mi) {
                uint32_t addr = sAb +
                    (uint32_t)(((wm + mi * 16 + (lane & 15)) * ASTRIDE) +
                               ks + ((lane >> 4) << 3)) * 2;
                ldm_x4(addr, afrag[mi]);
            }
            uint32_t bfrag[8][2];
#pragma unroll
            for (int nq = 0; nq < 4; ++nq) {
                uint32_t r[4];
                uint32_t addr = sBb +
                    (uint32_t)(((wn + nq * 16 + (lane & 7) + ((lane >> 4) << 3)) * ASTRIDE) +
                               ks + (((lane >> 3) & 1) << 3)) * 2;
                ldm_x4(addr, r);
                bfrag[2 * nq][0]     = r[0];
                bfrag[2 * nq][1]     = r[1];
                bfrag[2 * nq + 1][0] = r[2];
                bfrag[2 * nq + 1][1] = r[3];
            }
#pragma unroll
            for (int mi = 0; mi < 2; ++mi)
#pragma unroll
                for (int nj = 0; nj < 8; ++nj)
                    mma16816h(acc[mi][nj], afrag[mi], bfrag[nj]);
        }
        __syncthreads();
    }

    const int rbase = m0 + wm + (lane >> 2);
    const int cbase = n0 + wn + (lane & 3) * 2;
#pragma unroll
    for (int mi = 0; mi < 2; ++mi) {
#pragma unroll
        for (int nj = 0; nj < 8; ++nj) {
            const int col = cbase + nj * 8;
            const float2 bb = *(const float2*)(bias + col);
            float2 v0, v1;
            v0.x = acc[mi][nj][0] + bb.x;
            v0.y = acc[mi][nj][1] + bb.y;
            v1.x = acc[mi][nj][2] + bb.x;
            v1.y = acc[mi][nj][3] + bb.y;
            const int r0 = (rbase + mi * 16) * D + col;
            const int r1 = (rbase + mi * 16 + 8) * D + col;
            if (Cf) {
                *(float2*)(Cf + r0) = v0;
                *(float2*)(Cf + r1) = v1;
            }
            if (Ch) {
                *(uint32_t*)(Ch + r0) = pk2h(v0.x * hscale, v0.y * hscale);
                *(uint32_t*)(Ch + r1) = pk2h(v1.x * hscale, v1.y * hscale);
            }
        }
    }
}

// q/k/v projections: single-pass fp16 (weight-rounding adds ~2.8e-4, budgeted).
__global__ __launch_bounds__(256)
void qkv_mma_kernel(const float* __restrict__ bq, const float* __restrict__ bk,
                    const float* __restrict__ bv) {
    if (blockIdx.z == 0)
        mma_gemm_body_h<1>(h_x, h_wh, h_wh, bq, g_q, a_q_h, QSCALE);
    else if (blockIdx.z == 1)
        mma_gemm_body_h<1>(h_c, h_wh + D * D, h_wh + D * D, bk, g_k, a_k_h, 1.f);
    else
        mma_gemm_body_h<1>(h_c, h_wh + 2 * D * D, h_wh + 2 * D * D, bv,
                           nullptr, a_v_h, 1.f);
}

// out projection: keep 2-pass (error hits output unsmoothed).
__global__ __launch_bounds__(256)
void out_mma_kernel(const float* __restrict__ bo, float* __restrict__ out) {
    mma_gemm_body_h<2>(a_o_h, h_wh + 3 * D * D, h_wl + 3 * D * D, bo,
                       out, nullptr, 1.f);
}

// ---------------------------------------------------------------------------
// Convert kernels
// ---------------------------------------------------------------------------
__global__ __launch_bounds__(256)
void convert_xc_kernel(const float* __restrict__ x, const float* __restrict__ c) {
    int idx = blockIdx.x * 256 + threadIdx.x;     // float4 index
    const float* src;
    __half* dst;
    if (idx < MTOT * D / 4) { src = x; dst = h_x; }
    else { idx -= MTOT * D / 4; src = c; dst = h_c; }
    float4 v = ((const float4*)src)[idx];
    uint2 p;
    p.x = pk2h(v.x, v.y);
    p.y = pk2h(v.z, v.w);
    *(uint2*)(dst + idx * 4) = p;
}

__global__ __launch_bounds__(256)
void convert_w_kernel(const float* __restrict__ wq, const float* __restrict__ wk,
                      const float* __restrict__ wv, const float* __restrict__ wo) {
    __shared__ float tile[32][33];
    const int w = blockIdx.z;
    const float* W = (w == 0) ? wq : (w == 1) ? wk : (w == 2) ? wv : wo;
    const int kb = blockIdx.x * 32;
    const int nb = blockIdx.y * 32;
    const int tx = threadIdx.x & 31;
    const int ty = threadIdx.x >> 5;
#pragma unroll
    for (int i = ty; i < 32; i += 8)
        tile[i][tx] = W[(kb + i) * D + nb + tx];
    __syncthreads();
    __half* oh = h_wh + w * D * D;
    __half* ol = h_wl + w * D * D;
#pragma unroll
    for (int i = ty; i < 32; i += 8) {
        float v = tile[tx][i];
        __half h = __float2half(v);
        __half l = __float2half(v - __half2float(h));
        oh[(nb + i) * D + kb + tx] = h;
        ol[(nb + i) * D + kb + tx] = l;
    }
}

// ---------------------------------------------------------------------------
// fp16 single-pass HMMA flash attention, fixed-m softmax, exp2 domain.
// CTA: 128 queries. Keys loaded in 128-token tiles (one sync per 128),
// computed in two 64-token halves (register footprint unchanged). 8 tiles.
// 2 CTAs/SM -> 256 CTAs in one wave.
// ---------------------------------------------------------------------------
#define SQ 136
#define SK2 136                          // row stride for 128-token KV tiles
#define OSTRIDE 68
#define KVCOMP  (64 * SK2 * 2)           // 17408 B per component (K or V)
#define KVSTAGE (2 * KVCOMP)             // 34816
#define OFF_Q   0
#define OFF_KV  17408
#define OFF_EK  (OFF_KV + 2 * KVSTAGE)   // 87040
#define OFF_EV  (OFF_EK + 2304)
#define OFF_RB  (OFF_EV + 2304)
#define OFF_LS  (OFF_RB + 6144)
#define ATT_SMEM (OFF_LS + 512)          // 98304

__global__ __launch_bounds__(256, 2)
void attn_mma_kernel(const float* __restrict__ ek, const float* __restrict__ ev) {
    extern __shared__ char sm[];
    float* ost = (float*)(sm + OFF_Q);            // finalize staging (reuses Q/KV)
    float* ek_s = (float*)(sm + OFF_EK);
    float* ev_s = (float*)(sm + OFF_EV);
    float* rbw  = (float*)(sm + OFF_RB);
    float* l_s  = (float*)(sm + OFF_LS);

    const int tid = threadIdx.x, wid = tid >> 5, lane = tid & 31;
    const int bh = blockIdx.y, q0 = blockIdx.x * 128;
    const size_t base = (size_t)bh * 65536;
    const float* Qb = g_q + base;
    const float* Kb = g_k + base;

    const uint32_t smq = smem_u32(sm + OFF_Q);

    // Q tile load: [c 0..63][tok 128] fp16.
#pragma unroll
    for (int u = 0; u < 4; ++u) {
        int idx = tid + u * 256;
        int row = idx >> 4, ch = idx & 15;
        cp_async16(smq + (uint32_t)(row * SQ + ch * 8) * 2,
                   a_q_h + base + row * 1024 + q0 + ch * 8);
    }
    cp_commit();

    // K/V 128-token stage 0. Each thread: one row-half (64 halves = 8 chunks).
    const uint32_t smkv = smem_u32(sm + OFF_KV);
    const int kvcomp = tid >> 7, kvrow = (tid >> 1) & 63, kvhalf = tid & 1;
    const __half* kvsrc = (kvcomp ? a_v_h : a_k_h) + base + kvrow * 1024 + kvhalf * 64;
    const uint32_t kvdst0 = smkv + (uint32_t)kvcomp * KVCOMP +
                            (uint32_t)(kvrow * SK2 + kvhalf * 64) * 2;
    {
#pragma unroll
        for (int ch = 0; ch < 8; ++ch)
            cp_async16(kvdst0 + ch * 16, kvsrc + ch * 8);
    }
    cp_commit();

    for (int i = tid; i < 576; i += 256) { ek_s[i] = ek[i]; ev_s[i] = ev[i]; }

    // rb[tok][r] = (q_tok . ek[r]) * QSCALE   (exp2 domain, fp32)
    if (tid < 128) {
        float qv[64];
#pragma unroll
        for (int c = 0; c < 64; ++c) qv[c] = Qb[c * 1024 + q0 + tid];
#pragma unroll
        for (int r = 0; r < 9; ++r) {
            float s = 0.f;
#pragma unroll
            for (int c = 0; c < 64; ++c) s += qv[c] * ek_s[r * 64 + c];
            rbw[tid * 12 + r] = s * QSCALE;
        }
    }

    asm volatile("cp.async.wait_group 0;");
    __syncthreads();

    // Persistent Q A-fragments.
    const int wm = wid * 16;
    uint32_t qf[4][4];
    {
        int coff = (lane & 7) + ((lane >> 4) << 3);
        int tok  = wm + (((lane >> 3) & 1) << 3);
#pragma unroll
        for (int ks = 0; ks < 4; ++ks)
            ldm_x4_t(smq + (uint32_t)((ks * 16 + coff) * SQ + tok) * 2, qf[ks]);
    }

    float l0 = 0.f, l1 = 0.f;
    float oacc[8][4] = {};

    for (int kt = 0; kt < 8; ++kt) {
        const uint32_t sbuf = smkv + (uint32_t)(kt & 1) * KVSTAGE;

        if (kt > 0) asm volatile("cp.async.wait_group 0;");
        __syncthreads();

        if (kt < 7) {  // prefetch next 128-token tile into other buffer
            uint32_t dst = kvdst0 + (uint32_t)((kt & 1) ^ 1) * KVSTAGE;
            const __half* src = kvsrc + (kt + 1) * 128;
#pragma unroll
            for (int ch = 0; ch < 8; ++ch)
                cp_async16(dst + ch * 16, src + ch * 8);
            cp_commit();
        }

        const uint32_t smk = sbuf, smv = sbuf + KVCOMP;

#pragma unroll
        for (int h = 0; h < 2; ++h) {
            const int kg = kt * 128 + h * 64;
            const int hoff = h * 64;

            // ---- S = Q.K^T (single fp16 pass) ----
            float sacc[8][4] = {};
#pragma unroll
            for (int ks = 0; ks < 4; ++ks) {
                int cK = ks * 16 + (lane & 7) + (((lane >> 3) & 1) << 3);
#pragma unroll
                for (int p = 0; p < 4; ++p) {
                    int tokp = hoff + p * 16 + ((lane >> 4) << 3);
                    uint32_t r[4];
                    ldm_x4_t(smk + (uint32_t)(cK * SK2 + tokp) * 2, r);
                    uint32_t b0[2] = {r[0], r[1]}, b1[2] = {r[2], r[3]};
                    mma16816h(sacc[2*p],   qf[ks], b0);
                    mma16816h(sacc[2*p+1], qf[ks], b1);
                }
            }

            // ---- banded relative-key bias ----
            const int qwbase = q0 + wm;
            if (kg <= qwbase + 19 && kg + 63 >= qwbase - 4) {
                int qg0 = qwbase + (lane >> 2);
#pragma unroll
                for (int nj = 0; nj < 8; ++nj) {
                    int kgg = kg + nj * 8 + ((lane & 3) << 1);
#pragma unroll
                    for (int i = 0; i < 4; ++i) {
                        int qg = qg0 + ((i >> 1) << 3);
                        int r = kgg + (i & 1) - qg + 4;
                        if ((unsigned)r <= 8u)
                            sacc[nj][i] += rbw[(qg - q0) * 12 + r];
                    }
                }
            }

            // ---- fixed-m softmax: e = 2^s; l per-thread; fp16 P frags ----
            uint32_t pA[4][4];
#pragma unroll
            for (int p = 0; p < 4; ++p) {
                float e00 = ex2(sacc[2*p][0]),   e01 = ex2(sacc[2*p][1]);
                float e02 = ex2(sacc[2*p][2]),   e03 = ex2(sacc[2*p][3]);
                float e10 = ex2(sacc[2*p+1][0]), e11 = ex2(sacc[2*p+1][1]);
                float e12 = ex2(sacc[2*p+1][2]), e13 = ex2(sacc[2*p+1][3]);
                l0 += e00 + e01 + e10 + e11;
                l1 += e02 + e03 + e12 + e13;
                pA[p][0] = pk2h(e00, e01);
                pA[p][1] = pk2h(e02, e03);
                pA[p][2] = pk2h(e10, e11);
                pA[p][3] = pk2h(e12, e13);
            }

            // ---- O += P.V (single fp16 pass) ----
#pragma unroll
            for (int ks = 0; ks < 4; ++ks) {
                int kV = hoff + ks * 16 + (((lane >> 3) & 1) << 3);
#pragma unroll
                for (int p = 0; p < 4; ++p) {
                    int nV = p * 16 + (lane & 7) + ((lane >> 4) << 3);
                    uint32_t r[4];
                    ldm_x4(smv + (uint32_t)(nV * SK2 + kV) * 2, r);
                    uint32_t b0[2] = {r[0], r[1]}, b1[2] = {r[2], r[3]};
                    mma16816h(oacc[2*p],   pA[ks], b0);
                    mma16816h(oacc[2*p+1], pA[ks], b1);
                }
            }
        }
    }

    // ---- single end-of-loop l reduction across the quad ----
    l0 += __shfl_xor_sync(0xffffffffu, l0, 1);
    l0 += __shfl_xor_sync(0xffffffffu, l0, 2);
    l1 += __shfl_xor_sync(0xffffffffu, l1, 1);
    l1 += __shfl_xor_sync(0xffffffffu, l1, 2);

    if ((lane & 3) == 0) {
        int row = wm + (lane >> 2);
        l_s[row] = l0;
        l_s[row + 8] = l1;
    }
    __syncthreads();

    // Band weights w[tok][r] = 2^((s+s2)*QSCALE) / l  (fp32 recompute, m=0).
    if (tid < 128) {
        float qv[64];
#pragma unroll
        for (int c = 0; c < 64; ++c) qv[c] = Qb[c * 1024 + q0 + tid];
        float invl = 1.f / l_s[tid];
        int qg = q0 + tid;
        float w[9];
#pragma unroll
        for (int r = 0; r < 9; ++r) {
            int kj = qg + r - 4;
            float wv = 0.f;
            if (kj >= 0 && kj < 1024) {
                float s = 0.f;
#pragma unroll
                for (int c = 0; c < 64; ++c) s += qv[c] * Kb[c * 1024 + kj];
                float s2 = 0.f;
#pragma unroll
                for (int c = 0; c < 64; ++c) s2 += qv[c] * ek_s[r * 64 + c];
                wv = ex2((s + s2) * QSCALE) * invl;
            }
            w[r] = wv;
        }
#pragma unroll
        for (int r = 0; r < 9; ++r) rbw[tid * 12 + r] = w[r];
    }
    __syncthreads();

    // O fragments -> staging smem [tok][c] with 1/l and band-ev add.
    {
        float inv0 = 1.f / l0, inv1 = 1.f / l1;
        int row0 = wm + (lane >> 2), row1 = row0 + 8;
        float w0[9], w1[9];
#pragma unroll
        for (int r = 0; r < 9; ++r) { w0[r] = rbw[row0 * 12 + r]; w1[r] = rbw[row1 * 12 + r]; }
#pragma unroll
        for (int nj = 0; nj < 8; ++nj) {
            int cb = nj * 8 + ((lane & 3) << 1);
#pragma unroll
            for (int i = 0; i < 4; ++i) {
                int cc = cb + (i & 1);
                const float* wr = (i < 2) ? w0 : w1;
                float band = 0.f;
#pragma unroll
                for (int r = 0; r < 9; ++r) band += wr[r] * ev_s[r * 64 + cc];
                float val = oacc[nj][i] * ((i < 2) ? inv0 : inv1) + band;
                ost[((i < 2) ? row0 : row1) * OSTRIDE + cc] = val;
            }
        }
    }
    __syncthreads();

    // Remapped fp16 store (faithful reshape flat index).
    const size_t obase = (size_t)(bh >> 3) * 524288 + (size_t)(bh & 7) * 65536;
    for (int idx = tid; idx < 8192; idx += 256) {
        int c = idx >> 7, tl = idx & 127;
        float v = ost[tl * OSTRIDE + c];
        a_o_h[obase + c * 1024 + q0 + tl] = __float2half(v);
    }
}

// ---------------------------------------------------------------------------
extern "C" void kernel_launch(void* const* d_in, const int* in_sizes, int n_in,
                              void* d_out, int out_size) {
    const float* x  = (const float*)d_in[0];
    const float* c  = (const float*)d_in[1];
    const float* wq = (const float*)d_in[2];
    const float* bq = (const float*)d_in[3];
    const float* wk = (const float*)d_in[4];
    const float* bk = (const float*)d_in[5];
    const float* wv = (const float*)d_in[6];
    const float* bv = (const float*)d_in[7];
    const float* wo = (const float*)d_in[8];
    const float* bo = (const float*)d_in[9];
    const float* ek = (const float*)d_in[10];
    const float* ev = (const float*)d_in[11];
    float* out = (float*)d_out;

    cudaFuncSetAttribute(attn_mma_kernel,
                         cudaFuncAttributeMaxDynamicSharedMemorySize, ATT_SMEM);

    convert_w_kernel<<<dim3(16, 16, 4), 256>>>(wq, wk, wv, wo);
    convert_xc_kernel<<<4096, 256>>>(x, c);

    qkv_mma_kernel<<<dim3(4, 32, 3), 256>>>(bq, bk, bv);

    attn_mma_kernel<<<dim3(8, 32), 256, ATT_SMEM>>>(ek, ev);

    out_mma_kernel<<<dim3(4, 32), 256>>>(bo, out);
}

// round 13
// speedup vs baseline: 8.9347x; 1.1140x over previous
#include <cuda_runtime.h>
#include <cuda_bf16.h>
#include <cuda_fp16.h>
#include <cstdint>

#define T      1024
#define D      512
#define KC     64
#define BATCH  4
#define BH     (BATCH * 8)
#define MTOT   (BATCH * T)

// exp2-domain scale: 0.125 * log2(e)
#define QSCALE 0.1803368801111f

// ---------------------------------------------------------------------------
// Device scratch (no allocation allowed)
// ---------------------------------------------------------------------------
__device__ float g_q[MTOT * D];           // fp32 q (attn rb + band recompute)
__device__ float g_k[MTOT * D];           // fp32 k (attn band recompute)

__device__ __half h_x[MTOT * D];          // fp16 activations
__device__ __half h_c[MTOT * D];
__device__ __half h_wh[4 * D * D];        // fp16 weight split, [n][k], q/k/v/o
__device__ __half h_wl[4 * D * D];
__device__ __half a_q_h[MTOT * D];        // attn operands (q pre-scaled)
__device__ __half a_k_h[MTOT * D];
__device__ __half a_v_h[MTOT * D];
__device__ __half a_o_h[MTOT * D];        // attn output (out-GEMM A operand)

__device__ __forceinline__ uint32_t smem_u32(const void* p) {
    uint32_t a;
    asm("{ .reg .u64 t; cvta.to.shared.u64 t, %1; cvt.u32.u64 %0, t; }" : "=r"(a) : "l"(p));
    return a;
}

__device__ __forceinline__ void cp_async16(uint32_t saddr, const void* gaddr) {
    asm volatile("cp.async.cg.shared.global [%0], [%1], 16;" :: "r"(saddr), "l"(gaddr));
}
__device__ __forceinline__ void cp_commit() {
    asm volatile("cp.async.commit_group;");
}

__device__ __forceinline__ void ldm_x4(uint32_t addr, uint32_t r[4]) {
    asm volatile("ldmatrix.sync.aligned.m8n8.x4.shared.b16 {%0,%1,%2,%3}, [%4];"
                 : "=r"(r[0]), "=r"(r[1]), "=r"(r[2]), "=r"(r[3]) : "r"(addr));
}
__device__ __forceinline__ void ldm_x4_t(uint32_t addr, uint32_t r[4]) {
    asm volatile("ldmatrix.sync.aligned.m8n8.x4.trans.shared.b16 {%0,%1,%2,%3}, [%4];"
                 : "=r"(r[0]), "=r"(r[1]), "=r"(r[2]), "=r"(r[3]) : "r"(addr));
}

__device__ __forceinline__ void mma16816h(float c[4], const uint32_t a[4],
                                          const uint32_t b[2]) {
    asm volatile(
        "mma.sync.aligned.m16n8k16.row.col.f32.f16.f16.f32 "
        "{%0,%1,%2,%3}, {%4,%5,%6,%7}, {%8,%9}, {%0,%1,%2,%3};"
        : "+f"(c[0]), "+f"(c[1]), "+f"(c[2]), "+f"(c[3])
        : "r"(a[0]), "r"(a[1]), "r"(a[2]), "r"(a[3]), "r"(b[0]), "r"(b[1]));
}

__device__ __forceinline__ uint32_t pk2h(float a, float b) {
    __half2 t = __floats2half2_rn(a, b);
    return *(uint32_t*)&t;
}
__device__ __forceinline__ float ex2(float x) {
    float y;
    asm("ex2.approx.ftz.f32 %0, %1;" : "=f"(y) : "f"(x));
    return y;
}

// ---------------------------------------------------------------------------
// fp16 HMMA GEMM, NPASS passes (A single fp16; W = Wh [+ Wl]): C = A @ W^T + b.
// CTA tile 128x128, 8 warps of 32x64, BK=32, cp.async double buffer.
// ---------------------------------------------------------------------------
#define BK        32
#define ASTRIDE   40
#define STAGE_ELEMS (128 * ASTRIDE)

template <int NPASS>
__device__ __forceinline__ void mma_gemm_body_h(
    const __half* __restrict__ A,
    const __half* __restrict__ Wh, const __half* __restrict__ Wl,
    const float* __restrict__ bias,
    float* __restrict__ Cf, __half* __restrict__ Ch, float hscale) {
    __shared__ __half sA[2][STAGE_ELEMS];
    __shared__ __half sB[2][STAGE_ELEMS];

    constexpr int NITER = NPASS * 16;

    const int tid  = threadIdx.x;
    const int wid  = tid >> 5;
    const int lane = tid & 31;
    const int n0   = blockIdx.x * 128;
    const int m0   = blockIdx.y * 128;

    const __half* BPS[2] = {Wh, Wl};

    const int lrow   = tid >> 1;
    const int lcbase = (tid & 1) * 2;

    auto issue_load = [&](int it, int stage) {
        const __half* B = BPS[it >> 4];
        const int k0 = (it & 15) * BK;
        const uint32_t sa0 = smem_u32(sA[stage]);
        const uint32_t sb0 = smem_u32(sB[stage]);
#pragma unroll
        for (int cc = 0; cc < 2; ++cc) {
            const int ch = lcbase + cc;
            const uint32_t soff = (uint32_t)(lrow * ASTRIDE + ch * 8) * 2;
            cp_async16(sa0 + soff, A + (m0 + lrow) * D + k0 + ch * 8);
            cp_async16(sb0 + soff, B + (n0 + lrow) * D + k0 + ch * 8);
        }
        cp_commit();
    };

    const int wm = (wid & 3) * 32;
    const int wn = (wid >> 2) * 64;

    float acc[2][8][4];
#pragma unroll
    for (int mi = 0; mi < 2; ++mi)
#pragma unroll
        for (int nj = 0; nj < 8; ++nj)
#pragma unroll
            for (int r = 0; r < 4; ++r) acc[mi][nj][r] = 0.f;

    issue_load(0, 0);

    for (int it = 0; it < NITER; ++it) {
        const int stage = it & 1;
        if (it + 1 < NITER) {
            issue_load(it + 1, stage ^ 1);
            asm volatile("cp.async.wait_group 1;");
        } else {
            asm volatile("cp.async.wait_group 0;");
        }
        __syncthreads();

        const uint32_t sAb = smem_u32(sA[stage]);
        const uint32_t sBb = smem_u32(sB[stage]);
#pragma unroll
        for (int ks = 0; ks < BK; ks += 16) {
            uint32_t afrag[2][4];
#pragma unroll
            for (int mi = 0; mi < 2; ++mi) {
                uint32_t addr = sAb +
                    (uint32_t)(((wm + mi * 16 + (lane & 15)) * ASTRIDE) +
                               ks + ((lane >> 4) << 3)) * 2;
                ldm_x4(addr, afrag[mi]);
            }
            uint32_t bfrag[8][2];
#pragma unroll
            for (int nq = 0; nq < 4; ++nq) {
                uint32_t r[4];
                uint32_t addr = sBb +
                    (uint32_t)(((wn + nq * 16 + (lane & 7) + ((lane >> 4) << 3)) * ASTRIDE) +
                               ks + (((lane >> 3) & 1) << 3)) * 2;
                ldm_x4(addr, r);
                bfrag[2 * nq][0]     = r[0];
                bfrag[2 * nq][1]     = r[1];
                bfrag[2 * nq + 1][0] = r[2];
                bfrag[2 * nq + 1][1] = r[3];
            }
#pragma unroll
            for (int mi = 0; mi < 2; ++mi)
#pragma unroll
                for (int nj = 0; nj < 8; ++nj)
                    mma16816h(acc[mi][nj], afrag[mi], bfrag[nj]);
        }
        __syncthreads();
    }

    const int rbase = m0 + wm + (lane >> 2);
    const int cbase = n0 + wn + (lane & 3) * 2;
#pragma unroll
    for (int mi = 0; mi < 2; ++mi) {
#pragma unroll
        for (int nj = 0; nj < 8; ++nj) {
            const int col = cbase + nj * 8;
            const float2 bb = *(const float2*)(bias + col);
            float2 v0, v1;
            v0.x = acc[mi][nj][0] + bb.x;
            v0.y = acc[mi][nj][1] + bb.y;
            v1.x = acc[mi][nj][2] + bb.x;
            v1.y = acc[mi][nj][3] + bb.y;
            const int r0 = (rbase + mi * 16) * D + col;
            const int r1 = (rbase + mi * 16 + 8) * D + col;
            if (Cf) {
                *(float2*)(Cf + r0) = v0;
                *(float2*)(Cf + r1) = v1;
            }
            if (Ch) {
                *(uint32_t*)(Ch + r0) = pk2h(v0.x * hscale, v0.y * hscale);
                *(uint32_t*)(Ch + r1) = pk2h(v1.x * hscale, v1.y * hscale);
            }
        }
    }
}

// q/k/v projections: single-pass fp16 (weight-rounding budgeted; R11 validated).
__global__ __launch_bounds__(256)
void qkv_mma_kernel(const float* __restrict__ bq, const float* __restrict__ bk,
                    const float* __restrict__ bv) {
    if (blockIdx.z == 0)
        mma_gemm_body_h<1>(h_x, h_wh, h_wh, bq, g_q, a_q_h, QSCALE);
    else if (blockIdx.z == 1)
        mma_gemm_body_h<1>(h_c, h_wh + D * D, h_wh + D * D, bk, g_k, a_k_h, 1.f);
    else
        mma_gemm_body_h<1>(h_c, h_wh + 2 * D * D, h_wh + 2 * D * D, bv,
                           nullptr, a_v_h, 1.f);
}

// out projection: keep 2-pass (error hits output unsmoothed).
__global__ __launch_bounds__(256)
void out_mma_kernel(const float* __restrict__ bo, float* __restrict__ out) {
    mma_gemm_body_h<2>(a_o_h, h_wh + 3 * D * D, h_wl + 3 * D * D, bo,
                       out, nullptr, 1.f);
}

// ---------------------------------------------------------------------------
// Convert kernels
// ---------------------------------------------------------------------------
__global__ __launch_bounds__(256)
void convert_xc_kernel(const float* __restrict__ x, const float* __restrict__ c) {
    int idx = blockIdx.x * 256 + threadIdx.x;     // float4 index
    const float* src;
    __half* dst;
    if (idx < MTOT * D / 4) { src = x; dst = h_x; }
    else { idx -= MTOT * D / 4; src = c; dst = h_c; }
    float4 v = ((const float4*)src)[idx];
    uint2 p;
    p.x = pk2h(v.x, v.y);
    p.y = pk2h(v.z, v.w);
    *(uint2*)(dst + idx * 4) = p;
}

__global__ __launch_bounds__(256)
void convert_w_kernel(const float* __restrict__ wq, const float* __restrict__ wk,
                      const float* __restrict__ wv, const float* __restrict__ wo) {
    __shared__ float tile[32][33];
    const int w = blockIdx.z;
    const float* W = (w == 0) ? wq : (w == 1) ? wk : (w == 2) ? wv : wo;
    const int kb = blockIdx.x * 32;
    const int nb = blockIdx.y * 32;
    const int tx = threadIdx.x & 31;
    const int ty = threadIdx.x >> 5;
#pragma unroll
    for (int i = ty; i < 32; i += 8)
        tile[i][tx] = W[(kb + i) * D + nb + tx];
    __syncthreads();
    __half* oh = h_wh + w * D * D;
    __half* ol = h_wl + w * D * D;
#pragma unroll
    for (int i = ty; i < 32; i += 8) {
        float v = tile[tx][i];
        __half h = __float2half(v);
        __half l = __float2half(v - __half2float(h));
        oh[(nb + i) * D + kb + tx] = h;
        ol[(nb + i) * D + kb + tx] = l;
    }
}

// ---------------------------------------------------------------------------
// fp16 single-pass HMMA flash attention, fixed-m softmax, exp2 domain.
// R10-validated shape: 64-token k-tiles, 16 iterations, 65 KB smem.
// CTA: 128 queries x 1024-key sweep. 8 warps, m16 each. 2 CTAs/SM.
// ---------------------------------------------------------------------------
#define SQ 136
#define SK 72
#define OSTRIDE 68
#define KVCOMP  9216
#define KVSTAGE (2 * KVCOMP)
#define OFF_Q   0
#define OFF_KV  17408
#define OFF_EK  (OFF_KV + 2 * KVSTAGE)
#define OFF_EV  (OFF_EK + 2304)
#define OFF_RB  (OFF_EV + 2304)
#define OFF_LS  (OFF_RB + 6144)
#define ATT_SMEM (OFF_LS + 512)          // 65536

__global__ __launch_bounds__(256, 2)
void attn_mma_kernel(const float* __restrict__ ek, const float* __restrict__ ev) {
    extern __shared__ char sm[];
    float* ost = (float*)(sm + OFF_Q);            // finalize staging (reuses Q/KV)
    float* ek_s = (float*)(sm + OFF_EK);
    float* ev_s = (float*)(sm + OFF_EV);
    float* rbw  = (float*)(sm + OFF_RB);
    float* l_s  = (float*)(sm + OFF_LS);

    const int tid = threadIdx.x, wid = tid >> 5, lane = tid & 31;
    const int bh = blockIdx.y, q0 = blockIdx.x * 128;
    const size_t base = (size_t)bh * 65536;
    const float* Qb = g_q + base;
    const float* Kb = g_k + base;

    const uint32_t smq = smem_u32(sm + OFF_Q);

    // Q tile load: [c 0..63][tok 128] fp16.
#pragma unroll
    for (int u = 0; u < 4; ++u) {
        int idx = tid + u * 256;
        int row = idx >> 4, ch = idx & 15;
        cp_async16(smq + (uint32_t)(row * SQ + ch * 8) * 2,
                   a_q_h + base + row * 1024 + q0 + ch * 8);
    }
    cp_commit();

    // K/V stage 0.
    const uint32_t smkv = smem_u32(sm + OFF_KV);
    const int kvcomp = tid >> 7, kvrow = (tid >> 1) & 63, kvhalf = tid & 1;
    const __half* kvsrc = (kvcomp ? a_v_h : a_k_h) + base + kvrow * 1024 + kvhalf * 32;
    const uint32_t kvdst0 = smkv + (uint32_t)kvcomp * KVCOMP +
                            (uint32_t)(kvrow * SK + kvhalf * 32) * 2;
    {
#pragma unroll
        for (int ch = 0; ch < 4; ++ch)
            cp_async16(kvdst0 + ch * 16, kvsrc + ch * 8);
    }
    cp_commit();

    for (int i = tid; i < 576; i += 256) { ek_s[i] = ek[i]; ev_s[i] = ev[i]; }

    // rb[tok][r] = (q_tok . ek[r]) * QSCALE   (exp2 domain, fp32)
    if (tid < 128) {
        float qv[64];
#pragma unroll
        for (int c = 0; c < 64; ++c) qv[c] = Qb[c * 1024 + q0 + tid];
#pragma unroll
        for (int r = 0; r < 9; ++r) {
            float s = 0.f;
#pragma unroll
            for (int c = 0; c < 64; ++c) s += qv[c] * ek_s[r * 64 + c];
            rbw[tid * 12 + r] = s * QSCALE;
        }
    }

    asm volatile("cp.async.wait_group 0;");
    __syncthreads();

    // Persistent Q A-fragments.
    const int wm = wid * 16;
    uint32_t qf[4][4];
    {
        int coff = (lane & 7) + ((lane >> 4) << 3);
        int tok  = wm + (((lane >> 3) & 1) << 3);
#pragma unroll
        for (int ks = 0; ks < 4; ++ks)
            ldm_x4_t(smq + (uint32_t)((ks * 16 + coff) * SQ + tok) * 2, qf[ks]);
    }

    float l0 = 0.f, l1 = 0.f;
    float oacc[8][4] = {};

    for (int kt = 0; kt < 16; ++kt) {
        const int kg = kt * 64;
        const uint32_t sbuf = smkv + (uint32_t)(kt & 1) * KVSTAGE;

        if (kt > 0) asm volatile("cp.async.wait_group 0;");
        __syncthreads();

        if (kt < 15) {
            uint32_t dst = kvdst0 + (uint32_t)((kt & 1) ^ 1) * KVSTAGE;
            const __half* src = kvsrc + kg + 64;
#pragma unroll
            for (int ch = 0; ch < 4; ++ch)
                cp_async16(dst + ch * 16, src + ch * 8);
            cp_commit();
        }

        const uint32_t smk = sbuf, smv = sbuf + KVCOMP;

        // ---- S = Q.K^T (single fp16 pass) ----
        float sacc[8][4] = {};
#pragma unroll
        for (int ks = 0; ks < 4; ++ks) {
            int cK = ks * 16 + (lane & 7) + (((lane >> 3) & 1) << 3);
#pragma unroll
            for (int p = 0; p < 4; ++p) {
                int tokp = p * 16 + ((lane >> 4) << 3);
                uint32_t r[4];
                ldm_x4_t(smk + (uint32_t)(cK * SK + tokp) * 2, r);
                uint32_t b0[2] = {r[0], r[1]}, b1[2] = {r[2], r[3]};
                mma16816h(sacc[2*p],   qf[ks], b0);
                mma16816h(sacc[2*p+1], qf[ks], b1);
            }
        }

        // ---- banded relative-key bias ----
        const int qwbase = q0 + wm;
        if (kg <= qwbase + 19 && kg + 63 >= qwbase - 4) {
            int qg0 = qwbase + (lane >> 2);
#pragma unroll
            for (int nj = 0; nj < 8; ++nj) {
                int kgg = kg + nj * 8 + ((lane & 3) << 1);
#pragma unroll
                for (int i = 0; i < 4; ++i) {
                    int qg = qg0 + ((i >> 1) << 3);
                    int r = kgg + (i & 1) - qg + 4;
                    if ((unsigned)r <= 8u)
                        sacc[nj][i] += rbw[(qg - q0) * 12 + r];
                }
            }
        }

        // ---- fixed-m softmax: e = 2^s; l per-thread; pack fp16 P frags ----
        uint32_t pA[4][4];
#pragma unroll
        for (int p = 0; p < 4; ++p) {
            float e00 = ex2(sacc[2*p][0]),   e01 = ex2(sacc[2*p][1]);
            float e02 = ex2(sacc[2*p][2]),   e03 = ex2(sacc[2*p][3]);
            float e10 = ex2(sacc[2*p+1][0]), e11 = ex2(sacc[2*p+1][1]);
            float e12 = ex2(sacc[2*p+1][2]), e13 = ex2(sacc[2*p+1][3]);
            l0 += e00 + e01 + e10 + e11;
            l1 += e02 + e03 + e12 + e13;
            pA[p][0] = pk2h(e00, e01);
            pA[p][1] = pk2h(e02, e03);
            pA[p][2] = pk2h(e10, e11);
            pA[p][3] = pk2h(e12, e13);
        }

        // ---- O += P.V (single fp16 pass) ----
#pragma unroll
        for (int ks = 0; ks < 4; ++ks) {
            int kV = ks * 16 + (((lane >> 3) & 1) << 3);
#pragma unroll
            for (int p = 0; p < 4; ++p) {
                int nV = p * 16 + (lane & 7) + ((lane >> 4) << 3);
                uint32_t r[4];
                ldm_x4(smv + (uint32_t)(nV * SK + kV) * 2, r);
                uint32_t b0[2] = {r[0], r[1]}, b1[2] = {r[2], r[3]};
                mma16816h(oacc[2*p],   pA[ks], b0);
                mma16816h(oacc[2*p+1], pA[ks], b1);
            }
        }
    }

    // ---- single end-of-loop l reduction across the quad ----
    l0 += __shfl_xor_sync(0xffffffffu, l0, 1);
    l0 += __shfl_xor_sync(0xffffffffu, l0, 2);
    l1 += __shfl_xor_sync(0xffffffffu, l1, 1);
    l1 += __shfl_xor_sync(0xffffffffu, l1, 2);

    if ((lane & 3) == 0) {
        int row = wm + (lane >> 2);
        l_s[row] = l0;
        l_s[row + 8] = l1;
    }
    __syncthreads();

    // Band weights w[tok][r] = 2^((s+s2)*QSCALE) / l  (fp32 recompute, m=0).
    if (tid < 128) {
        float qv[64];
#pragma unroll
        for (int c = 0; c < 64; ++c) qv[c] = Qb[c * 1024 + q0 + tid];
        float invl = 1.f / l_s[tid];
        int qg = q0 + tid;
        float w[9];
#pragma unroll
        for (int r = 0; r < 9; ++r) {
            int kj = qg + r - 4;
            float wv = 0.f;
            if (kj >= 0 && kj < 1024) {
                float s = 0.f;
#pragma unroll
                for (int c = 0; c < 64; ++c) s += qv[c] * Kb[c * 1024 + kj];
                float s2 = 0.f;
#pragma unroll
                for (int c = 0; c < 64; ++c) s2 += qv[c] * ek_s[r * 64 + c];
                wv = ex2((s + s2) * QSCALE) * invl;
            }
            w[r] = wv;
        }
#pragma unroll
        for (int r = 0; r < 9; ++r) rbw[tid * 12 + r] = w[r];
    }
    __syncthreads();

    // O fragments -> staging smem [tok][c] with 1/l and band-ev add.
    {
        float inv0 = 1.f / l0, inv1 = 1.f / l1;
        int row0 = wm + (lane >> 2), row1 = row0 + 8;
        float w0[9], w1[9];
#pragma unroll
        for (int r = 0; r < 9; ++r) { w0[r] = rbw[row0 * 12 + r]; w1[r] = rbw[row1 * 12 + r]; }
#pragma unroll
        for (int nj = 0; nj < 8; ++nj) {
            int cb = nj * 8 + ((lane & 3) << 1);
#pragma unroll
            for (int i = 0; i < 4; ++i) {
                int cc = cb + (i & 1);
                const float* wr = (i < 2) ? w0 : w1;
                float band = 0.f;
#pragma unroll
                for (int r = 0; r < 9; ++r) band += wr[r] * ev_s[r * 64 + cc];
                float val = oacc[nj][i] * ((i < 2) ? inv0 : inv1) + band;
                ost[((i < 2) ? row0 : row1) * OSTRIDE + cc] = val;
            }
        }
    }
    __syncthreads();

    // Remapped fp16 store (faithful reshape flat index).
    const size_t obase = (size_t)(bh >> 3) * 524288 + (size_t)(bh & 7) * 65536;
    for (int idx = tid; idx < 8192; idx += 256) {
        int c = idx >> 7, tl = idx & 127;
        float v = ost[tl * OSTRIDE + c];
        a_o_h[obase + c * 1024 + q0 + tl] = __float2half(v);
    }
}

// ---------------------------------------------------------------------------
extern "C" void kernel_launch(void* const* d_in, const int* in_sizes, int n_in,
                              void* d_out, int out_size) {
    const float* x  = (const float*)d_in[0];
    const float* c  = (const float*)d_in[1];
    const float* wq = (const float*)d_in[2];
    const float* bq = (const float*)d_in[3];
    const float* wk = (const float*)d_in[4];
    const float* bk = (const float*)d_in[5];
    const float* wv = (const float*)d_in[6];
    const float* bv = (const float*)d_in[7];
    const float* wo = (const float*)d_in[8];
    const float* bo = (const float*)d_in[9];
    const float* ek = (const float*)d_in[10];
    const float* ev = (const float*)d_in[11];
    float* out = (float*)d_out;

    cudaFuncSetAttribute(attn_mma_kernel,
                         cudaFuncAttributeMaxDynamicSharedMemorySize, ATT_SMEM);

    convert_w_kernel<<<dim3(16, 16, 4), 256>>>(wq, wk, wv, wo);
    convert_xc_kernel<<<4096, 256>>>(x, c);

    qkv_mma_kernel<<<dim3(4, 32, 3), 256>>>(bq, bk, bv);

    attn_mma_kernel<<<dim3(8, 32), 256, ATT_SMEM>>>(ek, ev);

    out_mma_kernel<<<dim3(4, 32), 256>>>(bo, out);
}